// round 11
// baseline (speedup 1.0000x reference)
#include <cuda_runtime.h>
#include <cuda_fp16.h>
#include <cstdint>

#define NN 100000
#define NE 1600000
#define NG 64
#define NBLK 98   // ceil(NN/1024)

// ---------------- scratch ----------------
__device__ __align__(256) uint32_t g_xA[(size_t)NN * 64];
__device__ __align__(256) uint32_t g_xB[(size_t)NN * 64];
__device__ __align__(256) float g_xC[(size_t)NN * 64];   // fp32 final-layer output
__device__ __align__(256) __half2 g_z[(size_t)NN * 32];
__device__ int g_deg[NN];
__device__ int g_cursor[NN];
__device__ int g_rowptr[NN + 1];
__device__ int g_adj[NE];
__device__ int g_bsum[NBLK];
__device__ int g_boff[NBLK];
__device__ unsigned g_gmax[NG * 64];
__device__ float g_gsum[NG * 64];
__device__ int g_gcnt[NG];

// ---------------- helpers ----------------
__device__ __forceinline__ uint32_t f2h2(float lo, float hi) {
    __half2 h = __floats2half2_rn(lo, hi);
    return *reinterpret_cast<uint32_t*>(&h);
}
__device__ __forceinline__ void mma16(float* c, const uint32_t* a, const uint32_t* b) {
    asm volatile(
        "mma.sync.aligned.m16n8k16.row.col.f32.f16.f16.f32 "
        "{%0,%1,%2,%3}, {%4,%5,%6,%7}, {%8,%9}, {%0,%1,%2,%3};"
        : "+f"(c[0]), "+f"(c[1]), "+f"(c[2]), "+f"(c[3])
        : "r"(a[0]), "r"(a[1]), "r"(a[2]), "r"(a[3]), "r"(b[0]), "r"(b[1]));
}
__device__ __forceinline__ unsigned fenc(float f) {
    unsigned u = __float_as_uint(f);
    return (u & 0x80000000u) ? ~u : (u | 0x80000000u);
}
__device__ __forceinline__ float fdec(unsigned e) {
    return __uint_as_float((e & 0x80000000u) ? (e ^ 0x80000000u) : ~e);
}

// ---------------- fp16 XOR-swizzled tiles ----------------
__device__ __forceinline__ void stTile4(uint32_t* s, int row, int qq, uint4 w) {
    *reinterpret_cast<uint4*>(s + row * 32 + 4 * (qq ^ (row & 7))) = w;
}
__device__ __forceinline__ void stXh(uint32_t* sX, int row, int c2, uint32_t w) {
    uint32_t* t = sX + (c2 >> 4) * 4096;
    int lc = c2 & 15;
    t[row * 32 + 4 * ((lc >> 2) ^ (row & 7)) + (lc & 3)] = w;
}

template <int NT>
__device__ __forceinline__ void chunk_mma_h(const uint32_t* sA, const uint32_t* sB,
                                            float (&acc)[2][NT][4], int rowB, int colB, int lane) {
    const int qr = lane >> 2, qc = lane & 3;
#pragma unroll
    for (int s = 0; s < 2; s++) {
        uint32_t a[2][4];
#pragma unroll
        for (int mt = 0; mt < 2; mt++) {
            int r0 = rowB + mt * 16 + qr;
            const uint32_t* p0 = sA + r0 * 32;
            const uint32_t* p1 = sA + (r0 + 8) * 32;
            a[mt][0] = p0[4 * ((2 * s) ^ qr) + qc];
            a[mt][1] = p1[4 * ((2 * s) ^ qr) + qc];
            a[mt][2] = p0[4 * ((2 * s + 1) ^ qr) + qc];
            a[mt][3] = p1[4 * ((2 * s + 1) ^ qr) + qc];
        }
#pragma unroll
        for (int nt = 0; nt < NT; nt++) {
            int n = colB + nt * 8 + qr;
            const uint32_t* bb = sB + n * 32;
            uint32_t b[2] = { bb[4 * ((2 * s) ^ qr) + qc], bb[4 * ((2 * s + 1) ^ qr) + qc] };
#pragma unroll
            for (int mt = 0; mt < 2; mt++) mma16(acc[mt][nt], a[mt], b);
        }
    }
}

// ---------------- init ----------------
__global__ void init_kernel() {
    int j = blockIdx.x * blockDim.x + threadIdx.x;
    if (j < NN) { g_deg[j] = 0; g_cursor[j] = 0; }
    if (j < NG * 64) { g_gmax[j] = 0x007FFFFFu; g_gsum[j] = 0.f; }
    if (j < NG) g_gcnt[j] = 0;
}

// ---------------- CSR build ----------------
__global__ void hist_kernel(const int* __restrict__ dst) {
    int e = blockIdx.x * blockDim.x + threadIdx.x;
    if (e < NE) atomicAdd(&g_deg[dst[e]], 1);
}

__global__ void scan1_kernel() {
    __shared__ int wsum[8];
    int b = blockIdx.x, tid = threadIdx.x, lane = tid & 31, w = tid >> 5;
    int i0 = b * 1024 + tid * 4;
    int s = 0;
#pragma unroll
    for (int j = 0; j < 4; j++) { int i = i0 + j; if (i < NN) s += g_deg[i]; }
#pragma unroll
    for (int o = 16; o > 0; o >>= 1) s += __shfl_xor_sync(0xffffffffu, s, o);
    if (lane == 0) wsum[w] = s;
    __syncthreads();
    if (tid == 0) {
        int t = 0;
#pragma unroll
        for (int k = 0; k < 8; k++) t += wsum[k];
        g_bsum[b] = t;
    }
}

__global__ void scan2_kernel() {
    __shared__ int ws[4];
    int tid = threadIdx.x, lane = tid & 31, w = tid >> 5;
    int v = (tid < NBLK) ? g_bsum[tid] : 0;
    int si = v;
#pragma unroll
    for (int o = 1; o < 32; o <<= 1) { int t = __shfl_up_sync(0xffffffffu, si, o); if (lane >= o) si += t; }
    if (lane == 31) ws[w] = si;
    __syncthreads();
    if (tid == 0) {
        int run = 0;
#pragma unroll
        for (int k = 0; k < 4; k++) { int t = ws[k]; ws[k] = run; run += t; }
        g_rowptr[NN] = run;
    }
    __syncthreads();
    if (tid < NBLK) g_boff[tid] = ws[w] + si - v;
}

__global__ void scan3_kernel() {
    __shared__ int wsum[8];
    int b = blockIdx.x, tid = threadIdx.x, lane = tid & 31, w = tid >> 5;
    int i0 = b * 1024 + tid * 4;
    int v[4], s = 0;
#pragma unroll
    for (int j = 0; j < 4; j++) { int i = i0 + j; v[j] = (i < NN) ? g_deg[i] : 0; s += v[j]; }
    int si = s;
#pragma unroll
    for (int o = 1; o < 32; o <<= 1) { int t = __shfl_up_sync(0xffffffffu, si, o); if (lane >= o) si += t; }
    if (lane == 31) wsum[w] = si;
    __syncthreads();
    if (tid == 0) {
        int run = 0;
#pragma unroll
        for (int k = 0; k < 8; k++) { int t = wsum[k]; wsum[k] = run; run += t; }
    }
    __syncthreads();
    int off = g_boff[b] + wsum[w] + (si - s);
#pragma unroll
    for (int j = 0; j < 4; j++) { int i = i0 + j; if (i < NN) g_rowptr[i] = off; off += v[j]; }
}

__global__ void fill_adj_kernel(const int* __restrict__ src, const int* __restrict__ dst) {
    int e = blockIdx.x * blockDim.x + threadIdx.x;
    if (e < NE) {
        int d = dst[e];
        int p = atomicAdd(&g_cursor[d], 1);
        g_adj[g_rowptr[d] + p] = src[e];
    }
}

// ---------------- lin ----------------
__device__ __forceinline__ float4 lin_ld4(const float* nf, const float* cf,
                                          const int* opc, const float* emb, int grow, int k) {
    float4 v = make_float4(0, 0, 0, 0);
    if (k < 140)      v = *(const float4*)(nf + (size_t)grow * 140 + k);
    else if (k < 172) v = *(const float4*)(emb + (size_t)opc[grow] * 32 + (k - 140));
    else if (k < 190) {
        const float* cp = cf + (size_t)grow * 18;
        int off = k - 172;
        v.x = cp[off];
        v.y = (off + 1 < 18) ? cp[off + 1] : 0.f;
        v.z = (off + 2 < 18) ? cp[off + 2] : 0.f;
        v.w = (off + 3 < 18) ? cp[off + 3] : 0.f;
    }
    return v;
}

__global__ void __launch_bounds__(256)
lin_h(const float* __restrict__ nf, const float* __restrict__ cf,
      const int* __restrict__ opc, const float* __restrict__ emb,
      const float* __restrict__ W, const float* __restrict__ bias,
      uint32_t* __restrict__ C) {
    extern __shared__ uint32_t smem[];
    const int tid = threadIdx.x, lane = tid & 31, wid = tid >> 5;
    const int warpM = wid & 3, warpN = wid >> 2;
    const int rowBase = blockIdx.x * 128;
    const int n0 = blockIdx.y * 64;

    float acc[2][4][4];
#pragma unroll
    for (int mt = 0; mt < 2; mt++)
#pragma unroll
        for (int nt = 0; nt < 4; nt++)
#pragma unroll
            for (int q = 0; q < 4; q++) acc[mt][nt][q] = 0.f;

    uint4 ra[2], rb;
    auto loadC = [&](int c) {
#pragma unroll
        for (int i = 0; i < 2; i++) {
            int g = tid + 256 * i;
            int row = g & 127, qq = g >> 7;
            int grow = rowBase + row;
            uint4 w = make_uint4(0, 0, 0, 0);
            if (grow < NN) {
                float4 v0 = lin_ld4(nf, cf, opc, emb, grow, c * 32 + 8 * qq);
                float4 v1 = lin_ld4(nf, cf, opc, emb, grow, c * 32 + 8 * qq + 4);
                w = make_uint4(f2h2(v0.x, v0.y), f2h2(v0.z, v0.w), f2h2(v1.x, v1.y), f2h2(v1.z, v1.w));
            }
            ra[i] = w;
        }
        {
            int n = tid & 63, qq = tid >> 6;
            float f[8];
#pragma unroll
            for (int j = 0; j < 8; j++) {
                int kg = c * 32 + 8 * qq + j;
                f[j] = (kg < 190) ? W[(size_t)kg * 128 + n0 + n] : 0.f;
            }
            rb = make_uint4(f2h2(f[0], f[1]), f2h2(f[2], f[3]), f2h2(f[4], f[5]), f2h2(f[6], f[7]));
        }
    };
    auto stage = [&](int b) {
        uint32_t* sa = smem + (b ? 4096 : 0);
        uint32_t* sb = smem + 8192 + (b ? 2048 : 0);
#pragma unroll
        for (int i = 0; i < 2; i++) {
            int g = tid + 256 * i;
            stTile4(sa, g & 127, g >> 7, ra[i]);
        }
        stTile4(sb, tid & 63, tid >> 6, rb);
    };

    loadC(0); stage(0); __syncthreads();
#pragma unroll 1
    for (int c = 0; c < 6; c++) {
        if (c < 5) loadC(c + 1);
        const uint32_t* sa = smem + ((c & 1) ? 4096 : 0);
        const uint32_t* sb = smem + 8192 + ((c & 1) ? 2048 : 0);
        chunk_mma_h<4>(sa, sb, acc, warpM * 32, warpN * 32, lane);
        if (c < 5) { stage((c + 1) & 1); __syncthreads(); }
    }

    const int qr = lane >> 2, qc = lane & 3;
#pragma unroll
    for (int mt = 0; mt < 2; mt++) {
        int r0 = rowBase + warpM * 32 + mt * 16 + qr;
#pragma unroll
        for (int nt = 0; nt < 4; nt++) {
            int gc = n0 + warpN * 32 + nt * 8 + 2 * qc;
            float b0 = __ldg(&bias[gc]), b1 = __ldg(&bias[gc + 1]);
            if (r0 < NN)
                C[(size_t)r0 * 64 + gc / 2] =
                    f2h2(fmaxf(acc[mt][nt][0] + b0, 0.f), fmaxf(acc[mt][nt][1] + b1, 0.f));
            if (r0 + 8 < NN)
                C[(size_t)(r0 + 8) * 64 + gc / 2] =
                    f2h2(fmaxf(acc[mt][nt][2] + b0, 0.f), fmaxf(acc[mt][nt][3] + b1, 0.f));
        }
    }
}

// ---------------- projz: Z(half2) = relu(A@PW + PB) @ WL ----------------
template <int K>
__global__ void __launch_bounds__(256)
projz_h(const uint32_t* __restrict__ A, const float* __restrict__ PW,
        const float* __restrict__ PB, const float* __restrict__ WL,
        __half2* __restrict__ Z) {
    constexpr int NCH = K / 32;
    constexpr int CW = K / 2;
    constexpr int NT1 = CW / 8;
    constexpr int INB = K * 32;
    constexpr int INW = 8192 + 2 * INB;
    constexpr int XW = NCH * 4096;
    constexpr int UW = (INW > XW) ? INW : XW;
    constexpr int NST = K / 64;
    extern __shared__ uint32_t smem[];
    uint32_t* W2 = smem + UW;

    const int tid = threadIdx.x, lane = tid & 31, wid = tid >> 5;
    const int warpM = wid & 3, warpN = wid >> 2;
    const int rowBase = blockIdx.x * 128;
    const int qr = lane >> 2, qc = lane & 3;

#pragma unroll
    for (int c = 0; c < NCH; c++) {
        int n = tid & 63, qq = tid >> 6;
        float f[8];
#pragma unroll
        for (int j = 0; j < 8; j++) f[j] = WL[(size_t)(c * 32 + 8 * qq + j) * 64 + n];
        stTile4(W2 + c * 2048, n, qq,
                make_uint4(f2h2(f[0], f[1]), f2h2(f[2], f[3]), f2h2(f[4], f[5]), f2h2(f[6], f[7])));
    }

    float acc1[2][NT1][4];
#pragma unroll
    for (int mt = 0; mt < 2; mt++)
#pragma unroll
        for (int nt = 0; nt < NT1; nt++)
#pragma unroll
            for (int q = 0; q < 4; q++) acc1[mt][nt][q] = 0.f;

    uint4 ra[2], rb[NST];
    auto loadC = [&](int c) {
#pragma unroll
        for (int i = 0; i < 2; i++) {
            int g = tid + 256 * i;
            int row = g & 127, qq = g >> 7;
            int grow = rowBase + row;
            ra[i] = (grow < NN)
                ? *reinterpret_cast<const uint4*>(A + (size_t)grow * (K / 2) + c * 16 + 4 * qq)
                : make_uint4(0, 0, 0, 0);
        }
#pragma unroll
        for (int i = 0; i < NST; i++) {
            int g = tid + 256 * i;
            int n = g % K, qq = g / K;
            float f[8];
#pragma unroll
            for (int j = 0; j < 8; j++) f[j] = PW[(size_t)(c * 32 + 8 * qq + j) * K + n];
            rb[i] = make_uint4(f2h2(f[0], f[1]), f2h2(f[2], f[3]), f2h2(f[4], f[5]), f2h2(f[6], f[7]));
        }
    };
    auto stage = [&](int b) {
        uint32_t* sa = smem + (b ? 4096 : 0);
        uint32_t* sb = smem + 8192 + (b ? INB : 0);
#pragma unroll
        for (int i = 0; i < 2; i++) {
            int g = tid + 256 * i;
            stTile4(sa, g & 127, g >> 7, ra[i]);
        }
#pragma unroll
        for (int i = 0; i < NST; i++) {
            int g = tid + 256 * i;
            stTile4(sb, g % K, g / K, rb[i]);
        }
    };

    loadC(0); stage(0); __syncthreads();
#pragma unroll 1
    for (int c = 0; c < NCH; c++) {
        if (c + 1 < NCH) loadC(c + 1);
        const uint32_t* sa = smem + ((c & 1) ? 4096 : 0);
        const uint32_t* sb = smem + 8192 + ((c & 1) ? INB : 0);
        chunk_mma_h<NT1>(sa, sb, acc1, warpM * 32, warpN * CW, lane);
        if (c + 1 < NCH) { stage((c + 1) & 1); __syncthreads(); }
    }
    __syncthreads();

#pragma unroll
    for (int mt = 0; mt < 2; mt++) {
        int r0 = warpM * 32 + mt * 16 + qr;
#pragma unroll
        for (int nt = 0; nt < NT1; nt++) {
            int col = warpN * CW + nt * 8 + 2 * qc;
            float b0 = __ldg(&PB[col]), b1 = __ldg(&PB[col + 1]);
            stXh(smem, r0, col / 2,
                 f2h2(fmaxf(acc1[mt][nt][0] + b0, 0.f), fmaxf(acc1[mt][nt][1] + b1, 0.f)));
            stXh(smem, r0 + 8, col / 2,
                 f2h2(fmaxf(acc1[mt][nt][2] + b0, 0.f), fmaxf(acc1[mt][nt][3] + b1, 0.f)));
        }
    }
    __syncthreads();

    float acc2[2][4][4];
#pragma unroll
    for (int mt = 0; mt < 2; mt++)
#pragma unroll
        for (int nt = 0; nt < 4; nt++)
#pragma unroll
            for (int q = 0; q < 4; q++) acc2[mt][nt][q] = 0.f;
#pragma unroll
    for (int c = 0; c < NCH; c++)
        chunk_mma_h<4>(smem + c * 4096, W2 + c * 2048, acc2, warpM * 32, warpN * 32, lane);

#pragma unroll
    for (int mt = 0; mt < 2; mt++) {
        int r0 = rowBase + warpM * 32 + mt * 16 + qr;
#pragma unroll
        for (int nt = 0; nt < 4; nt++) {
            int gc = warpN * 32 + nt * 8 + 2 * qc;
            if (r0 < NN)
                Z[(size_t)r0 * 32 + gc / 2] = __floats2half2_rn(acc2[mt][nt][0], acc2[mt][nt][1]);
            if (r0 + 8 < NN)
                Z[(size_t)(r0 + 8) * 32 + gc / 2] = __floats2half2_rn(acc2[mt][nt][2], acc2[mt][nt][3]);
        }
    }
}

// ---------------- fused combine: out = normalize(X@WR + mean_gather(Z) + BL) ----------------
template <int K, bool HOUT>
__global__ void __launch_bounds__(256)
combine_f(const uint32_t* __restrict__ X, const float* __restrict__ WR,
          const __half2* __restrict__ zp, const float* __restrict__ BL,
          void* __restrict__ Cout) {
    constexpr int NCH = K / 32;
    extern __shared__ uint32_t smem[];
    const int tid = threadIdx.x, lane = tid & 31, wid = tid >> 5;
    const int warpM = wid & 3, warpN = wid >> 2;
    const int rowBase = blockIdx.x * 128;

    float acc[2][4][4];
#pragma unroll
    for (int mt = 0; mt < 2; mt++)
#pragma unroll
        for (int nt = 0; nt < 4; nt++)
#pragma unroll
            for (int q = 0; q < 4; q++) acc[mt][nt][q] = 0.f;

    uint4 ra[2], rb;
    auto loadC = [&](int c) {
#pragma unroll
        for (int i = 0; i < 2; i++) {
            int g = tid + 256 * i;
            int row = g & 127, qq = g >> 7;
            int grow = rowBase + row;
            ra[i] = (grow < NN)
                ? *reinterpret_cast<const uint4*>(X + (size_t)grow * (K / 2) + c * 16 + 4 * qq)
                : make_uint4(0, 0, 0, 0);
        }
        {
            int n = tid & 63, qq = tid >> 6;
            float f[8];
#pragma unroll
            for (int j = 0; j < 8; j++) f[j] = WR[(size_t)(c * 32 + 8 * qq + j) * 64 + n];
            rb = make_uint4(f2h2(f[0], f[1]), f2h2(f[2], f[3]), f2h2(f[4], f[5]), f2h2(f[6], f[7]));
        }
    };
    auto stage = [&](int b) {
        uint32_t* sa = smem + (b ? 4096 : 0);
        uint32_t* sb = smem + 8192 + (b ? 2048 : 0);
#pragma unroll
        for (int i = 0; i < 2; i++) {
            int g = tid + 256 * i;
            stTile4(sa, g & 127, g >> 7, ra[i]);
        }
        stTile4(sb, tid & 63, tid >> 6, rb);
    };

    loadC(0); stage(0); __syncthreads();
#pragma unroll 1
    for (int c = 0; c < NCH; c++) {
        if (c + 1 < NCH) loadC(c + 1);
        const uint32_t* sa = smem + ((c & 1) ? 4096 : 0);
        const uint32_t* sb = smem + 8192 + ((c & 1) ? 2048 : 0);
        chunk_mma_h<4>(sa, sb, acc, warpM * 32, warpN * 32, lane);
        if (c + 1 < NCH) { stage((c + 1) & 1); __syncthreads(); }
    }

    // stage acc + bias to smem, then per-row: gather mean(z), add, normalize, store
    __syncthreads();
    float (*sOut)[66] = reinterpret_cast<float(*)[66]>(smem);
    const int qr = lane >> 2, qc = lane & 3;
#pragma unroll
    for (int mt = 0; mt < 2; mt++) {
        int rl = warpM * 32 + mt * 16 + qr;
#pragma unroll
        for (int nt = 0; nt < 4; nt++) {
            int cl = warpN * 32 + nt * 8 + 2 * qc;
            float b0 = __ldg(&BL[cl]), b1 = __ldg(&BL[cl + 1]);
            sOut[rl][cl]         = acc[mt][nt][0] + b0;
            sOut[rl][cl + 1]     = acc[mt][nt][1] + b1;
            sOut[rl + 8][cl]     = acc[mt][nt][2] + b0;
            sOut[rl + 8][cl + 1] = acc[mt][nt][3] + b1;
        }
    }
    __syncthreads();
#pragma unroll 1
    for (int rr = 0; rr < 16; rr++) {
        int r = wid * 16 + rr;
        int grow = rowBase + r;
        float2 v = *(const float2*)&sOut[r][2 * lane];
        if (grow < NN) {
            // fused mean aggregation over in-edges of grow
            int beg = g_rowptr[grow], end = g_rowptr[grow + 1];
            float2 az = make_float2(0.f, 0.f);
            int e = beg;
            for (; e + 4 <= end; e += 4) {
                int s0 = __ldg(&g_adj[e]);
                int s1 = __ldg(&g_adj[e + 1]);
                int s2 = __ldg(&g_adj[e + 2]);
                int s3 = __ldg(&g_adj[e + 3]);
                float2 v0 = __half22float2(zp[(size_t)s0 * 32 + lane]);
                float2 v1 = __half22float2(zp[(size_t)s1 * 32 + lane]);
                float2 v2 = __half22float2(zp[(size_t)s2 * 32 + lane]);
                float2 v3 = __half22float2(zp[(size_t)s3 * 32 + lane]);
                az.x += (v0.x + v1.x) + (v2.x + v3.x);
                az.y += (v0.y + v1.y) + (v2.y + v3.y);
            }
            for (; e < end; e++) {
                int s = __ldg(&g_adj[e]);
                float2 vv = __half22float2(zp[(size_t)s * 32 + lane]);
                az.x += vv.x; az.y += vv.y;
            }
            float inv = 1.0f / fmaxf((float)(end - beg), 1.0f);
            v.x += az.x * inv;
            v.y += az.y * inv;
        }
        float ss = v.x * v.x + v.y * v.y;
#pragma unroll
        for (int o = 16; o > 0; o >>= 1) ss += __shfl_xor_sync(0xffffffffu, ss, o);
        float sc = 1.0f / fmaxf(sqrtf(ss), 1e-12f);
        if (grow < NN) {
            if (HOUT) {
                ((uint32_t*)Cout)[(size_t)grow * 32 + lane] = f2h2(v.x * sc, v.y * sc);
            } else {
                *(float2*)((float*)Cout + (size_t)grow * 64 + 2 * lane) =
                    make_float2(v.x * sc, v.y * sc);
            }
        }
    }
}

// ---------------- pooling ----------------
__global__ void pool_kernel(const float* __restrict__ x, const int* __restrict__ batch) {
    int nwarps = (gridDim.x * blockDim.x) >> 5;
    int w = (blockIdx.x * blockDim.x + threadIdx.x) >> 5;
    int lane = threadIdx.x & 31;
    int per = (NN + nwarps - 1) / nwarps;
    int s = w * per;
    int e = min(NN, s + per);
    if (s >= e) return;
    float m0 = -__int_as_float(0x7f800000), m1 = m0;
    float s0 = 0.f, s1 = 0.f;
    int cnt = 0;
    int curg = __ldg(&batch[s]);
    for (int i = s; i < e; i++) {
        int g = __ldg(&batch[i]);
        if (g != curg) {
            atomicMax(&g_gmax[curg * 64 + lane], fenc(m0));
            atomicMax(&g_gmax[curg * 64 + lane + 32], fenc(m1));
            atomicAdd(&g_gsum[curg * 64 + lane], s0);
            atomicAdd(&g_gsum[curg * 64 + lane + 32], s1);
            if (lane == 0) atomicAdd(&g_gcnt[curg], cnt);
            m0 = m1 = -__int_as_float(0x7f800000);
            s0 = s1 = 0.f; cnt = 0; curg = g;
        }
        float v0 = x[(size_t)i * 64 + lane];
        float v1 = x[(size_t)i * 64 + lane + 32];
        m0 = fmaxf(m0, v0); m1 = fmaxf(m1, v1);
        s0 += v0; s1 += v1; cnt++;
    }
    atomicMax(&g_gmax[curg * 64 + lane], fenc(m0));
    atomicMax(&g_gmax[curg * 64 + lane + 32], fenc(m1));
    atomicAdd(&g_gsum[curg * 64 + lane], s0);
    atomicAdd(&g_gsum[curg * 64 + lane + 32], s1);
    if (lane == 0) atomicAdd(&g_gcnt[curg], cnt);
}

// ---------------- final ----------------
__global__ void final_kernel(const float* __restrict__ post_w, const float* __restrict__ post_b,
                             float* __restrict__ out) {
    int g = threadIdx.x;
    if (g >= NG) return;
    float inv = 1.0f / (float)g_gcnt[g];
    float v[64];
    float ss = 0.f;
#pragma unroll
    for (int c = 0; c < 64; c++) {
        float t = fdec(g_gmax[g * 64 + c]) + g_gsum[g * 64 + c] * inv;
        v[c] = t;
        ss += t * t;
    }
    float norm = sqrtf(ss);
    float dot = 0.f;
#pragma unroll
    for (int c = 0; c < 64; c++) dot += v[c] * post_w[c];
    out[g] = dot / norm + post_b[0];
}

// ---------------- launch ----------------
static cudaStream_t g_s2 = nullptr;
static cudaEvent_t g_ev1 = nullptr, g_ev2 = nullptr;

extern "C" void kernel_launch(void* const* d_in, const int* in_sizes, int n_in,
                              void* d_out, int out_size) {
    const float* node_feat = (const float*)d_in[0];
    const float* cfg_feat  = (const float*)d_in[1];
    const int*   opcode    = (const int*)d_in[2];
    const int*   edge      = (const int*)d_in[3];
    const int*   batch     = (const int*)d_in[4];
    const float* op_emb    = (const float*)d_in[5];
    const float* lin_w     = (const float*)d_in[6];
    const float* lin_b     = (const float*)d_in[7];
    const float* post_w    = (const float*)d_in[8];
    const float* post_b    = (const float*)d_in[9];
    const float* pw0 = (const float*)d_in[10];
    const float* pb0 = (const float*)d_in[11];
    const float* wl0 = (const float*)d_in[12];
    const float* bl0 = (const float*)d_in[13];
    const float* wr0 = (const float*)d_in[14];
    const float* pw1 = (const float*)d_in[15];
    const float* pb1 = (const float*)d_in[16];
    const float* wl1 = (const float*)d_in[17];
    const float* bl1 = (const float*)d_in[18];
    const float* wr1 = (const float*)d_in[19];
    const float* pw2 = (const float*)d_in[20];
    const float* pb2 = (const float*)d_in[21];
    const float* wl2 = (const float*)d_in[22];
    const float* bl2 = (const float*)d_in[23];
    const float* wr2 = (const float*)d_in[24];
    float* out = (float*)d_out;

    if (g_s2 == nullptr) {
        cudaStreamCreateWithFlags(&g_s2, cudaStreamNonBlocking);
        cudaEventCreateWithFlags(&g_ev1, cudaEventDisableTiming);
        cudaEventCreateWithFlags(&g_ev2, cudaEventDisableTiming);
        cudaFuncSetAttribute(projz_h<128>, cudaFuncAttributeMaxDynamicSharedMemorySize, 98304);
        cudaFuncSetAttribute(projz_h<64>,  cudaFuncAttributeMaxDynamicSharedMemorySize, 65536);
    }

    const int* src = edge;
    const int* dst = edge + NE;

    const int MB = (NN + 127) / 128;
    const int EB = (NE + 255) / 256;
    const size_t SMEM48 = 49152;
    const size_t SMEM_PZ128 = 98304;
    const size_t SMEM_PZ64  = 65536;

    uint32_t* dA; cudaGetSymbolAddress((void**)&dA, g_xA);
    uint32_t* dB; cudaGetSymbolAddress((void**)&dB, g_xB);
    float* dC; cudaGetSymbolAddress((void**)&dC, g_xC);
    __half2* dZ; cudaGetSymbolAddress((void**)&dZ, g_z);

    // fork: CSR build on side stream
    cudaEventRecord(g_ev1, 0);
    cudaStreamWaitEvent(g_s2, g_ev1, 0);
    init_kernel<<<(NN + 255) / 256, 256, 0, g_s2>>>();
    hist_kernel<<<EB, 256, 0, g_s2>>>(dst);
    scan1_kernel<<<NBLK, 256, 0, g_s2>>>();
    scan2_kernel<<<1, 128, 0, g_s2>>>();
    scan3_kernel<<<NBLK, 256, 0, g_s2>>>();
    fill_adj_kernel<<<EB, 256, 0, g_s2>>>(src, dst);
    cudaEventRecord(g_ev2, g_s2);

    lin_h<<<dim3(MB, 2), 256, SMEM48>>>(node_feat, cfg_feat, opcode, op_emb, lin_w, lin_b, dA);
    projz_h<128><<<MB, 256, SMEM_PZ128>>>(dA, pw0, pb0, wl0, dZ);

    cudaStreamWaitEvent(0, g_ev2, 0);  // combine gathers need the CSR

    // layer 0 (d=128 -> 64)
    combine_f<128, true><<<MB, 256, SMEM48>>>(dA, wr0, dZ, bl0, dB);

    // layer 1 (d=64 -> 64)
    projz_h<64><<<MB, 256, SMEM_PZ64>>>(dB, pw1, pb1, wl1, dZ);
    combine_f<64, true><<<MB, 256, SMEM48>>>(dB, wr1, dZ, bl1, dA);

    // layer 2 (d=64 -> 64), fp32 output for pooling
    projz_h<64><<<MB, 256, SMEM_PZ64>>>(dA, pw2, pb2, wl2, dZ);
    combine_f<64, false><<<MB, 256, SMEM48>>>(dA, wr2, dZ, bl2, dC);

    pool_kernel<<<128, 256>>>(dC, batch);
    final_kernel<<<1, 64>>>(post_w, post_b, out);
}

// round 12
// speedup vs baseline: 1.0963x; 1.0963x over previous
#include <cuda_runtime.h>
#include <cuda_fp16.h>
#include <cstdint>

#define NN 100000
#define NE 1600000
#define NG 64
#define NBLK 98   // ceil(NN/1024)

// ---------------- scratch ----------------
// activation buffers as half2 words; +128 rows slack so cp.async edge reads stay in-bounds
__device__ __align__(256) uint32_t g_xA[(size_t)(NN + 128) * 64];
__device__ __align__(256) uint32_t g_xB[(size_t)(NN + 128) * 64];
__device__ __align__(256) float g_xC[(size_t)NN * 64];   // fp32 final-layer output
__device__ __align__(256) __half2 g_z[(size_t)NN * 32];
__device__ __align__(256) float g_msg[(size_t)NN * 64];
__device__ __align__(256) __half g_wt[57344];            // transposed fp16 weights
__device__ int g_deg[NN];
__device__ int g_cursor[NN];
__device__ int g_rowptr[NN + 1];
__device__ int g_adj[NE];
__device__ int g_bsum[NBLK];
__device__ int g_boff[NBLK];
__device__ unsigned g_gmax[NG * 64];
__device__ float g_gsum[NG * 64];
__device__ int g_gcnt[NG];

// ---------------- helpers ----------------
__device__ __forceinline__ uint32_t smem_u32(const void* p) {
    uint32_t a;
    asm("{ .reg .u64 t; cvta.to.shared.u64 t, %1; cvt.u32.u64 %0, t; }" : "=r"(a) : "l"(p));
    return a;
}
#define CPA16(dst, src) \
    asm volatile("cp.async.cg.shared.global [%0], [%1], 16;" :: "r"(dst), "l"(src) : "memory")
#define CPA_COMMIT() asm volatile("cp.async.commit_group;" ::: "memory")
#define CPA_WAIT0()  asm volatile("cp.async.wait_group 0;" ::: "memory")

__device__ __forceinline__ uint32_t f2h2(float lo, float hi) {
    __half2 h = __floats2half2_rn(lo, hi);
    return *reinterpret_cast<uint32_t*>(&h);
}
__device__ __forceinline__ void mma16(float* c, const uint32_t* a, const uint32_t* b) {
    asm volatile(
        "mma.sync.aligned.m16n8k16.row.col.f32.f16.f16.f32 "
        "{%0,%1,%2,%3}, {%4,%5,%6,%7}, {%8,%9}, {%0,%1,%2,%3};"
        : "+f"(c[0]), "+f"(c[1]), "+f"(c[2]), "+f"(c[3])
        : "r"(a[0]), "r"(a[1]), "r"(a[2]), "r"(a[3]), "r"(b[0]), "r"(b[1]));
}
__device__ __forceinline__ unsigned fenc(float f) {
    unsigned u = __float_as_uint(f);
    return (u & 0x80000000u) ? ~u : (u | 0x80000000u);
}
__device__ __forceinline__ float fdec(unsigned e) {
    return __uint_as_float((e & 0x80000000u) ? (e ^ 0x80000000u) : ~e);
}

// ---------------- fp16 XOR-swizzled tiles (row stride 32 words, slots qq^(row&7)) ----------------
__device__ __forceinline__ void stTile4(uint32_t* s, int row, int qq, uint4 w) {
    *reinterpret_cast<uint4*>(s + row * 32 + 4 * (qq ^ (row & 7))) = w;
}
__device__ __forceinline__ uint32_t tileAddr(uint32_t base_b, int offW, int row, int qq) {
    return base_b + 4u * (uint32_t)(offW + row * 32 + 4 * (qq ^ (row & 7)));
}
__device__ __forceinline__ void stXh(uint32_t* sX, int row, int c2, uint32_t w) {
    uint32_t* t = sX + (c2 >> 4) * 4096;
    int lc = c2 & 15;
    t[row * 32 + 4 * ((lc >> 2) ^ (row & 7)) + (lc & 3)] = w;
}

template <int NT>
__device__ __forceinline__ void chunk_mma_h(const uint32_t* sA, const uint32_t* sB,
                                            float (&acc)[2][NT][4], int rowB, int colB, int lane) {
    const int qr = lane >> 2, qc = lane & 3;
#pragma unroll
    for (int s = 0; s < 2; s++) {
        uint32_t a[2][4];
#pragma unroll
        for (int mt = 0; mt < 2; mt++) {
            int r0 = rowB + mt * 16 + qr;
            const uint32_t* p0 = sA + r0 * 32;
            const uint32_t* p1 = sA + (r0 + 8) * 32;
            a[mt][0] = p0[4 * ((2 * s) ^ qr) + qc];
            a[mt][1] = p1[4 * ((2 * s) ^ qr) + qc];
            a[mt][2] = p0[4 * ((2 * s + 1) ^ qr) + qc];
            a[mt][3] = p1[4 * ((2 * s + 1) ^ qr) + qc];
        }
#pragma unroll
        for (int nt = 0; nt < NT; nt++) {
            int n = colB + nt * 8 + qr;
            const uint32_t* bb = sB + n * 32;
            uint32_t b[2] = { bb[4 * ((2 * s) ^ qr) + qc], bb[4 * ((2 * s + 1) ^ qr) + qc] };
#pragma unroll
            for (int mt = 0; mt < 2; mt++) mma16(acc[mt][nt], a[mt], b);
        }
    }
}

// ---------------- weight prep: fp32 [K][N] -> fp16 transposed [N][K] ----------------
__global__ void prep_w(const float* __restrict__ pw0, const float* __restrict__ wl0,
                       const float* __restrict__ wr0, const float* __restrict__ pw1,
                       const float* __restrict__ wl1, const float* __restrict__ wr1,
                       const float* __restrict__ pw2, const float* __restrict__ wl2,
                       const float* __restrict__ wr2, __half* __restrict__ wt) {
    int id = blockIdx.x * blockDim.x + threadIdx.x;
    const float* src; int K, N, off, loc;
    if (id < 16384)      { src = pw0; K = 128; N = 128; off = 0;     loc = id; }
    else if (id < 24576) { src = wl0; K = 128; N = 64;  off = 16384; loc = id - 16384; }
    else if (id < 32768) { src = wr0; K = 128; N = 64;  off = 24576; loc = id - 24576; }
    else if (id < 36864) { src = pw1; K = 64;  N = 64;  off = 32768; loc = id - 32768; }
    else if (id < 40960) { src = wl1; K = 64;  N = 64;  off = 36864; loc = id - 36864; }
    else if (id < 45056) { src = wr1; K = 64;  N = 64;  off = 40960; loc = id - 40960; }
    else if (id < 49152) { src = pw2; K = 64;  N = 64;  off = 45056; loc = id - 45056; }
    else if (id < 53248) { src = wl2; K = 64;  N = 64;  off = 49152; loc = id - 49152; }
    else if (id < 57344) { src = wr2; K = 64;  N = 64;  off = 53248; loc = id - 53248; }
    else return;
    int n = loc / K, k = loc % K;
    wt[off + loc] = __float2half(src[(size_t)k * N + n]);
}

// ---------------- init ----------------
__global__ void init_kernel() {
    int j = blockIdx.x * blockDim.x + threadIdx.x;
    if (j < NN) { g_deg[j] = 0; g_cursor[j] = 0; }
    if (j < NG * 64) { g_gmax[j] = 0x007FFFFFu; g_gsum[j] = 0.f; }
    if (j < NG) g_gcnt[j] = 0;
}

// ---------------- CSR build ----------------
__global__ void hist_kernel(const int* __restrict__ dst) {
    int e = blockIdx.x * blockDim.x + threadIdx.x;
    if (e < NE) atomicAdd(&g_deg[dst[e]], 1);
}

__global__ void scan1_kernel() {
    __shared__ int wsum[8];
    int b = blockIdx.x, tid = threadIdx.x, lane = tid & 31, w = tid >> 5;
    int i0 = b * 1024 + tid * 4;
    int s = 0;
#pragma unroll
    for (int j = 0; j < 4; j++) { int i = i0 + j; if (i < NN) s += g_deg[i]; }
#pragma unroll
    for (int o = 16; o > 0; o >>= 1) s += __shfl_xor_sync(0xffffffffu, s, o);
    if (lane == 0) wsum[w] = s;
    __syncthreads();
    if (tid == 0) {
        int t = 0;
#pragma unroll
        for (int k = 0; k < 8; k++) t += wsum[k];
        g_bsum[b] = t;
    }
}

__global__ void scan2_kernel() {
    __shared__ int ws[4];
    int tid = threadIdx.x, lane = tid & 31, w = tid >> 5;
    int v = (tid < NBLK) ? g_bsum[tid] : 0;
    int si = v;
#pragma unroll
    for (int o = 1; o < 32; o <<= 1) { int t = __shfl_up_sync(0xffffffffu, si, o); if (lane >= o) si += t; }
    if (lane == 31) ws[w] = si;
    __syncthreads();
    if (tid == 0) {
        int run = 0;
#pragma unroll
        for (int k = 0; k < 4; k++) { int t = ws[k]; ws[k] = run; run += t; }
        g_rowptr[NN] = run;
    }
    __syncthreads();
    if (tid < NBLK) g_boff[tid] = ws[w] + si - v;
}

__global__ void scan3_kernel() {
    __shared__ int wsum[8];
    int b = blockIdx.x, tid = threadIdx.x, lane = tid & 31, w = tid >> 5;
    int i0 = b * 1024 + tid * 4;
    int v[4], s = 0;
#pragma unroll
    for (int j = 0; j < 4; j++) { int i = i0 + j; v[j] = (i < NN) ? g_deg[i] : 0; s += v[j]; }
    int si = s;
#pragma unroll
    for (int o = 1; o < 32; o <<= 1) { int t = __shfl_up_sync(0xffffffffu, si, o); if (lane >= o) si += t; }
    if (lane == 31) wsum[w] = si;
    __syncthreads();
    if (tid == 0) {
        int run = 0;
#pragma unroll
        for (int k = 0; k < 8; k++) { int t = wsum[k]; wsum[k] = run; run += t; }
    }
    __syncthreads();
    int off = g_boff[b] + wsum[w] + (si - s);
#pragma unroll
    for (int j = 0; j < 4; j++) { int i = i0 + j; if (i < NN) g_rowptr[i] = off; off += v[j]; }
}

__global__ void fill_adj_kernel(const int* __restrict__ src, const int* __restrict__ dst) {
    int e = blockIdx.x * blockDim.x + threadIdx.x;
    if (e < NE) {
        int d = dst[e];
        int p = atomicAdd(&g_cursor[d], 1);
        g_adj[g_rowptr[d] + p] = src[e];
    }
}

// ---------------- lin (fp32 sources -> half2 output), unchanged from R10 ----------------
__device__ __forceinline__ float4 lin_ld4(const float* nf, const float* cf,
                                          const int* opc, const float* emb, int grow, int k) {
    float4 v = make_float4(0, 0, 0, 0);
    if (k < 140)      v = *(const float4*)(nf + (size_t)grow * 140 + k);
    else if (k < 172) v = *(const float4*)(emb + (size_t)opc[grow] * 32 + (k - 140));
    else if (k < 190) {
        const float* cp = cf + (size_t)grow * 18;
        int off = k - 172;
        v.x = cp[off];
        v.y = (off + 1 < 18) ? cp[off + 1] : 0.f;
        v.z = (off + 2 < 18) ? cp[off + 2] : 0.f;
        v.w = (off + 3 < 18) ? cp[off + 3] : 0.f;
    }
    return v;
}

__global__ void __launch_bounds__(256)
lin_h(const float* __restrict__ nf, const float* __restrict__ cf,
      const int* __restrict__ opc, const float* __restrict__ emb,
      const float* __restrict__ W, const float* __restrict__ bias,
      uint32_t* __restrict__ C) {
    extern __shared__ uint32_t smem[];
    const int tid = threadIdx.x, lane = tid & 31, wid = tid >> 5;
    const int warpM = wid & 3, warpN = wid >> 2;
    const int rowBase = blockIdx.x * 128;
    const int n0 = blockIdx.y * 64;

    float acc[2][4][4];
#pragma unroll
    for (int mt = 0; mt < 2; mt++)
#pragma unroll
        for (int nt = 0; nt < 4; nt++)
#pragma unroll
            for (int q = 0; q < 4; q++) acc[mt][nt][q] = 0.f;

    uint4 ra[2], rb;
    auto loadC = [&](int c) {
#pragma unroll
        for (int i = 0; i < 2; i++) {
            int g = tid + 256 * i;
            int row = g & 127, qq = g >> 7;
            int grow = rowBase + row;
            uint4 w = make_uint4(0, 0, 0, 0);
            if (grow < NN) {
                float4 v0 = lin_ld4(nf, cf, opc, emb, grow, c * 32 + 8 * qq);
                float4 v1 = lin_ld4(nf, cf, opc, emb, grow, c * 32 + 8 * qq + 4);
                w = make_uint4(f2h2(v0.x, v0.y), f2h2(v0.z, v0.w), f2h2(v1.x, v1.y), f2h2(v1.z, v1.w));
            }
            ra[i] = w;
        }
        {
            int n = tid & 63, qq = tid >> 6;
            float f[8];
#pragma unroll
            for (int j = 0; j < 8; j++) {
                int kg = c * 32 + 8 * qq + j;
                f[j] = (kg < 190) ? W[(size_t)kg * 128 + n0 + n] : 0.f;
            }
            rb = make_uint4(f2h2(f[0], f[1]), f2h2(f[2], f[3]), f2h2(f[4], f[5]), f2h2(f[6], f[7]));
        }
    };
    auto stage = [&](int b) {
        uint32_t* sa = smem + (b ? 4096 : 0);
        uint32_t* sb = smem + 8192 + (b ? 2048 : 0);
#pragma unroll
        for (int i = 0; i < 2; i++) {
            int g = tid + 256 * i;
            stTile4(sa, g & 127, g >> 7, ra[i]);
        }
        stTile4(sb, tid & 63, tid >> 6, rb);
    };

    loadC(0); stage(0); __syncthreads();
#pragma unroll 1
    for (int c = 0; c < 6; c++) {
        if (c < 5) loadC(c + 1);
        const uint32_t* sa = smem + ((c & 1) ? 4096 : 0);
        const uint32_t* sb = smem + 8192 + ((c & 1) ? 2048 : 0);
        chunk_mma_h<4>(sa, sb, acc, warpM * 32, warpN * 32, lane);
        if (c < 5) { stage((c + 1) & 1); __syncthreads(); }
    }

    const int qr = lane >> 2, qc = lane & 3;
#pragma unroll
    for (int mt = 0; mt < 2; mt++) {
        int r0 = rowBase + warpM * 32 + mt * 16 + qr;
#pragma unroll
        for (int nt = 0; nt < 4; nt++) {
            int gc = n0 + warpN * 32 + nt * 8 + 2 * qc;
            float b0 = __ldg(&bias[gc]), b1 = __ldg(&bias[gc + 1]);
            if (r0 < NN)
                C[(size_t)r0 * 64 + gc / 2] =
                    f2h2(fmaxf(acc[mt][nt][0] + b0, 0.f), fmaxf(acc[mt][nt][1] + b1, 0.f));
            if (r0 + 8 < NN)
                C[(size_t)(r0 + 8) * 64 + gc / 2] =
                    f2h2(fmaxf(acc[mt][nt][2] + b0, 0.f), fmaxf(acc[mt][nt][3] + b1, 0.f));
        }
    }
}

// ---------------- projz (cp.async): Z = relu(A@PW + PB) @ WL ----------------
template <int K>
__global__ void __launch_bounds__(256)
projz_cp(const uint32_t* __restrict__ A, const __half* __restrict__ PWt,
         const float* __restrict__ PB, const __half* __restrict__ WLt,
         __half2* __restrict__ Z) {
    constexpr int NCH = K / 32;
    constexpr int CW = K / 2;
    constexpr int NT1 = CW / 8;
    constexpr int INB = K * 32;                 // B tile words per buffer
    constexpr int INW = 8192 + 2 * INB;
    constexpr int XW = NCH * 4096;
    constexpr int UW = (INW > XW) ? INW : XW;
    constexpr int NST = K / 64;                 // B cp.async per thread per chunk
    extern __shared__ uint32_t smem[];
    uint32_t* W2 = smem + UW;
    const uint32_t smb = smem_u32(smem);

    const int tid = threadIdx.x, lane = tid & 31, wid = tid >> 5;
    const int warpM = wid & 3, warpN = wid >> 2;
    const int rowBase = blockIdx.x * 128;
    const int qr = lane >> 2, qc = lane & 3;

    auto issueA = [&](int c, int b) {
#pragma unroll
        for (int i = 0; i < 2; i++) {
            int g = tid + 256 * i;
            int row = g & 127, qq = g >> 7;
            int grow = rowBase + row;
            CPA16(tileAddr(smb, b ? 4096 : 0, row, qq),
                  A + (size_t)grow * (K / 2) + c * 16 + 4 * qq);
        }
    };
    auto issueB = [&](int c, int b) {
#pragma unroll
        for (int i = 0; i < NST; i++) {
            int g = tid + 256 * i;
            int n = g % K, qq = g / K;
            CPA16(tileAddr(smb, 8192 + (b ? INB : 0), n, qq),
                  PWt + (size_t)n * K + c * 32 + 8 * qq);
        }
    };
    // WL tiles once (into W2 region)
#pragma unroll
    for (int c = 0; c < NCH; c++) {
        int n = tid & 63, qq = tid >> 6;
        CPA16(tileAddr(smb, UW + c * 2048, n, qq),
              WLt + (size_t)n * K + c * 32 + 8 * qq);
    }
    issueA(0, 0); issueB(0, 0); CPA_COMMIT();

    float acc1[2][NT1][4];
#pragma unroll
    for (int mt = 0; mt < 2; mt++)
#pragma unroll
        for (int nt = 0; nt < NT1; nt++)
#pragma unroll
            for (int q = 0; q < 4; q++) acc1[mt][nt][q] = 0.f;

#pragma unroll 1
    for (int c = 0; c < NCH; c++) {
        CPA_WAIT0();
        __syncthreads();
        if (c + 1 < NCH) { issueA(c + 1, (c + 1) & 1); issueB(c + 1, (c + 1) & 1); CPA_COMMIT(); }
        const uint32_t* sa = smem + ((c & 1) ? 4096 : 0);
        const uint32_t* sb = smem + 8192 + ((c & 1) ? INB : 0);
        chunk_mma_h<NT1>(sa, sb, acc1, warpM * 32, warpN * CW, lane);
    }
    __syncthreads();  // phase-1 reads done before overwrite

    // restage xp = relu(acc1 + PB) into X tiles (half2)
#pragma unroll
    for (int mt = 0; mt < 2; mt++) {
        int r0 = warpM * 32 + mt * 16 + qr;
#pragma unroll
        for (int nt = 0; nt < NT1; nt++) {
            int col = warpN * CW + nt * 8 + 2 * qc;
            float b0 = __ldg(&PB[col]), b1 = __ldg(&PB[col + 1]);
            stXh(smem, r0, col / 2,
                 f2h2(fmaxf(acc1[mt][nt][0] + b0, 0.f), fmaxf(acc1[mt][nt][1] + b1, 0.f)));
            stXh(smem, r0 + 8, col / 2,
                 f2h2(fmaxf(acc1[mt][nt][2] + b0, 0.f), fmaxf(acc1[mt][nt][3] + b1, 0.f)));
        }
    }
    __syncthreads();

    float acc2[2][4][4];
#pragma unroll
    for (int mt = 0; mt < 2; mt++)
#pragma unroll
        for (int nt = 0; nt < 4; nt++)
#pragma unroll
            for (int q = 0; q < 4; q++) acc2[mt][nt][q] = 0.f;
#pragma unroll
    for (int c = 0; c < NCH; c++)
        chunk_mma_h<4>(smem + c * 4096, W2 + c * 2048, acc2, warpM * 32, warpN * 32, lane);

#pragma unroll
    for (int mt = 0; mt < 2; mt++) {
        int r0 = rowBase + warpM * 32 + mt * 16 + qr;
#pragma unroll
        for (int nt = 0; nt < 4; nt++) {
            int gc = warpN * 32 + nt * 8 + 2 * qc;
            if (r0 < NN)
                Z[(size_t)r0 * 32 + gc / 2] = __floats2half2_rn(acc2[mt][nt][0], acc2[mt][nt][1]);
            if (r0 + 8 < NN)
                Z[(size_t)(r0 + 8) * 32 + gc / 2] = __floats2half2_rn(acc2[mt][nt][2], acc2[mt][nt][3]);
        }
    }
}

// ---------------- combine (cp.async): out = normalize(X@WR + MZ + BL) ----------------
template <int K, bool HOUT>
__global__ void __launch_bounds__(256)
combine_cp(const uint32_t* __restrict__ X, const __half* __restrict__ WRt,
           const float* __restrict__ MZ, const float* __restrict__ BL,
           void* __restrict__ Cout) {
    constexpr int NCH = K / 32;
    extern __shared__ uint32_t smem[];
    const uint32_t smb = smem_u32(smem);
    const int tid = threadIdx.x, lane = tid & 31, wid = tid >> 5;
    const int warpM = wid & 3, warpN = wid >> 2;
    const int rowBase = blockIdx.x * 128;

    auto issueA = [&](int c, int b) {
#pragma unroll
        for (int i = 0; i < 2; i++) {
            int g = tid + 256 * i;
            int row = g & 127, qq = g >> 7;
            int grow = rowBase + row;
            CPA16(tileAddr(smb, b ? 4096 : 0, row, qq),
                  X + (size_t)grow * (K / 2) + c * 16 + 4 * qq);
        }
    };
    auto issueB = [&](int c, int b) {
        int n = tid & 63, qq = tid >> 6;
        CPA16(tileAddr(smb, 8192 + (b ? 2048 : 0), n, qq),
              WRt + (size_t)n * K + c * 32 + 8 * qq);
    };

    float acc[2][4][4];
#pragma unroll
    for (int mt = 0; mt < 2; mt++)
#pragma unroll
        for (int nt = 0; nt < 4; nt++)
#pragma unroll
            for (int q = 0; q < 4; q++) acc[mt][nt][q] = 0.f;

    issueA(0, 0); issueB(0, 0); CPA_COMMIT();
#pragma unroll 1
    for (int c = 0; c < NCH; c++) {
        CPA_WAIT0();
        __syncthreads();
        if (c + 1 < NCH) { issueA(c + 1, (c + 1) & 1); issueB(c + 1, (c + 1) & 1); CPA_COMMIT(); }
        const uint32_t* sa = smem + ((c & 1) ? 4096 : 0);
        const uint32_t* sb = smem + 8192 + ((c & 1) ? 2048 : 0);
        chunk_mma_h<4>(sa, sb, acc, warpM * 32, warpN * 32, lane);
    }

    // epilogue: + MZ + BL, stage to smem (stride 66), row-normalize
    __syncthreads();
    float (*sOut)[66] = reinterpret_cast<float(*)[66]>(smem);
    const int qr = lane >> 2, qc = lane & 3;
#pragma unroll
    for (int mt = 0; mt < 2; mt++) {
        int rl = warpM * 32 + mt * 16 + qr;
        int g0 = rowBase + rl, g1 = rowBase + rl + 8;
#pragma unroll
        for (int nt = 0; nt < 4; nt++) {
            int cl = warpN * 32 + nt * 8 + 2 * qc;
            float b0 = __ldg(&BL[cl]), b1 = __ldg(&BL[cl + 1]);
            float2 m0 = (g0 < NN) ? *(const float2*)(MZ + (size_t)g0 * 64 + cl) : make_float2(0, 0);
            float2 m1 = (g1 < NN) ? *(const float2*)(MZ + (size_t)g1 * 64 + cl) : make_float2(0, 0);
            sOut[rl][cl]         = acc[mt][nt][0] + b0 + m0.x;
            sOut[rl][cl + 1]     = acc[mt][nt][1] + b1 + m0.y;
            sOut[rl + 8][cl]     = acc[mt][nt][2] + b0 + m1.x;
            sOut[rl + 8][cl + 1] = acc[mt][nt][3] + b1 + m1.y;
        }
    }
    __syncthreads();
#pragma unroll
    for (int rr = 0; rr < 16; rr++) {
        int r = wid * 16 + rr;
        int grow = rowBase + r;
        float2 v = *(const float2*)&sOut[r][2 * lane];
        float ss = v.x * v.x + v.y * v.y;
#pragma unroll
        for (int o = 16; o > 0; o >>= 1) ss += __shfl_xor_sync(0xffffffffu, ss, o);
        float sc = 1.0f / fmaxf(sqrtf(ss), 1e-12f);
        if (grow < NN) {
            if (HOUT) {
                ((uint32_t*)Cout)[(size_t)grow * 32 + lane] = f2h2(v.x * sc, v.y * sc);
            } else {
                *(float2*)((float*)Cout + (size_t)grow * 64 + 2 * lane) =
                    make_float2(v.x * sc, v.y * sc);
            }
        }
    }
}

// ---------------- mean aggregation over CSR (64-dim, half2 source, x4 MLP) ----------------
__global__ void agg_half(const __half2* __restrict__ zp, float* __restrict__ msg) {
    int w = (blockIdx.x * blockDim.x + threadIdx.x) >> 5;
    int lane = threadIdx.x & 31;
    if (w >= NN) return;
    int beg = g_rowptr[w], end = g_rowptr[w + 1];
    float2 acc = make_float2(0, 0);
    int e = beg;
    for (; e + 4 <= end; e += 4) {
        int s0 = __ldg(&g_adj[e]);
        int s1 = __ldg(&g_adj[e + 1]);
        int s2 = __ldg(&g_adj[e + 2]);
        int s3 = __ldg(&g_adj[e + 3]);
        float2 v0 = __half22float2(zp[(size_t)s0 * 32 + lane]);
        float2 v1 = __half22float2(zp[(size_t)s1 * 32 + lane]);
        float2 v2 = __half22float2(zp[(size_t)s2 * 32 + lane]);
        float2 v3 = __half22float2(zp[(size_t)s3 * 32 + lane]);
        acc.x += (v0.x + v1.x) + (v2.x + v3.x);
        acc.y += (v0.y + v1.y) + (v2.y + v3.y);
    }
    for (; e < end; e++) {
        int s = __ldg(&g_adj[e]);
        float2 v = __half22float2(zp[(size_t)s * 32 + lane]);
        acc.x += v.x; acc.y += v.y;
    }
    float inv = 1.0f / fmaxf((float)(end - beg), 1.0f);
    *reinterpret_cast<float2*>(msg + (size_t)w * 64 + lane * 2) =
        make_float2(acc.x * inv, acc.y * inv);
}

// ---------------- pooling ----------------
__global__ void pool_kernel(const float* __restrict__ x, const int* __restrict__ batch) {
    int nwarps = (gridDim.x * blockDim.x) >> 5;
    int w = (blockIdx.x * blockDim.x + threadIdx.x) >> 5;
    int lane = threadIdx.x & 31;
    int per = (NN + nwarps - 1) / nwarps;
    int s = w * per;
    int e = min(NN, s + per);
    if (s >= e) return;
    float m0 = -__int_as_float(0x7f800000), m1 = m0;
    float s0 = 0.f, s1 = 0.f;
    int cnt = 0;
    int curg = __ldg(&batch[s]);
    for (int i = s; i < e; i++) {
        int g = __ldg(&batch[i]);
        if (g != curg) {
            atomicMax(&g_gmax[curg * 64 + lane], fenc(m0));
            atomicMax(&g_gmax[curg * 64 + lane + 32], fenc(m1));
            atomicAdd(&g_gsum[curg * 64 + lane], s0);
            atomicAdd(&g_gsum[curg * 64 + lane + 32], s1);
            if (lane == 0) atomicAdd(&g_gcnt[curg], cnt);
            m0 = m1 = -__int_as_float(0x7f800000);
            s0 = s1 = 0.f; cnt = 0; curg = g;
        }
        float v0 = x[(size_t)i * 64 + lane];
        float v1 = x[(size_t)i * 64 + lane + 32];
        m0 = fmaxf(m0, v0); m1 = fmaxf(m1, v1);
        s0 += v0; s1 += v1; cnt++;
    }
    atomicMax(&g_gmax[curg * 64 + lane], fenc(m0));
    atomicMax(&g_gmax[curg * 64 + lane + 32], fenc(m1));
    atomicAdd(&g_gsum[curg * 64 + lane], s0);
    atomicAdd(&g_gsum[curg * 64 + lane + 32], s1);
    if (lane == 0) atomicAdd(&g_gcnt[curg], cnt);
}

// ---------------- final ----------------
__global__ void final_kernel(const float* __restrict__ post_w, const float* __restrict__ post_b,
                             float* __restrict__ out) {
    int g = threadIdx.x;
    if (g >= NG) return;
    float inv = 1.0f / (float)g_gcnt[g];
    float v[64];
    float ss = 0.f;
#pragma unroll
    for (int c = 0; c < 64; c++) {
        float t = fdec(g_gmax[g * 64 + c]) + g_gsum[g * 64 + c] * inv;
        v[c] = t;
        ss += t * t;
    }
    float norm = sqrtf(ss);
    float dot = 0.f;
#pragma unroll
    for (int c = 0; c < 64; c++) dot += v[c] * post_w[c];
    out[g] = dot / norm + post_b[0];
}

// ---------------- launch ----------------
static cudaStream_t g_s2 = nullptr;
static cudaEvent_t g_ev1 = nullptr, g_ev2 = nullptr, g_evW = nullptr;

extern "C" void kernel_launch(void* const* d_in, const int* in_sizes, int n_in,
                              void* d_out, int out_size) {
    const float* node_feat = (const float*)d_in[0];
    const float* cfg_feat  = (const float*)d_in[1];
    const int*   opcode    = (const int*)d_in[2];
    const int*   edge      = (const int*)d_in[3];
    const int*   batch     = (const int*)d_in[4];
    const float* op_emb    = (const float*)d_in[5];
    const float* lin_w     = (const float*)d_in[6];
    const float* lin_b     = (const float*)d_in[7];
    const float* post_w    = (const float*)d_in[8];
    const float* post_b    = (const float*)d_in[9];
    const float* pw0 = (const float*)d_in[10];
    const float* pb0 = (const float*)d_in[11];
    const float* wl0 = (const float*)d_in[12];
    const float* bl0 = (const float*)d_in[13];
    const float* wr0 = (const float*)d_in[14];
    const float* pw1 = (const float*)d_in[15];
    const float* pb1 = (const float*)d_in[16];
    const float* wl1 = (const float*)d_in[17];
    const float* bl1 = (const float*)d_in[18];
    const float* wr1 = (const float*)d_in[19];
    const float* pw2 = (const float*)d_in[20];
    const float* pb2 = (const float*)d_in[21];
    const float* wl2 = (const float*)d_in[22];
    const float* bl2 = (const float*)d_in[23];
    const float* wr2 = (const float*)d_in[24];
    float* out = (float*)d_out;

    if (g_s2 == nullptr) {
        cudaStreamCreateWithFlags(&g_s2, cudaStreamNonBlocking);
        cudaEventCreateWithFlags(&g_ev1, cudaEventDisableTiming);
        cudaEventCreateWithFlags(&g_ev2, cudaEventDisableTiming);
        cudaEventCreateWithFlags(&g_evW, cudaEventDisableTiming);
        cudaFuncSetAttribute(projz_cp<128>, cudaFuncAttributeMaxDynamicSharedMemorySize, 98304);
        cudaFuncSetAttribute(projz_cp<64>,  cudaFuncAttributeMaxDynamicSharedMemorySize, 65536);
    }

    const int* src = edge;
    const int* dst = edge + NE;

    const int MB = (NN + 127) / 128;
    const int EB = (NE + 255) / 256;
    const int AGGB = (NN * 32 + 255) / 256;
    const size_t SMEM48 = 49152;
    const size_t SMEM_PZ128 = 98304;
    const size_t SMEM_PZ64  = 65536;

    uint32_t* dA; cudaGetSymbolAddress((void**)&dA, g_xA);
    uint32_t* dB; cudaGetSymbolAddress((void**)&dB, g_xB);
    float* dC; cudaGetSymbolAddress((void**)&dC, g_xC);
    __half2* dZ; cudaGetSymbolAddress((void**)&dZ, g_z);
    float* dM; cudaGetSymbolAddress((void**)&dM, g_msg);
    __half* dW; cudaGetSymbolAddress((void**)&dW, g_wt);

    const __half* pwt0 = dW;
    const __half* wlt0 = dW + 16384;
    const __half* wrt0 = dW + 24576;
    const __half* pwt1 = dW + 32768;
    const __half* wlt1 = dW + 36864;
    const __half* wrt1 = dW + 40960;
    const __half* pwt2 = dW + 45056;
    const __half* wlt2 = dW + 49152;
    const __half* wrt2 = dW + 53248;

    // fork: weight prep + CSR build on side stream
    cudaEventRecord(g_ev1, 0);
    cudaStreamWaitEvent(g_s2, g_ev1, 0);
    prep_w<<<224, 256, 0, g_s2>>>(pw0, wl0, wr0, pw1, wl1, wr1, pw2, wl2, wr2, dW);
    cudaEventRecord(g_evW, g_s2);
    init_kernel<<<(NN + 255) / 256, 256, 0, g_s2>>>();
    hist_kernel<<<EB, 256, 0, g_s2>>>(dst);
    scan1_kernel<<<NBLK, 256, 0, g_s2>>>();
    scan2_kernel<<<1, 128, 0, g_s2>>>();
    scan3_kernel<<<NBLK, 256, 0, g_s2>>>();
    fill_adj_kernel<<<EB, 256, 0, g_s2>>>(src, dst);
    cudaEventRecord(g_ev2, g_s2);

    lin_h<<<dim3(MB, 2), 256, SMEM48>>>(node_feat, cfg_feat, opcode, op_emb, lin_w, lin_b, dA);
    cudaStreamWaitEvent(0, g_evW, 0);   // weights ready
    projz_cp<128><<<MB, 256, SMEM_PZ128>>>(dA, pwt0, pb0, wlt0, dZ);

    cudaStreamWaitEvent(0, g_ev2, 0);   // CSR ready

    // layer 0 (d=128 -> 64)
    agg_half<<<AGGB, 256>>>(dZ, dM);
    combine_cp<128, true><<<MB, 256, SMEM48>>>(dA, wrt0, dM, bl0, dB);

    // layer 1 (d=64 -> 64)
    projz_cp<64><<<MB, 256, SMEM_PZ64>>>(dB, pwt1, pb1, wlt1, dZ);
    agg_half<<<AGGB, 256>>>(dZ, dM);
    combine_cp<64, true><<<MB, 256, SMEM48>>>(dB, wrt1, dM, bl1, dA);

    // layer 2 (d=64 -> 64), fp32 output for pooling
    projz_cp<64><<<MB, 256, SMEM_PZ64>>>(dA, pwt2, pb2, wlt2, dZ);
    agg_half<<<AGGB, 256>>>(dZ, dM);
    combine_cp<64, false><<<MB, 256, SMEM48>>>(dA, wrt2, dM, bl2, dC);

    pool_kernel<<<128, 256>>>(dC, batch);
    final_kernel<<<1, 64>>>(post_w, post_b, out);
}

// round 13
// speedup vs baseline: 1.1528x; 1.0515x over previous
#include <cuda_runtime.h>
#include <cuda_fp16.h>
#include <cstdint>

#define NN 100000
#define NE 1600000
#define NG 64
#define NBLK 98   // ceil(NN/1024)

// ---------------- scratch ----------------
__device__ __align__(256) uint32_t g_xA[(size_t)NN * 64];
__device__ __align__(256) uint32_t g_xB[(size_t)NN * 64];
__device__ __align__(256) float g_xC[(size_t)NN * 64];   // fp32 final-layer output
__device__ __align__(256) __half2 g_z[(size_t)NN * 32];
__device__ __align__(256) float g_msg[(size_t)NN * 64];
__device__ __align__(256) __half g_wt[57344];            // transposed fp16 weights
__device__ int g_deg[NN];
__device__ int g_cursor[NN];
__device__ int g_rowptr[NN + 1];
__device__ int g_adj[NE];
__device__ int g_bsum[NBLK];
__device__ int g_boff[NBLK];
__device__ unsigned g_gmax[NG * 64];
__device__ float g_gsum[NG * 64];
__device__ int g_gcnt[NG];

// ---------------- helpers ----------------
__device__ __forceinline__ uint32_t f2h2(float lo, float hi) {
    __half2 h = __floats2half2_rn(lo, hi);
    return *reinterpret_cast<uint32_t*>(&h);
}
__device__ __forceinline__ void mma16(float* c, const uint32_t* a, const uint32_t* b) {
    asm volatile(
        "mma.sync.aligned.m16n8k16.row.col.f32.f16.f16.f32 "
        "{%0,%1,%2,%3}, {%4,%5,%6,%7}, {%8,%9}, {%0,%1,%2,%3};"
        : "+f"(c[0]), "+f"(c[1]), "+f"(c[2]), "+f"(c[3])
        : "r"(a[0]), "r"(a[1]), "r"(a[2]), "r"(a[3]), "r"(b[0]), "r"(b[1]));
}
__device__ __forceinline__ unsigned fenc(float f) {
    unsigned u = __float_as_uint(f);
    return (u & 0x80000000u) ? ~u : (u | 0x80000000u);
}
__device__ __forceinline__ float fdec(unsigned e) {
    return __uint_as_float((e & 0x80000000u) ? (e ^ 0x80000000u) : ~e);
}

// ---------------- fp16 XOR-swizzled tiles ----------------
__device__ __forceinline__ void stTile4(uint32_t* s, int row, int qq, uint4 w) {
    *reinterpret_cast<uint4*>(s + row * 32 + 4 * (qq ^ (row & 7))) = w;
}
__device__ __forceinline__ void stXh(uint32_t* sX, int row, int c2, uint32_t w) {
    uint32_t* t = sX + (c2 >> 4) * 4096;
    int lc = c2 & 15;
    t[row * 32 + 4 * ((lc >> 2) ^ (row & 7)) + (lc & 3)] = w;
}

template <int NT>
__device__ __forceinline__ void chunk_mma_h(const uint32_t* sA, const uint32_t* sB,
                                            float (&acc)[2][NT][4], int rowB, int colB, int lane) {
    const int qr = lane >> 2, qc = lane & 3;
#pragma unroll
    for (int s = 0; s < 2; s++) {
        uint32_t a[2][4];
#pragma unroll
        for (int mt = 0; mt < 2; mt++) {
            int r0 = rowB + mt * 16 + qr;
            const uint32_t* p0 = sA + r0 * 32;
            const uint32_t* p1 = sA + (r0 + 8) * 32;
            a[mt][0] = p0[4 * ((2 * s) ^ qr) + qc];
            a[mt][1] = p1[4 * ((2 * s) ^ qr) + qc];
            a[mt][2] = p0[4 * ((2 * s + 1) ^ qr) + qc];
            a[mt][3] = p1[4 * ((2 * s + 1) ^ qr) + qc];
        }
#pragma unroll
        for (int nt = 0; nt < NT; nt++) {
            int n = colB + nt * 8 + qr;
            const uint32_t* bb = sB + n * 32;
            uint32_t b[2] = { bb[4 * ((2 * s) ^ qr) + qc], bb[4 * ((2 * s + 1) ^ qr) + qc] };
#pragma unroll
            for (int mt = 0; mt < 2; mt++) mma16(acc[mt][nt], a[mt], b);
        }
    }
}

// ---------------- weight prep: fp32 [K][N] -> fp16 transposed [N][K] ----------------
__global__ void prep_w(const float* __restrict__ pw0, const float* __restrict__ wl0,
                       const float* __restrict__ wr0, const float* __restrict__ pw1,
                       const float* __restrict__ wl1, const float* __restrict__ wr1,
                       const float* __restrict__ pw2, const float* __restrict__ wl2,
                       const float* __restrict__ wr2, __half* __restrict__ wt) {
    int id = blockIdx.x * blockDim.x + threadIdx.x;
    const float* src; int K, N, off, loc;
    if (id < 16384)      { src = pw0; K = 128; N = 128; off = 0;     loc = id; }
    else if (id < 24576) { src = wl0; K = 128; N = 64;  off = 16384; loc = id - 16384; }
    else if (id < 32768) { src = wr0; K = 128; N = 64;  off = 24576; loc = id - 24576; }
    else if (id < 36864) { src = pw1; K = 64;  N = 64;  off = 32768; loc = id - 32768; }
    else if (id < 40960) { src = wl1; K = 64;  N = 64;  off = 36864; loc = id - 36864; }
    else if (id < 45056) { src = wr1; K = 64;  N = 64;  off = 40960; loc = id - 40960; }
    else if (id < 49152) { src = pw2; K = 64;  N = 64;  off = 45056; loc = id - 45056; }
    else if (id < 53248) { src = wl2; K = 64;  N = 64;  off = 49152; loc = id - 49152; }
    else if (id < 57344) { src = wr2; K = 64;  N = 64;  off = 53248; loc = id - 53248; }
    else return;
    int n = loc / K, k = loc % K;
    wt[off + loc] = __float2half(src[(size_t)k * N + n]);
}

// ---------------- init ----------------
__global__ void init_kernel() {
    int j = blockIdx.x * blockDim.x + threadIdx.x;
    if (j < NN) { g_deg[j] = 0; g_cursor[j] = 0; }
    if (j < NG * 64) { g_gmax[j] = 0x007FFFFFu; g_gsum[j] = 0.f; }
    if (j < NG) g_gcnt[j] = 0;
}

// ---------------- CSR build ----------------
__global__ void hist_kernel(const int* __restrict__ dst) {
    int e = blockIdx.x * blockDim.x + threadIdx.x;
    if (e < NE) atomicAdd(&g_deg[dst[e]], 1);
}

__global__ void scan1_kernel() {
    __shared__ int wsum[8];
    int b = blockIdx.x, tid = threadIdx.x, lane = tid & 31, w = tid >> 5;
    int i0 = b * 1024 + tid * 4;
    int s = 0;
#pragma unroll
    for (int j = 0; j < 4; j++) { int i = i0 + j; if (i < NN) s += g_deg[i]; }
#pragma unroll
    for (int o = 16; o > 0; o >>= 1) s += __shfl_xor_sync(0xffffffffu, s, o);
    if (lane == 0) wsum[w] = s;
    __syncthreads();
    if (tid == 0) {
        int t = 0;
#pragma unroll
        for (int k = 0; k < 8; k++) t += wsum[k];
        g_bsum[b] = t;
    }
}

__global__ void scan2_kernel() {
    __shared__ int ws[4];
    int tid = threadIdx.x, lane = tid & 31, w = tid >> 5;
    int v = (tid < NBLK) ? g_bsum[tid] : 0;
    int si = v;
#pragma unroll
    for (int o = 1; o < 32; o <<= 1) { int t = __shfl_up_sync(0xffffffffu, si, o); if (lane >= o) si += t; }
    if (lane == 31) ws[w] = si;
    __syncthreads();
    if (tid == 0) {
        int run = 0;
#pragma unroll
        for (int k = 0; k < 4; k++) { int t = ws[k]; ws[k] = run; run += t; }
        g_rowptr[NN] = run;
    }
    __syncthreads();
    if (tid < NBLK) g_boff[tid] = ws[w] + si - v;
}

__global__ void scan3_kernel() {
    __shared__ int wsum[8];
    int b = blockIdx.x, tid = threadIdx.x, lane = tid & 31, w = tid >> 5;
    int i0 = b * 1024 + tid * 4;
    int v[4], s = 0;
#pragma unroll
    for (int j = 0; j < 4; j++) { int i = i0 + j; v[j] = (i < NN) ? g_deg[i] : 0; s += v[j]; }
    int si = s;
#pragma unroll
    for (int o = 1; o < 32; o <<= 1) { int t = __shfl_up_sync(0xffffffffu, si, o); if (lane >= o) si += t; }
    if (lane == 31) wsum[w] = si;
    __syncthreads();
    if (tid == 0) {
        int run = 0;
#pragma unroll
        for (int k = 0; k < 8; k++) { int t = wsum[k]; wsum[k] = run; run += t; }
    }
    __syncthreads();
    int off = g_boff[b] + wsum[w] + (si - s);
#pragma unroll
    for (int j = 0; j < 4; j++) { int i = i0 + j; if (i < NN) g_rowptr[i] = off; off += v[j]; }
}

__global__ void fill_adj_kernel(const int* __restrict__ src, const int* __restrict__ dst) {
    int e = blockIdx.x * blockDim.x + threadIdx.x;
    if (e < NE) {
        int d = dst[e];
        int p = atomicAdd(&g_cursor[d], 1);
        g_adj[g_rowptr[d] + p] = src[e];
    }
}

// ---------------- lin ----------------
__device__ __forceinline__ float4 lin_ld4(const float* nf, const float* cf,
                                          const int* opc, const float* emb, int grow, int k) {
    float4 v = make_float4(0, 0, 0, 0);
    if (k < 140)      v = *(const float4*)(nf + (size_t)grow * 140 + k);
    else if (k < 172) v = *(const float4*)(emb + (size_t)opc[grow] * 32 + (k - 140));
    else if (k < 190) {
        const float* cp = cf + (size_t)grow * 18;
        int off = k - 172;
        v.x = cp[off];
        v.y = (off + 1 < 18) ? cp[off + 1] : 0.f;
        v.z = (off + 2 < 18) ? cp[off + 2] : 0.f;
        v.w = (off + 3 < 18) ? cp[off + 3] : 0.f;
    }
    return v;
}

__global__ void __launch_bounds__(256)
lin_h(const float* __restrict__ nf, const float* __restrict__ cf,
      const int* __restrict__ opc, const float* __restrict__ emb,
      const float* __restrict__ W, const float* __restrict__ bias,
      uint32_t* __restrict__ C) {
    extern __shared__ uint32_t smem[];
    const int tid = threadIdx.x, lane = tid & 31, wid = tid >> 5;
    const int warpM = wid & 3, warpN = wid >> 2;
    const int rowBase = blockIdx.x * 128;
    const int n0 = blockIdx.y * 64;

    float acc[2][4][4];
#pragma unroll
    for (int mt = 0; mt < 2; mt++)
#pragma unroll
        for (int nt = 0; nt < 4; nt++)
#pragma unroll
            for (int q = 0; q < 4; q++) acc[mt][nt][q] = 0.f;

    uint4 ra[2], rb;
    auto loadC = [&](int c) {
#pragma unroll
        for (int i = 0; i < 2; i++) {
            int g = tid + 256 * i;
            int row = g & 127, qq = g >> 7;
            int grow = rowBase + row;
            uint4 w = make_uint4(0, 0, 0, 0);
            if (grow < NN) {
                float4 v0 = lin_ld4(nf, cf, opc, emb, grow, c * 32 + 8 * qq);
                float4 v1 = lin_ld4(nf, cf, opc, emb, grow, c * 32 + 8 * qq + 4);
                w = make_uint4(f2h2(v0.x, v0.y), f2h2(v0.z, v0.w), f2h2(v1.x, v1.y), f2h2(v1.z, v1.w));
            }
            ra[i] = w;
        }
        {
            int n = tid & 63, qq = tid >> 6;
            float f[8];
#pragma unroll
            for (int j = 0; j < 8; j++) {
                int kg = c * 32 + 8 * qq + j;
                f[j] = (kg < 190) ? W[(size_t)kg * 128 + n0 + n] : 0.f;
            }
            rb = make_uint4(f2h2(f[0], f[1]), f2h2(f[2], f[3]), f2h2(f[4], f[5]), f2h2(f[6], f[7]));
        }
    };
    auto stage = [&](int b) {
        uint32_t* sa = smem + (b ? 4096 : 0);
        uint32_t* sb = smem + 8192 + (b ? 2048 : 0);
#pragma unroll
        for (int i = 0; i < 2; i++) {
            int g = tid + 256 * i;
            stTile4(sa, g & 127, g >> 7, ra[i]);
        }
        stTile4(sb, tid & 63, tid >> 6, rb);
    };

    loadC(0); stage(0); __syncthreads();
#pragma unroll 1
    for (int c = 0; c < 6; c++) {
        if (c < 5) loadC(c + 1);
        const uint32_t* sa = smem + ((c & 1) ? 4096 : 0);
        const uint32_t* sb = smem + 8192 + ((c & 1) ? 2048 : 0);
        chunk_mma_h<4>(sa, sb, acc, warpM * 32, warpN * 32, lane);
        if (c < 5) { stage((c + 1) & 1); __syncthreads(); }
    }

    const int qr = lane >> 2, qc = lane & 3;
#pragma unroll
    for (int mt = 0; mt < 2; mt++) {
        int r0 = rowBase + warpM * 32 + mt * 16 + qr;
#pragma unroll
        for (int nt = 0; nt < 4; nt++) {
            int gc = n0 + warpN * 32 + nt * 8 + 2 * qc;
            float b0 = __ldg(&bias[gc]), b1 = __ldg(&bias[gc + 1]);
            if (r0 < NN)
                C[(size_t)r0 * 64 + gc / 2] =
                    f2h2(fmaxf(acc[mt][nt][0] + b0, 0.f), fmaxf(acc[mt][nt][1] + b1, 0.f));
            if (r0 + 8 < NN)
                C[(size_t)(r0 + 8) * 64 + gc / 2] =
                    f2h2(fmaxf(acc[mt][nt][2] + b0, 0.f), fmaxf(acc[mt][nt][3] + b1, 0.f));
        }
    }
}

// ---------------- projz: Z(half2) = relu(A@PW + PB) @ WL, prepped fp16 weights ----------------
template <int K>
__global__ void __launch_bounds__(256)
projz_h(const uint32_t* __restrict__ A, const __half* __restrict__ PWt,
        const float* __restrict__ PB, const __half* __restrict__ WLt,
        __half2* __restrict__ Z) {
    constexpr int NCH = K / 32;
    constexpr int CW = K / 2;
    constexpr int NT1 = CW / 8;
    constexpr int INB = K * 32;
    constexpr int INW = 8192 + 2 * INB;
    constexpr int XW = NCH * 4096;
    constexpr int UW = (INW > XW) ? INW : XW;
    constexpr int NST = K / 64;
    extern __shared__ uint32_t smem[];
    uint32_t* W2 = smem + UW;

    const int tid = threadIdx.x, lane = tid & 31, wid = tid >> 5;
    const int warpM = wid & 3, warpN = wid >> 2;
    const int rowBase = blockIdx.x * 128;
    const int qr = lane >> 2, qc = lane & 3;

    // stage WL chunks once (one LDG.128 each)
#pragma unroll
    for (int c = 0; c < NCH; c++) {
        int n = tid & 63, qq = tid >> 6;
        uint4 w = *reinterpret_cast<const uint4*>(WLt + (size_t)n * K + c * 32 + 8 * qq);
        stTile4(W2 + c * 2048, n, qq, w);
    }

    float acc1[2][NT1][4];
#pragma unroll
    for (int mt = 0; mt < 2; mt++)
#pragma unroll
        for (int nt = 0; nt < NT1; nt++)
#pragma unroll
            for (int q = 0; q < 4; q++) acc1[mt][nt][q] = 0.f;

    uint4 ra[2], rb[NST];
    auto loadC = [&](int c) {
#pragma unroll
        for (int i = 0; i < 2; i++) {
            int g = tid + 256 * i;
            int row = g & 127, qq = g >> 7;
            int grow = rowBase + row;
            ra[i] = (grow < NN)
                ? *reinterpret_cast<const uint4*>(A + (size_t)grow * (K / 2) + c * 16 + 4 * qq)
                : make_uint4(0, 0, 0, 0);
        }
#pragma unroll
        for (int i = 0; i < NST; i++) {
            int g = tid + 256 * i;
            int n = g % K, qq = g / K;
            rb[i] = *reinterpret_cast<const uint4*>(PWt + (size_t)n * K + c * 32 + 8 * qq);
        }
    };
    auto stage = [&](int b) {
        uint32_t* sa = smem + (b ? 4096 : 0);
        uint32_t* sb = smem + 8192 + (b ? INB : 0);
#pragma unroll
        for (int i = 0; i < 2; i++) {
            int g = tid + 256 * i;
            stTile4(sa, g & 127, g >> 7, ra[i]);
        }
#pragma unroll
        for (int i = 0; i < NST; i++) {
            int g = tid + 256 * i;
            stTile4(sb, g % K, g / K, rb[i]);
        }
    };

    loadC(0); stage(0); __syncthreads();
#pragma unroll 1
    for (int c = 0; c < NCH; c++) {
        if (c + 1 < NCH) loadC(c + 1);
        const uint32_t* sa = smem + ((c & 1) ? 4096 : 0);
        const uint32_t* sb = smem + 8192 + ((c & 1) ? INB : 0);
        chunk_mma_h<NT1>(sa, sb, acc1, warpM * 32, warpN * CW, lane);
        if (c + 1 < NCH) { stage((c + 1) & 1); __syncthreads(); }
    }
    __syncthreads();

#pragma unroll
    for (int mt = 0; mt < 2; mt++) {
        int r0 = warpM * 32 + mt * 16 + qr;
#pragma unroll
        for (int nt = 0; nt < NT1; nt++) {
            int col = warpN * CW + nt * 8 + 2 * qc;
            float b0 = __ldg(&PB[col]), b1 = __ldg(&PB[col + 1]);
            stXh(smem, r0, col / 2,
                 f2h2(fmaxf(acc1[mt][nt][0] + b0, 0.f), fmaxf(acc1[mt][nt][1] + b1, 0.f)));
            stXh(smem, r0 + 8, col / 2,
                 f2h2(fmaxf(acc1[mt][nt][2] + b0, 0.f), fmaxf(acc1[mt][nt][3] + b1, 0.f)));
        }
    }
    __syncthreads();

    float acc2[2][4][4];
#pragma unroll
    for (int mt = 0; mt < 2; mt++)
#pragma unroll
        for (int nt = 0; nt < 4; nt++)
#pragma unroll
            for (int q = 0; q < 4; q++) acc2[mt][nt][q] = 0.f;
#pragma unroll
    for (int c = 0; c < NCH; c++)
        chunk_mma_h<4>(smem + c * 4096, W2 + c * 2048, acc2, warpM * 32, warpN * 32, lane);

#pragma unroll
    for (int mt = 0; mt < 2; mt++) {
        int r0 = rowBase + warpM * 32 + mt * 16 + qr;
#pragma unroll
        for (int nt = 0; nt < 4; nt++) {
            int gc = warpN * 32 + nt * 8 + 2 * qc;
            if (r0 < NN)
                Z[(size_t)r0 * 32 + gc / 2] = __floats2half2_rn(acc2[mt][nt][0], acc2[mt][nt][1]);
            if (r0 + 8 < NN)
                Z[(size_t)(r0 + 8) * 32 + gc / 2] = __floats2half2_rn(acc2[mt][nt][2], acc2[mt][nt][3]);
        }
    }
}

// ---------------- combine: out = normalize(X@WR + MZ + BL), prepped fp16 WR ----------------
template <int K, bool HOUT>
__global__ void __launch_bounds__(256)
combine_h(const uint32_t* __restrict__ X, const __half* __restrict__ WRt,
          const float* __restrict__ MZ, const float* __restrict__ BL,
          void* __restrict__ Cout) {
    constexpr int NCH = K / 32;
    extern __shared__ uint32_t smem[];
    const int tid = threadIdx.x, lane = tid & 31, wid = tid >> 5;
    const int warpM = wid & 3, warpN = wid >> 2;
    const int rowBase = blockIdx.x * 128;

    float acc[2][4][4];
#pragma unroll
    for (int mt = 0; mt < 2; mt++)
#pragma unroll
        for (int nt = 0; nt < 4; nt++)
#pragma unroll
            for (int q = 0; q < 4; q++) acc[mt][nt][q] = 0.f;

    uint4 ra[2], rb;
    auto loadC = [&](int c) {
#pragma unroll
        for (int i = 0; i < 2; i++) {
            int g = tid + 256 * i;
            int row = g & 127, qq = g >> 7;
            int grow = rowBase + row;
            ra[i] = (grow < NN)
                ? *reinterpret_cast<const uint4*>(X + (size_t)grow * (K / 2) + c * 16 + 4 * qq)
                : make_uint4(0, 0, 0, 0);
        }
        {
            int n = tid & 63, qq = tid >> 6;
            rb = *reinterpret_cast<const uint4*>(WRt + (size_t)n * K + c * 32 + 8 * qq);
        }
    };
    auto stage = [&](int b) {
        uint32_t* sa = smem + (b ? 4096 : 0);
        uint32_t* sb = smem + 8192 + (b ? 2048 : 0);
#pragma unroll
        for (int i = 0; i < 2; i++) {
            int g = tid + 256 * i;
            stTile4(sa, g & 127, g >> 7, ra[i]);
        }
        stTile4(sb, tid & 63, tid >> 6, rb);
    };

    loadC(0); stage(0); __syncthreads();
#pragma unroll 1
    for (int c = 0; c < NCH; c++) {
        if (c + 1 < NCH) loadC(c + 1);
        const uint32_t* sa = smem + ((c & 1) ? 4096 : 0);
        const uint32_t* sb = smem + 8192 + ((c & 1) ? 2048 : 0);
        chunk_mma_h<4>(sa, sb, acc, warpM * 32, warpN * 32, lane);
        if (c + 1 < NCH) { stage((c + 1) & 1); __syncthreads(); }
    }

    __syncthreads();
    float (*sOut)[66] = reinterpret_cast<float(*)[66]>(smem);
    const int qr = lane >> 2, qc = lane & 3;
#pragma unroll
    for (int mt = 0; mt < 2; mt++) {
        int rl = warpM * 32 + mt * 16 + qr;
        int g0 = rowBase + rl, g1 = rowBase + rl + 8;
#pragma unroll
        for (int nt = 0; nt < 4; nt++) {
            int cl = warpN * 32 + nt * 8 + 2 * qc;
            float b0 = __ldg(&BL[cl]), b1 = __ldg(&BL[cl + 1]);
            float2 m0 = (g0 < NN) ? *(const float2*)(MZ + (size_t)g0 * 64 + cl) : make_float2(0, 0);
            float2 m1 = (g1 < NN) ? *(const float2*)(MZ + (size_t)g1 * 64 + cl) : make_float2(0, 0);
            sOut[rl][cl]         = acc[mt][nt][0] + b0 + m0.x;
            sOut[rl][cl + 1]     = acc[mt][nt][1] + b1 + m0.y;
            sOut[rl + 8][cl]     = acc[mt][nt][2] + b0 + m1.x;
            sOut[rl + 8][cl + 1] = acc[mt][nt][3] + b1 + m1.y;
        }
    }
    __syncthreads();
#pragma unroll
    for (int rr = 0; rr < 16; rr++) {
        int r = wid * 16 + rr;
        int grow = rowBase + r;
        float2 v = *(const float2*)&sOut[r][2 * lane];
        float ss = v.x * v.x + v.y * v.y;
#pragma unroll
        for (int o = 16; o > 0; o >>= 1) ss += __shfl_xor_sync(0xffffffffu, ss, o);
        float sc = 1.0f / fmaxf(sqrtf(ss), 1e-12f);
        if (grow < NN) {
            if (HOUT) {
                ((uint32_t*)Cout)[(size_t)grow * 32 + lane] = f2h2(v.x * sc, v.y * sc);
            } else {
                *(float2*)((float*)Cout + (size_t)grow * 64 + 2 * lane) =
                    make_float2(v.x * sc, v.y * sc);
            }
        }
    }
}

// ---------------- mean aggregation over CSR ----------------
__global__ void agg_half(const __half2* __restrict__ zp, float* __restrict__ msg) {
    int w = (blockIdx.x * blockDim.x + threadIdx.x) >> 5;
    int lane = threadIdx.x & 31;
    if (w >= NN) return;
    int beg = g_rowptr[w], end = g_rowptr[w + 1];
    float2 acc = make_float2(0, 0);
    int e = beg;
    for (; e + 4 <= end; e += 4) {
        int s0 = __ldg(&g_adj[e]);
        int s1 = __ldg(&g_adj[e + 1]);
        int s2 = __ldg(&g_adj[e + 2]);
        int s3 = __ldg(&g_adj[e + 3]);
        float2 v0 = __half22float2(zp[(size_t)s0 * 32 + lane]);
        float2 v1 = __half22float2(zp[(size_t)s1 * 32 + lane]);
        float2 v2 = __half22float2(zp[(size_t)s2 * 32 + lane]);
        float2 v3 = __half22float2(zp[(size_t)s3 * 32 + lane]);
        acc.x += (v0.x + v1.x) + (v2.x + v3.x);
        acc.y += (v0.y + v1.y) + (v2.y + v3.y);
    }
    for (; e < end; e++) {
        int s = __ldg(&g_adj[e]);
        float2 v = __half22float2(zp[(size_t)s * 32 + lane]);
        acc.x += v.x; acc.y += v.y;
    }
    float inv = 1.0f / fmaxf((float)(end - beg), 1.0f);
    *reinterpret_cast<float2*>(msg + (size_t)w * 64 + lane * 2) =
        make_float2(acc.x * inv, acc.y * inv);
}

// ---------------- pooling ----------------
__global__ void pool_kernel(const float* __restrict__ x, const int* __restrict__ batch) {
    int nwarps = (gridDim.x * blockDim.x) >> 5;
    int w = (blockIdx.x * blockDim.x + threadIdx.x) >> 5;
    int lane = threadIdx.x & 31;
    int per = (NN + nwarps - 1) / nwarps;
    int s = w * per;
    int e = min(NN, s + per);
    if (s >= e) return;
    float m0 = -__int_as_float(0x7f800000), m1 = m0;
    float s0 = 0.f, s1 = 0.f;
    int cnt = 0;
    int curg = __ldg(&batch[s]);
    for (int i = s; i < e; i++) {
        int g = __ldg(&batch[i]);
        if (g != curg) {
            atomicMax(&g_gmax[curg * 64 + lane], fenc(m0));
            atomicMax(&g_gmax[curg * 64 + lane + 32], fenc(m1));
            atomicAdd(&g_gsum[curg * 64 + lane], s0);
            atomicAdd(&g_gsum[curg * 64 + lane + 32], s1);
            if (lane == 0) atomicAdd(&g_gcnt[curg], cnt);
            m0 = m1 = -__int_as_float(0x7f800000);
            s0 = s1 = 0.f; cnt = 0; curg = g;
        }
        float v0 = x[(size_t)i * 64 + lane];
        float v1 = x[(size_t)i * 64 + lane + 32];
        m0 = fmaxf(m0, v0); m1 = fmaxf(m1, v1);
        s0 += v0; s1 += v1; cnt++;
    }
    atomicMax(&g_gmax[curg * 64 + lane], fenc(m0));
    atomicMax(&g_gmax[curg * 64 + lane + 32], fenc(m1));
    atomicAdd(&g_gsum[curg * 64 + lane], s0);
    atomicAdd(&g_gsum[curg * 64 + lane + 32], s1);
    if (lane == 0) atomicAdd(&g_gcnt[curg], cnt);
}

// ---------------- final ----------------
__global__ void final_kernel(const float* __restrict__ post_w, const float* __restrict__ post_b,
                             float* __restrict__ out) {
    int g = threadIdx.x;
    if (g >= NG) return;
    float inv = 1.0f / (float)g_gcnt[g];
    float v[64];
    float ss = 0.f;
#pragma unroll
    for (int c = 0; c < 64; c++) {
        float t = fdec(g_gmax[g * 64 + c]) + g_gsum[g * 64 + c] * inv;
        v[c] = t;
        ss += t * t;
    }
    float norm = sqrtf(ss);
    float dot = 0.f;
#pragma unroll
    for (int c = 0; c < 64; c++) dot += v[c] * post_w[c];
    out[g] = dot / norm + post_b[0];
}

// ---------------- launch ----------------
static cudaStream_t g_s2 = nullptr;
static cudaEvent_t g_ev1 = nullptr, g_ev2 = nullptr, g_evW = nullptr;

extern "C" void kernel_launch(void* const* d_in, const int* in_sizes, int n_in,
                              void* d_out, int out_size) {
    const float* node_feat = (const float*)d_in[0];
    const float* cfg_feat  = (const float*)d_in[1];
    const int*   opcode    = (const int*)d_in[2];
    const int*   edge      = (const int*)d_in[3];
    const int*   batch     = (const int*)d_in[4];
    const float* op_emb    = (const float*)d_in[5];
    const float* lin_w     = (const float*)d_in[6];
    const float* lin_b     = (const float*)d_in[7];
    const float* post_w    = (const float*)d_in[8];
    const float* post_b    = (const float*)d_in[9];
    const float* pw0 = (const float*)d_in[10];
    const float* pb0 = (const float*)d_in[11];
    const float* wl0 = (const float*)d_in[12];
    const float* bl0 = (const float*)d_in[13];
    const float* wr0 = (const float*)d_in[14];
    const float* pw1 = (const float*)d_in[15];
    const float* pb1 = (const float*)d_in[16];
    const float* wl1 = (const float*)d_in[17];
    const float* bl1 = (const float*)d_in[18];
    const float* wr1 = (const float*)d_in[19];
    const float* pw2 = (const float*)d_in[20];
    const float* pb2 = (const float*)d_in[21];
    const float* wl2 = (const float*)d_in[22];
    const float* bl2 = (const float*)d_in[23];
    const float* wr2 = (const float*)d_in[24];
    float* out = (float*)d_out;

    if (g_s2 == nullptr) {
        cudaStreamCreateWithFlags(&g_s2, cudaStreamNonBlocking);
        cudaEventCreateWithFlags(&g_ev1, cudaEventDisableTiming);
        cudaEventCreateWithFlags(&g_ev2, cudaEventDisableTiming);
        cudaEventCreateWithFlags(&g_evW, cudaEventDisableTiming);
        cudaFuncSetAttribute(projz_h<128>, cudaFuncAttributeMaxDynamicSharedMemorySize, 98304);
        cudaFuncSetAttribute(projz_h<64>,  cudaFuncAttributeMaxDynamicSharedMemorySize, 65536);
    }

    const int* src = edge;
    const int* dst = edge + NE;

    const int MB = (NN + 127) / 128;
    const int EB = (NE + 255) / 256;
    const int AGGB = (NN * 32 + 255) / 256;
    const size_t SMEM48 = 49152;
    const size_t SMEM_PZ128 = 98304;
    const size_t SMEM_PZ64  = 65536;

    uint32_t* dA; cudaGetSymbolAddress((void**)&dA, g_xA);
    uint32_t* dB; cudaGetSymbolAddress((void**)&dB, g_xB);
    float* dC; cudaGetSymbolAddress((void**)&dC, g_xC);
    __half2* dZ; cudaGetSymbolAddress((void**)&dZ, g_z);
    float* dM; cudaGetSymbolAddress((void**)&dM, g_msg);
    __half* dW; cudaGetSymbolAddress((void**)&dW, g_wt);

    const __half* pwt0 = dW;
    const __half* wlt0 = dW + 16384;
    const __half* wrt0 = dW + 24576;
    const __half* pwt1 = dW + 32768;
    const __half* wlt1 = dW + 36864;
    const __half* wrt1 = dW + 40960;
    const __half* pwt2 = dW + 45056;
    const __half* wlt2 = dW + 49152;
    const __half* wrt2 = dW + 53248;

    // fork: weight prep + CSR build on side stream
    cudaEventRecord(g_ev1, 0);
    cudaStreamWaitEvent(g_s2, g_ev1, 0);
    prep_w<<<224, 256, 0, g_s2>>>(pw0, wl0, wr0, pw1, wl1, wr1, pw2, wl2, wr2, dW);
    cudaEventRecord(g_evW, g_s2);
    init_kernel<<<(NN + 255) / 256, 256, 0, g_s2>>>();
    hist_kernel<<<EB, 256, 0, g_s2>>>(dst);
    scan1_kernel<<<NBLK, 256, 0, g_s2>>>();
    scan2_kernel<<<1, 128, 0, g_s2>>>();
    scan3_kernel<<<NBLK, 256, 0, g_s2>>>();
    fill_adj_kernel<<<EB, 256, 0, g_s2>>>(src, dst);
    cudaEventRecord(g_ev2, g_s2);

    lin_h<<<dim3(MB, 2), 256, SMEM48>>>(node_feat, cfg_feat, opcode, op_emb, lin_w, lin_b, dA);
    cudaStreamWaitEvent(0, g_evW, 0);   // weights ready
    projz_h<128><<<MB, 256, SMEM_PZ128>>>(dA, pwt0, pb0, wlt0, dZ);

    cudaStreamWaitEvent(0, g_ev2, 0);   // CSR ready

    // layer 0 (d=128 -> 64)
    agg_half<<<AGGB, 256>>>(dZ, dM);
    combine_h<128, true><<<MB, 256, SMEM48>>>(dA, wrt0, dM, bl0, dB);

    // layer 1 (d=64 -> 64)
    projz_h<64><<<MB, 256, SMEM_PZ64>>>(dB, pwt1, pb1, wlt1, dZ);
    agg_half<<<AGGB, 256>>>(dZ, dM);
    combine_h<64, true><<<MB, 256, SMEM48>>>(dB, wrt1, dM, bl1, dA);

    // layer 2 (d=64 -> 64), fp32 output for pooling
    projz_h<64><<<MB, 256, SMEM_PZ64>>>(dA, pwt2, pb2, wlt2, dZ);
    agg_half<<<AGGB, 256>>>(dZ, dM);
    combine_h<64, false><<<MB, 256, SMEM48>>>(dA, wrt2, dM, bl2, dC);

    pool_kernel<<<128, 256>>>(dC, batch);
    final_kernel<<<1, 64>>>(post_w, post_b, out);
}

// round 14
// speedup vs baseline: 1.2383x; 1.0743x over previous
#include <cuda_runtime.h>
#include <cuda_fp16.h>
#include <cstdint>

#define NN 100000
#define NE 1600000
#define NG 64
#define NBLK 98   // ceil(NN/1024)

// ---------------- scratch ----------------
__device__ __align__(256) uint32_t g_xA[(size_t)NN * 64];
__device__ __align__(256) uint32_t g_xB[(size_t)NN * 64];
__device__ __align__(256) float g_xC[(size_t)NN * 64];   // fp32 final-layer output
__device__ __align__(256) __half2 g_z[(size_t)NN * 32];
__device__ __align__(256) float g_msg[(size_t)NN * 64];
__device__ int g_deg[NN];
__device__ int g_cursor[NN];
__device__ int g_rowptr[NN + 1];
__device__ int g_adj[NE];
__device__ int g_bsum[NBLK];
__device__ int g_boff[NBLK];
__device__ unsigned g_gmax[NG * 64];
__device__ float g_gsum[NG * 64];
__device__ int g_gcnt[NG];

// ---------------- helpers ----------------
__device__ __forceinline__ uint32_t smem_u32(const void* p) {
    uint32_t a;
    asm("{ .reg .u64 t; cvta.to.shared.u64 t, %1; cvt.u32.u64 %0, t; }" : "=r"(a) : "l"(p));
    return a;
}
__device__ __forceinline__ uint32_t f2h2(float lo, float hi) {
    __half2 h = __floats2half2_rn(lo, hi);
    return *reinterpret_cast<uint32_t*>(&h);
}
__device__ __forceinline__ void mma16(float* c, const uint32_t* a, const uint32_t* b) {
    asm volatile(
        "mma.sync.aligned.m16n8k16.row.col.f32.f16.f16.f32 "
        "{%0,%1,%2,%3}, {%4,%5,%6,%7}, {%8,%9}, {%0,%1,%2,%3};"
        : "+f"(c[0]), "+f"(c[1]), "+f"(c[2]), "+f"(c[3])
        : "r"(a[0]), "r"(a[1]), "r"(a[2]), "r"(a[3]), "r"(b[0]), "r"(b[1]));
}
__device__ __forceinline__ unsigned fenc(float f) {
    unsigned u = __float_as_uint(f);
    return (u & 0x80000000u) ? ~u : (u | 0x80000000u);
}
__device__ __forceinline__ float fdec(unsigned e) {
    return __uint_as_float((e & 0x80000000u) ? (e ^ 0x80000000u) : ~e);
}

// ---------------- fp16 XOR-swizzled tiles (row stride 32 words, 16B slot qq^(row&7)) ----------------
__device__ __forceinline__ void stTile4(uint32_t* s, int row, int qq, uint4 w) {
    *reinterpret_cast<uint4*>(s + row * 32 + 4 * (qq ^ (row & 7))) = w;
}
__device__ __forceinline__ void stXh(uint32_t* sX, int row, int c2, uint32_t w) {
    uint32_t* t = sX + (c2 >> 4) * 4096;
    int lc = c2 & 15;
    t[row * 32 + 4 * ((lc >> 2) ^ (row & 7)) + (lc & 3)] = w;
}

// ldmatrix-based fragment consumer: per 32-K chunk, 4 A-ldmatrix.x4 + NT/2 B-ldmatrix.x4 per s
template <int NT>
__device__ __forceinline__ void chunk_mma_ldm(uint32_t aB, uint32_t bB,
                                              float (&acc)[2][NT][4], int rowB, int colB, int lane) {
#pragma unroll
    for (int s = 0; s < 2; s++) {
        uint32_t a[2][4];
#pragma unroll
        for (int mt = 0; mt < 2; mt++) {
            int row = rowB + mt * 16 + (lane & 15);
            int qq = 2 * s + (lane >> 4);
            uint32_t addr = aB + row * 128 + 16 * (qq ^ (row & 7));
            asm volatile("ldmatrix.sync.aligned.m8n8.x4.shared.b16 {%0,%1,%2,%3}, [%4];"
                         : "=r"(a[mt][0]), "=r"(a[mt][1]), "=r"(a[mt][2]), "=r"(a[mt][3])
                         : "r"(addr));
        }
#pragma unroll
        for (int ntp = 0; ntp < NT / 2; ntp++) {
            int m = lane >> 3;
            int nt = 2 * ntp + (m >> 1);
            int qq = 2 * s + (m & 1);
            int n = colB + nt * 8 + (lane & 7);
            uint32_t addr = bB + n * 128 + 16 * (qq ^ (n & 7));
            uint32_t b[4];
            asm volatile("ldmatrix.sync.aligned.m8n8.x4.shared.b16 {%0,%1,%2,%3}, [%4];"
                         : "=r"(b[0]), "=r"(b[1]), "=r"(b[2]), "=r"(b[3])
                         : "r"(addr));
#pragma unroll
            for (int mt = 0; mt < 2; mt++) {
                mma16(acc[mt][2 * ntp], a[mt], b);
                mma16(acc[mt][2 * ntp + 1], a[mt], b + 2);
            }
        }
    }
}

// ---------------- init ----------------
__global__ void init_kernel() {
    int j = blockIdx.x * blockDim.x + threadIdx.x;
    if (j < NN) { g_deg[j] = 0; g_cursor[j] = 0; }
    if (j < NG * 64) { g_gmax[j] = 0x007FFFFFu; g_gsum[j] = 0.f; }
    if (j < NG) g_gcnt[j] = 0;
}

// ---------------- CSR build ----------------
__global__ void hist_kernel(const int* __restrict__ dst) {
    int e = blockIdx.x * blockDim.x + threadIdx.x;
    if (e < NE) atomicAdd(&g_deg[dst[e]], 1);
}

__global__ void scan1_kernel() {
    __shared__ int wsum[8];
    int b = blockIdx.x, tid = threadIdx.x, lane = tid & 31, w = tid >> 5;
    int i0 = b * 1024 + tid * 4;
    int s = 0;
#pragma unroll
    for (int j = 0; j < 4; j++) { int i = i0 + j; if (i < NN) s += g_deg[i]; }
#pragma unroll
    for (int o = 16; o > 0; o >>= 1) s += __shfl_xor_sync(0xffffffffu, s, o);
    if (lane == 0) wsum[w] = s;
    __syncthreads();
    if (tid == 0) {
        int t = 0;
#pragma unroll
        for (int k = 0; k < 8; k++) t += wsum[k];
        g_bsum[b] = t;
    }
}

__global__ void scan2_kernel() {
    __shared__ int ws[4];
    int tid = threadIdx.x, lane = tid & 31, w = tid >> 5;
    int v = (tid < NBLK) ? g_bsum[tid] : 0;
    int si = v;
#pragma unroll
    for (int o = 1; o < 32; o <<= 1) { int t = __shfl_up_sync(0xffffffffu, si, o); if (lane >= o) si += t; }
    if (lane == 31) ws[w] = si;
    __syncthreads();
    if (tid == 0) {
        int run = 0;
#pragma unroll
        for (int k = 0; k < 4; k++) { int t = ws[k]; ws[k] = run; run += t; }
        g_rowptr[NN] = run;
    }
    __syncthreads();
    if (tid < NBLK) g_boff[tid] = ws[w] + si - v;
}

__global__ void scan3_kernel() {
    __shared__ int wsum[8];
    int b = blockIdx.x, tid = threadIdx.x, lane = tid & 31, w = tid >> 5;
    int i0 = b * 1024 + tid * 4;
    int v[4], s = 0;
#pragma unroll
    for (int j = 0; j < 4; j++) { int i = i0 + j; v[j] = (i < NN) ? g_deg[i] : 0; s += v[j]; }
    int si = s;
#pragma unroll
    for (int o = 1; o < 32; o <<= 1) { int t = __shfl_up_sync(0xffffffffu, si, o); if (lane >= o) si += t; }
    if (lane == 31) wsum[w] = si;
    __syncthreads();
    if (tid == 0) {
        int run = 0;
#pragma unroll
        for (int k = 0; k < 8; k++) { int t = wsum[k]; wsum[k] = run; run += t; }
    }
    __syncthreads();
    int off = g_boff[b] + wsum[w] + (si - s);
#pragma unroll
    for (int j = 0; j < 4; j++) { int i = i0 + j; if (i < NN) g_rowptr[i] = off; off += v[j]; }
}

__global__ void fill_adj_kernel(const int* __restrict__ src, const int* __restrict__ dst) {
    int e = blockIdx.x * blockDim.x + threadIdx.x;
    if (e < NE) {
        int d = dst[e];
        int p = atomicAdd(&g_cursor[d], 1);
        g_adj[g_rowptr[d] + p] = src[e];
    }
}

// ---------------- lin ----------------
__device__ __forceinline__ float4 lin_ld4(const float* nf, const float* cf,
                                          const int* opc, const float* emb, int grow, int k) {
    float4 v = make_float4(0, 0, 0, 0);
    if (k < 140)      v = *(const float4*)(nf + (size_t)grow * 140 + k);
    else if (k < 172) v = *(const float4*)(emb + (size_t)opc[grow] * 32 + (k - 140));
    else if (k < 190) {
        const float* cp = cf + (size_t)grow * 18;
        int off = k - 172;
        v.x = cp[off];
        v.y = (off + 1 < 18) ? cp[off + 1] : 0.f;
        v.z = (off + 2 < 18) ? cp[off + 2] : 0.f;
        v.w = (off + 3 < 18) ? cp[off + 3] : 0.f;
    }
    return v;
}

__global__ void __launch_bounds__(256)
lin_h(const float* __restrict__ nf, const float* __restrict__ cf,
      const int* __restrict__ opc, const float* __restrict__ emb,
      const float* __restrict__ W, const float* __restrict__ bias,
      uint32_t* __restrict__ C) {
    extern __shared__ uint32_t smem[];
    const uint32_t smb = smem_u32(smem);
    const int tid = threadIdx.x, lane = tid & 31, wid = tid >> 5;
    const int warpM = wid & 3, warpN = wid >> 2;
    const int rowBase = blockIdx.x * 128;
    const int n0 = blockIdx.y * 64;

    float acc[2][4][4];
#pragma unroll
    for (int mt = 0; mt < 2; mt++)
#pragma unroll
        for (int nt = 0; nt < 4; nt++)
#pragma unroll
            for (int q = 0; q < 4; q++) acc[mt][nt][q] = 0.f;

    uint4 ra[2], rb;
    auto loadC = [&](int c) {
#pragma unroll
        for (int i = 0; i < 2; i++) {
            int g = tid + 256 * i;
            int row = g & 127, qq = g >> 7;
            int grow = rowBase + row;
            uint4 w = make_uint4(0, 0, 0, 0);
            if (grow < NN) {
                float4 v0 = lin_ld4(nf, cf, opc, emb, grow, c * 32 + 8 * qq);
                float4 v1 = lin_ld4(nf, cf, opc, emb, grow, c * 32 + 8 * qq + 4);
                w = make_uint4(f2h2(v0.x, v0.y), f2h2(v0.z, v0.w), f2h2(v1.x, v1.y), f2h2(v1.z, v1.w));
            }
            ra[i] = w;
        }
        {
            int n = tid & 63, qq = tid >> 6;
            float f[8];
#pragma unroll
            for (int j = 0; j < 8; j++) {
                int kg = c * 32 + 8 * qq + j;
                f[j] = (kg < 190) ? W[(size_t)kg * 128 + n0 + n] : 0.f;
            }
            rb = make_uint4(f2h2(f[0], f[1]), f2h2(f[2], f[3]), f2h2(f[4], f[5]), f2h2(f[6], f[7]));
        }
    };
    auto stage = [&](int b) {
        uint32_t* sa = smem + (b ? 4096 : 0);
        uint32_t* sb = smem + 8192 + (b ? 2048 : 0);
#pragma unroll
        for (int i = 0; i < 2; i++) {
            int g = tid + 256 * i;
            stTile4(sa, g & 127, g >> 7, ra[i]);
        }
        stTile4(sb, tid & 63, tid >> 6, rb);
    };

    loadC(0); stage(0); __syncthreads();
#pragma unroll 1
    for (int c = 0; c < 6; c++) {
        if (c < 5) loadC(c + 1);
        uint32_t aB = smb + ((c & 1) ? 4096u : 0u) * 4u;
        uint32_t bB = smb + (8192u + ((c & 1) ? 2048u : 0u)) * 4u;
        chunk_mma_ldm<4>(aB, bB, acc, warpM * 32, warpN * 32, lane);
        if (c < 5) { stage((c + 1) & 1); __syncthreads(); }
    }

    const int qr = lane >> 2, qc = lane & 3;
#pragma unroll
    for (int mt = 0; mt < 2; mt++) {
        int r0 = rowBase + warpM * 32 + mt * 16 + qr;
#pragma unroll
        for (int nt = 0; nt < 4; nt++) {
            int gc = n0 + warpN * 32 + nt * 8 + 2 * qc;
            float b0 = __ldg(&bias[gc]), b1 = __ldg(&bias[gc + 1]);
            if (r0 < NN)
                C[(size_t)r0 * 64 + gc / 2] =
                    f2h2(fmaxf(acc[mt][nt][0] + b0, 0.f), fmaxf(acc[mt][nt][1] + b1, 0.f));
            if (r0 + 8 < NN)
                C[(size_t)(r0 + 8) * 64 + gc / 2] =
                    f2h2(fmaxf(acc[mt][nt][2] + b0, 0.f), fmaxf(acc[mt][nt][3] + b1, 0.f));
        }
    }
}

// ---------------- projz: Z(half2) = relu(A@PW + PB) @ WL ----------------
template <int K>
__global__ void __launch_bounds__(256)
projz_h(const uint32_t* __restrict__ A, const float* __restrict__ PW,
        const float* __restrict__ PB, const float* __restrict__ WL,
        __half2* __restrict__ Z) {
    constexpr int NCH = K / 32;
    constexpr int CW = K / 2;
    constexpr int NT1 = CW / 8;
    constexpr int INB = K * 32;
    constexpr int INW = 8192 + 2 * INB;
    constexpr int XW = NCH * 4096;
    constexpr int UW = (INW > XW) ? INW : XW;
    constexpr int NST = K / 64;
    extern __shared__ uint32_t smem[];
    uint32_t* W2 = smem + UW;
    const uint32_t smb = smem_u32(smem);

    const int tid = threadIdx.x, lane = tid & 31, wid = tid >> 5;
    const int warpM = wid & 3, warpN = wid >> 2;
    const int rowBase = blockIdx.x * 128;
    const int qr = lane >> 2, qc = lane & 3;

    // stage WL chunks once (fp32 coalesced loads)
#pragma unroll
    for (int c = 0; c < NCH; c++) {
        int n = tid & 63, qq = tid >> 6;
        float f[8];
#pragma unroll
        for (int j = 0; j < 8; j++) f[j] = WL[(size_t)(c * 32 + 8 * qq + j) * 64 + n];
        stTile4(W2 + c * 2048, n, qq,
                make_uint4(f2h2(f[0], f[1]), f2h2(f[2], f[3]), f2h2(f[4], f[5]), f2h2(f[6], f[7])));
    }

    float acc1[2][NT1][4];
#pragma unroll
    for (int mt = 0; mt < 2; mt++)
#pragma unroll
        for (int nt = 0; nt < NT1; nt++)
#pragma unroll
            for (int q = 0; q < 4; q++) acc1[mt][nt][q] = 0.f;

    uint4 ra[2], rb[NST];
    auto loadC = [&](int c) {
#pragma unroll
        for (int i = 0; i < 2; i++) {
            int g = tid + 256 * i;
            int row = g & 127, qq = g >> 7;
            int grow = rowBase + row;
            ra[i] = (grow < NN)
                ? *reinterpret_cast<const uint4*>(A + (size_t)grow * (K / 2) + c * 16 + 4 * qq)
                : make_uint4(0, 0, 0, 0);
        }
#pragma unroll
        for (int i = 0; i < NST; i++) {
            int g = tid + 256 * i;
            int n = g % K, qq = g / K;
            float f[8];
#pragma unroll
            for (int j = 0; j < 8; j++) f[j] = PW[(size_t)(c * 32 + 8 * qq + j) * K + n];
            rb[i] = make_uint4(f2h2(f[0], f[1]), f2h2(f[2], f[3]), f2h2(f[4], f[5]), f2h2(f[6], f[7]));
        }
    };
    auto stage = [&](int b) {
        uint32_t* sa = smem + (b ? 4096 : 0);
        uint32_t* sb = smem + 8192 + (b ? INB : 0);
#pragma unroll
        for (int i = 0; i < 2; i++) {
            int g = tid + 256 * i;
            stTile4(sa, g & 127, g >> 7, ra[i]);
        }
#pragma unroll
        for (int i = 0; i < NST; i++) {
            int g = tid + 256 * i;
            stTile4(sb, g % K, g / K, rb[i]);
        }
    };

    loadC(0); stage(0); __syncthreads();
#pragma unroll 1
    for (int c = 0; c < NCH; c++) {
        if (c + 1 < NCH) loadC(c + 1);
        uint32_t aB = smb + ((c & 1) ? 4096u : 0u) * 4u;
        uint32_t bB = smb + (8192u + ((c & 1) ? (uint32_t)INB : 0u)) * 4u;
        chunk_mma_ldm<NT1>(aB, bB, acc1, warpM * 32, warpN * CW, lane);
        if (c + 1 < NCH) { stage((c + 1) & 1); __syncthreads(); }
    }
    __syncthreads();

    // restage xp = relu(acc1 + PB) into X tiles (half2)
#pragma unroll
    for (int mt = 0; mt < 2; mt++) {
        int r0 = warpM * 32 + mt * 16 + qr;
#pragma unroll
        for (int nt = 0; nt < NT1; nt++) {
            int col = warpN * CW + nt * 8 + 2 * qc;
            float b0 = __ldg(&PB[col]), b1 = __ldg(&PB[col + 1]);
            stXh(smem, r0, col / 2,
                 f2h2(fmaxf(acc1[mt][nt][0] + b0, 0.f), fmaxf(acc1[mt][nt][1] + b1, 0.f)));
            stXh(smem, r0 + 8, col / 2,
                 f2h2(fmaxf(acc1[mt][nt][2] + b0, 0.f), fmaxf(acc1[mt][nt][3] + b1, 0.f)));
        }
    }
    __syncthreads();

    float acc2[2][4][4];
#pragma unroll
    for (int mt = 0; mt < 2; mt++)
#pragma unroll
        for (int nt = 0; nt < 4; nt++)
#pragma unroll
            for (int q = 0; q < 4; q++) acc2[mt][nt][q] = 0.f;
#pragma unroll
    for (int c = 0; c < NCH; c++)
        chunk_mma_ldm<4>(smb + (uint32_t)(c * 4096) * 4u,
                         smb + (uint32_t)(UW + c * 2048) * 4u,
                         acc2, warpM * 32, warpN * 32, lane);

#pragma unroll
    for (int mt = 0; mt < 2; mt++) {
        int r0 = rowBase + warpM * 32 + mt * 16 + qr;
#pragma unroll
        for (int nt = 0; nt < 4; nt++) {
            int gc = warpN * 32 + nt * 8 + 2 * qc;
            if (r0 < NN)
                Z[(size_t)r0 * 32 + gc / 2] = __floats2half2_rn(acc2[mt][nt][0], acc2[mt][nt][1]);
            if (r0 + 8 < NN)
                Z[(size_t)(r0 + 8) * 32 + gc / 2] = __floats2half2_rn(acc2[mt][nt][2], acc2[mt][nt][3]);
        }
    }
}

// ---------------- combine: out = normalize(X@WR + MZ + BL) ----------------
template <int K, bool HOUT>
__global__ void __launch_bounds__(256)
combine_h(const uint32_t* __restrict__ X, const float* __restrict__ WR,
          const float* __restrict__ MZ, const float* __restrict__ BL,
          void* __restrict__ Cout) {
    constexpr int NCH = K / 32;
    extern __shared__ uint32_t smem[];
    const uint32_t smb = smem_u32(smem);
    const int tid = threadIdx.x, lane = tid & 31, wid = tid >> 5;
    const int warpM = wid & 3, warpN = wid >> 2;
    const int rowBase = blockIdx.x * 128;

    float acc[2][4][4];
#pragma unroll
    for (int mt = 0; mt < 2; mt++)
#pragma unroll
        for (int nt = 0; nt < 4; nt++)
#pragma unroll
            for (int q = 0; q < 4; q++) acc[mt][nt][q] = 0.f;

    uint4 ra[2], rb;
    auto loadC = [&](int c) {
#pragma unroll
        for (int i = 0; i < 2; i++) {
            int g = tid + 256 * i;
            int row = g & 127, qq = g >> 7;
            int grow = rowBase + row;
            ra[i] = (grow < NN)
                ? *reinterpret_cast<const uint4*>(X + (size_t)grow * (K / 2) + c * 16 + 4 * qq)
                : make_uint4(0, 0, 0, 0);
        }
        {
            int n = tid & 63, qq = tid >> 6;
            float f[8];
#pragma unroll
            for (int j = 0; j < 8; j++) f[j] = WR[(size_t)(c * 32 + 8 * qq + j) * 64 + n];
            rb = make_uint4(f2h2(f[0], f[1]), f2h2(f[2], f[3]), f2h2(f[4], f[5]), f2h2(f[6], f[7]));
        }
    };
    auto stage = [&](int b) {
        uint32_t* sa = smem + (b ? 4096 : 0);
        uint32_t* sb = smem + 8192 + (b ? 2048 : 0);
#pragma unroll
        for (int i = 0; i < 2; i++) {
            int g = tid + 256 * i;
            stTile4(sa, g & 127, g >> 7, ra[i]);
        }
        stTile4(sb, tid & 63, tid >> 6, rb);
    };

    loadC(0); stage(0); __syncthreads();
#pragma unroll 1
    for (int c = 0; c < NCH; c++) {
        if (c + 1 < NCH) loadC(c + 1);
        uint32_t aB = smb + ((c & 1) ? 4096u : 0u) * 4u;
        uint32_t bB = smb + (8192u + ((c & 1) ? 2048u : 0u)) * 4u;
        chunk_mma_ldm<4>(aB, bB, acc, warpM * 32, warpN * 32, lane);
        if (c + 1 < NCH) { stage((c + 1) & 1); __syncthreads(); }
    }

    __syncthreads();
    float (*sOut)[66] = reinterpret_cast<float(*)[66]>(smem);
    const int qr = lane >> 2, qc = lane & 3;
#pragma unroll
    for (int mt = 0; mt < 2; mt++) {
        int rl = warpM * 32 + mt * 16 + qr;
        int g0 = rowBase + rl, g1 = rowBase + rl + 8;
#pragma unroll
        for (int nt = 0; nt < 4; nt++) {
            int cl = warpN * 32 + nt * 8 + 2 * qc;
            float b0 = __ldg(&BL[cl]), b1 = __ldg(&BL[cl + 1]);
            float2 m0 = (g0 < NN) ? *(const float2*)(MZ + (size_t)g0 * 64 + cl) : make_float2(0, 0);
            float2 m1 = (g1 < NN) ? *(const float2*)(MZ + (size_t)g1 * 64 + cl) : make_float2(0, 0);
            sOut[rl][cl]         = acc[mt][nt][0] + b0 + m0.x;
            sOut[rl][cl + 1]     = acc[mt][nt][1] + b1 + m0.y;
            sOut[rl + 8][cl]     = acc[mt][nt][2] + b0 + m1.x;
            sOut[rl + 8][cl + 1] = acc[mt][nt][3] + b1 + m1.y;
        }
    }
    __syncthreads();
#pragma unroll
    for (int rr = 0; rr < 16; rr++) {
        int r = wid * 16 + rr;
        int grow = rowBase + r;
        float2 v = *(const float2*)&sOut[r][2 * lane];
        float ss = v.x * v.x + v.y * v.y;
#pragma unroll
        for (int o = 16; o > 0; o >>= 1) ss += __shfl_xor_sync(0xffffffffu, ss, o);
        float sc = 1.0f / fmaxf(sqrtf(ss), 1e-12f);
        if (grow < NN) {
            if (HOUT) {
                ((uint32_t*)Cout)[(size_t)grow * 32 + lane] = f2h2(v.x * sc, v.y * sc);
            } else {
                *(float2*)((float*)Cout + (size_t)grow * 64 + 2 * lane) =
                    make_float2(v.x * sc, v.y * sc);
            }
        }
    }
}

// ---------------- mean aggregation over CSR ----------------
__global__ void agg_half(const __half2* __restrict__ zp, float* __restrict__ msg) {
    int w = (blockIdx.x * blockDim.x + threadIdx.x) >> 5;
    int lane = threadIdx.x & 31;
    if (w >= NN) return;
    int beg = g_rowptr[w], end = g_rowptr[w + 1];
    float2 acc = make_float2(0, 0);
    int e = beg;
    for (; e + 4 <= end; e += 4) {
        int s0 = __ldg(&g_adj[e]);
        int s1 = __ldg(&g_adj[e + 1]);
        int s2 = __ldg(&g_adj[e + 2]);
        int s3 = __ldg(&g_adj[e + 3]);
        float2 v0 = __half22float2(zp[(size_t)s0 * 32 + lane]);
        float2 v1 = __half22float2(zp[(size_t)s1 * 32 + lane]);
        float2 v2 = __half22float2(zp[(size_t)s2 * 32 + lane]);
        float2 v3 = __half22float2(zp[(size_t)s3 * 32 + lane]);
        acc.x += (v0.x + v1.x) + (v2.x + v3.x);
        acc.y += (v0.y + v1.y) + (v2.y + v3.y);
    }
    for (; e < end; e++) {
        int s = __ldg(&g_adj[e]);
        float2 v = __half22float2(zp[(size_t)s * 32 + lane]);
        acc.x += v.x; acc.y += v.y;
    }
    float inv = 1.0f / fmaxf((float)(end - beg), 1.0f);
    *reinterpret_cast<float2*>(msg + (size_t)w * 64 + lane * 2) =
        make_float2(acc.x * inv, acc.y * inv);
}

// ---------------- pooling ----------------
__global__ void pool_kernel(const float* __restrict__ x, const int* __restrict__ batch) {
    int nwarps = (gridDim.x * blockDim.x) >> 5;
    int w = (blockIdx.x * blockDim.x + threadIdx.x) >> 5;
    int lane = threadIdx.x & 31;
    int per = (NN + nwarps - 1) / nwarps;
    int s = w * per;
    int e = min(NN, s + per);
    if (s >= e) return;
    float m0 = -__int_as_float(0x7f800000), m1 = m0;
    float s0 = 0.f, s1 = 0.f;
    int cnt = 0;
    int curg = __ldg(&batch[s]);
    for (int i = s; i < e; i++) {
        int g = __ldg(&batch[i]);
        if (g != curg) {
            atomicMax(&g_gmax[curg * 64 + lane], fenc(m0));
            atomicMax(&g_gmax[curg * 64 + lane + 32], fenc(m1));
            atomicAdd(&g_gsum[curg * 64 + lane], s0);
            atomicAdd(&g_gsum[curg * 64 + lane + 32], s1);
            if (lane == 0) atomicAdd(&g_gcnt[curg], cnt);
            m0 = m1 = -__int_as_float(0x7f800000);
            s0 = s1 = 0.f; cnt = 0; curg = g;
        }
        float v0 = x[(size_t)i * 64 + lane];
        float v1 = x[(size_t)i * 64 + lane + 32];
        m0 = fmaxf(m0, v0); m1 = fmaxf(m1, v1);
        s0 += v0; s1 += v1; cnt++;
    }
    atomicMax(&g_gmax[curg * 64 + lane], fenc(m0));
    atomicMax(&g_gmax[curg * 64 + lane + 32], fenc(m1));
    atomicAdd(&g_gsum[curg * 64 + lane], s0);
    atomicAdd(&g_gsum[curg * 64 + lane + 32], s1);
    if (lane == 0) atomicAdd(&g_gcnt[curg], cnt);
}

// ---------------- final ----------------
__global__ void final_kernel(const float* __restrict__ post_w, const float* __restrict__ post_b,
                             float* __restrict__ out) {
    int g = threadIdx.x;
    if (g >= NG) return;
    float inv = 1.0f / (float)g_gcnt[g];
    float v[64];
    float ss = 0.f;
#pragma unroll
    for (int c = 0; c < 64; c++) {
        float t = fdec(g_gmax[g * 64 + c]) + g_gsum[g * 64 + c] * inv;
        v[c] = t;
        ss += t * t;
    }
    float norm = sqrtf(ss);
    float dot = 0.f;
#pragma unroll
    for (int c = 0; c < 64; c++) dot += v[c] * post_w[c];
    out[g] = dot / norm + post_b[0];
}

// ---------------- launch ----------------
static cudaStream_t g_s2 = nullptr;
static cudaEvent_t g_ev1 = nullptr, g_ev2 = nullptr;

extern "C" void kernel_launch(void* const* d_in, const int* in_sizes, int n_in,
                              void* d_out, int out_size) {
    const float* node_feat = (const float*)d_in[0];
    const float* cfg_feat  = (const float*)d_in[1];
    const int*   opcode    = (const int*)d_in[2];
    const int*   edge      = (const int*)d_in[3];
    const int*   batch     = (const int*)d_in[4];
    const float* op_emb    = (const float*)d_in[5];
    const float* lin_w     = (const float*)d_in[6];
    const float* lin_b     = (const float*)d_in[7];
    const float* post_w    = (const float*)d_in[8];
    const float* post_b    = (const float*)d_in[9];
    const float* pw0 = (const float*)d_in[10];
    const float* pb0 = (const float*)d_in[11];
    const float* wl0 = (const float*)d_in[12];
    const float* bl0 = (const float*)d_in[13];
    const float* wr0 = (const float*)d_in[14];
    const float* pw1 = (const float*)d_in[15];
    const float* pb1 = (const float*)d_in[16];
    const float* wl1 = (const float*)d_in[17];
    const float* bl1 = (const float*)d_in[18];
    const float* wr1 = (const float*)d_in[19];
    const float* pw2 = (const float*)d_in[20];
    const float* pb2 = (const float*)d_in[21];
    const float* wl2 = (const float*)d_in[22];
    const float* bl2 = (const float*)d_in[23];
    const float* wr2 = (const float*)d_in[24];
    float* out = (float*)d_out;

    if (g_s2 == nullptr) {
        cudaStreamCreateWithFlags(&g_s2, cudaStreamNonBlocking);
        cudaEventCreateWithFlags(&g_ev1, cudaEventDisableTiming);
        cudaEventCreateWithFlags(&g_ev2, cudaEventDisableTiming);
        cudaFuncSetAttribute(projz_h<128>, cudaFuncAttributeMaxDynamicSharedMemorySize, 98304);
        cudaFuncSetAttribute(projz_h<64>,  cudaFuncAttributeMaxDynamicSharedMemorySize, 65536);
    }

    const int* src = edge;
    const int* dst = edge + NE;

    const int MB = (NN + 127) / 128;
    const int EB = (NE + 255) / 256;
    const int AGGB = (NN * 32 + 255) / 256;
    const size_t SMEM48 = 49152;
    const size_t SMEM_PZ128 = 98304;
    const size_t SMEM_PZ64  = 65536;

    uint32_t* dA; cudaGetSymbolAddress((void**)&dA, g_xA);
    uint32_t* dB; cudaGetSymbolAddress((void**)&dB, g_xB);
    float* dC; cudaGetSymbolAddress((void**)&dC, g_xC);
    __half2* dZ; cudaGetSymbolAddress((void**)&dZ, g_z);
    float* dM; cudaGetSymbolAddress((void**)&dM, g_msg);

    // fork: CSR build on side stream
    cudaEventRecord(g_ev1, 0);
    cudaStreamWaitEvent(g_s2, g_ev1, 0);
    init_kernel<<<(NN + 255) / 256, 256, 0, g_s2>>>();
    hist_kernel<<<EB, 256, 0, g_s2>>>(dst);
    scan1_kernel<<<NBLK, 256, 0, g_s2>>>();
    scan2_kernel<<<1, 128, 0, g_s2>>>();
    scan3_kernel<<<NBLK, 256, 0, g_s2>>>();
    fill_adj_kernel<<<EB, 256, 0, g_s2>>>(src, dst);
    cudaEventRecord(g_ev2, g_s2);

    lin_h<<<dim3(MB, 2), 256, SMEM48>>>(node_feat, cfg_feat, opcode, op_emb, lin_w, lin_b, dA);
    projz_h<128><<<MB, 256, SMEM_PZ128>>>(dA, pw0, pb0, wl0, dZ);

    cudaStreamWaitEvent(0, g_ev2, 0);

    // layer 0 (d=128 -> 64)
    agg_half<<<AGGB, 256>>>(dZ, dM);
    combine_h<128, true><<<MB, 256, SMEM48>>>(dA, wr0, dM, bl0, dB);

    // layer 1 (d=64 -> 64)
    projz_h<64><<<MB, 256, SMEM_PZ64>>>(dB, pw1, pb1, wl1, dZ);
    agg_half<<<AGGB, 256>>>(dZ, dM);
    combine_h<64, true><<<MB, 256, SMEM48>>>(dB, wr1, dM, bl1, dA);

    // layer 2 (d=64 -> 64), fp32 output for pooling
    projz_h<64><<<MB, 256, SMEM_PZ64>>>(dA, pw2, pb2, wl2, dZ);
    agg_half<<<AGGB, 256>>>(dZ, dM);
    combine_h<64, false><<<MB, 256, SMEM48>>>(dA, wr2, dM, bl2, dC);

    pool_kernel<<<128, 256>>>(dC, batch);
    final_kernel<<<1, 64>>>(post_w, post_b, out);
}

// round 15
// speedup vs baseline: 1.2947x; 1.0455x over previous
#include <cuda_runtime.h>
#include <cuda_fp16.h>
#include <cstdint>

#define NN 100000
#define NE 1600000
#define NG 64
#define NBLK 98   // ceil(NN/1024)

// ---------------- scratch ----------------
__device__ __align__(256) uint32_t g_xA[(size_t)NN * 64];
__device__ __align__(256) uint32_t g_xB[(size_t)NN * 64];
__device__ __align__(256) float g_xC[(size_t)NN * 64];   // fp32 final-layer output
__device__ __align__(256) __half2 g_z[(size_t)NN * 32];
__device__ __align__(256) __half2 g_msg[(size_t)NN * 32];
__device__ int g_deg[NN];
__device__ int g_cursor[NN];
__device__ int g_rowptr[NN + 1];
__device__ int g_adj[NE];
__device__ int g_bsum[NBLK];
__device__ int g_boff[NBLK];
__device__ unsigned g_gmax[NG * 64];
__device__ float g_gsum[NG * 64];
__device__ int g_gcnt[NG];

// ---------------- helpers ----------------
__device__ __forceinline__ uint32_t smem_u32(const void* p) {
    uint32_t a;
    asm("{ .reg .u64 t; cvta.to.shared.u64 t, %1; cvt.u32.u64 %0, t; }" : "=r"(a) : "l"(p));
    return a;
}
__device__ __forceinline__ uint32_t f2h2(float lo, float hi) {
    __half2 h = __floats2half2_rn(lo, hi);
    return *reinterpret_cast<uint32_t*>(&h);
}
__device__ __forceinline__ void mma16(float* c, const uint32_t* a, const uint32_t* b) {
    asm volatile(
        "mma.sync.aligned.m16n8k16.row.col.f32.f16.f16.f32 "
        "{%0,%1,%2,%3}, {%4,%5,%6,%7}, {%8,%9}, {%0,%1,%2,%3};"
        : "+f"(c[0]), "+f"(c[1]), "+f"(c[2]), "+f"(c[3])
        : "r"(a[0]), "r"(a[1]), "r"(a[2]), "r"(a[3]), "r"(b[0]), "r"(b[1]));
}
__device__ __forceinline__ unsigned fenc(float f) {
    unsigned u = __float_as_uint(f);
    return (u & 0x80000000u) ? ~u : (u | 0x80000000u);
}
__device__ __forceinline__ float fdec(unsigned e) {
    return __uint_as_float((e & 0x80000000u) ? (e ^ 0x80000000u) : ~e);
}

// ---------------- fp16 XOR-swizzled tiles ----------------
__device__ __forceinline__ void stTile4(uint32_t* s, int row, int qq, uint4 w) {
    *reinterpret_cast<uint4*>(s + row * 32 + 4 * (qq ^ (row & 7))) = w;
}
__device__ __forceinline__ void stXh(uint32_t* sX, int row, int c2, uint32_t w) {
    uint32_t* t = sX + (c2 >> 4) * 4096;
    int lc = c2 & 15;
    t[row * 32 + 4 * ((lc >> 2) ^ (row & 7)) + (lc & 3)] = w;
}

// ldmatrix-based fragment consumer
template <int NT>
__device__ __forceinline__ void chunk_mma_ldm(uint32_t aB, uint32_t bB,
                                              float (&acc)[2][NT][4], int rowB, int colB, int lane) {
#pragma unroll
    for (int s = 0; s < 2; s++) {
        uint32_t a[2][4];
#pragma unroll
        for (int mt = 0; mt < 2; mt++) {
            int row = rowB + mt * 16 + (lane & 15);
            int qq = 2 * s + (lane >> 4);
            uint32_t addr = aB + row * 128 + 16 * (qq ^ (row & 7));
            asm volatile("ldmatrix.sync.aligned.m8n8.x4.shared.b16 {%0,%1,%2,%3}, [%4];"
                         : "=r"(a[mt][0]), "=r"(a[mt][1]), "=r"(a[mt][2]), "=r"(a[mt][3])
                         : "r"(addr));
        }
#pragma unroll
        for (int ntp = 0; ntp < NT / 2; ntp++) {
            int m = lane >> 3;
            int nt = 2 * ntp + (m >> 1);
            int qq = 2 * s + (m & 1);
            int n = colB + nt * 8 + (lane & 7);
            uint32_t addr = bB + n * 128 + 16 * (qq ^ (n & 7));
            uint32_t b[4];
            asm volatile("ldmatrix.sync.aligned.m8n8.x4.shared.b16 {%0,%1,%2,%3}, [%4];"
                         : "=r"(b[0]), "=r"(b[1]), "=r"(b[2]), "=r"(b[3])
                         : "r"(addr));
#pragma unroll
            for (int mt = 0; mt < 2; mt++) {
                mma16(acc[mt][2 * ntp], a[mt], b);
                mma16(acc[mt][2 * ntp + 1], a[mt], b + 2);
            }
        }
    }
}

// ---------------- init ----------------
__global__ void init_kernel() {
    int j = blockIdx.x * blockDim.x + threadIdx.x;
    if (j < NN) { g_deg[j] = 0; g_cursor[j] = 0; }
    if (j < NG * 64) { g_gmax[j] = 0x007FFFFFu; g_gsum[j] = 0.f; }
    if (j < NG) g_gcnt[j] = 0;
}

// ---------------- CSR build ----------------
__global__ void hist_kernel(const int* __restrict__ dst) {
    int e = blockIdx.x * blockDim.x + threadIdx.x;
    if (e < NE) atomicAdd(&g_deg[dst[e]], 1);
}

__global__ void scan1_kernel() {
    __shared__ int wsum[8];
    int b = blockIdx.x, tid = threadIdx.x, lane = tid & 31, w = tid >> 5;
    int i0 = b * 1024 + tid * 4;
    int s = 0;
#pragma unroll
    for (int j = 0; j < 4; j++) { int i = i0 + j; if (i < NN) s += g_deg[i]; }
#pragma unroll
    for (int o = 16; o > 0; o >>= 1) s += __shfl_xor_sync(0xffffffffu, s, o);
    if (lane == 0) wsum[w] = s;
    __syncthreads();
    if (tid == 0) {
        int t = 0;
#pragma unroll
        for (int k = 0; k < 8; k++) t += wsum[k];
        g_bsum[b] = t;
    }
}

__global__ void scan2_kernel() {
    __shared__ int ws[4];
    int tid = threadIdx.x, lane = tid & 31, w = tid >> 5;
    int v = (tid < NBLK) ? g_bsum[tid] : 0;
    int si = v;
#pragma unroll
    for (int o = 1; o < 32; o <<= 1) { int t = __shfl_up_sync(0xffffffffu, si, o); if (lane >= o) si += t; }
    if (lane == 31) ws[w] = si;
    __syncthreads();
    if (tid == 0) {
        int run = 0;
#pragma unroll
        for (int k = 0; k < 4; k++) { int t = ws[k]; ws[k] = run; run += t; }
        g_rowptr[NN] = run;
    }
    __syncthreads();
    if (tid < NBLK) g_boff[tid] = ws[w] + si - v;
}

__global__ void scan3_kernel() {
    __shared__ int wsum[8];
    int b = blockIdx.x, tid = threadIdx.x, lane = tid & 31, w = tid >> 5;
    int i0 = b * 1024 + tid * 4;
    int v[4], s = 0;
#pragma unroll
    for (int j = 0; j < 4; j++) { int i = i0 + j; v[j] = (i < NN) ? g_deg[i] : 0; s += v[j]; }
    int si = s;
#pragma unroll
    for (int o = 1; o < 32; o <<= 1) { int t = __shfl_up_sync(0xffffffffu, si, o); if (lane >= o) si += t; }
    if (lane == 31) wsum[w] = si;
    __syncthreads();
    if (tid == 0) {
        int run = 0;
#pragma unroll
        for (int k = 0; k < 8; k++) { int t = wsum[k]; wsum[k] = run; run += t; }
    }
    __syncthreads();
    int off = g_boff[b] + wsum[w] + (si - s);
#pragma unroll
    for (int j = 0; j < 4; j++) { int i = i0 + j; if (i < NN) g_rowptr[i] = off; off += v[j]; }
}

__global__ void fill_adj_kernel(const int* __restrict__ src, const int* __restrict__ dst) {
    int e = blockIdx.x * blockDim.x + threadIdx.x;
    if (e < NE) {
        int d = dst[e];
        int p = atomicAdd(&g_cursor[d], 1);
        g_adj[g_rowptr[d] + p] = src[e];
    }
}

// ---------------- lin: one pass, full N=128 (NT=8) ----------------
__device__ __forceinline__ float4 lin_ld4(const float* nf, const float* cf,
                                          const int* opc, const float* emb, int grow, int k) {
    float4 v = make_float4(0, 0, 0, 0);
    if (k < 140)      v = *(const float4*)(nf + (size_t)grow * 140 + k);
    else if (k < 172) v = *(const float4*)(emb + (size_t)opc[grow] * 32 + (k - 140));
    else if (k < 190) {
        const float* cp = cf + (size_t)grow * 18;
        int off = k - 172;
        v.x = cp[off];
        v.y = (off + 1 < 18) ? cp[off + 1] : 0.f;
        v.z = (off + 2 < 18) ? cp[off + 2] : 0.f;
        v.w = (off + 3 < 18) ? cp[off + 3] : 0.f;
    }
    return v;
}

__global__ void __launch_bounds__(256)
lin_h(const float* __restrict__ nf, const float* __restrict__ cf,
      const int* __restrict__ opc, const float* __restrict__ emb,
      const float* __restrict__ W, const float* __restrict__ bias,
      uint32_t* __restrict__ C) {
    // smem: A 2x4096 words, B 2x4096 words (128 n-rows x 16 h2) -> 16384 words
    extern __shared__ uint32_t smem[];
    const uint32_t smb = smem_u32(smem);
    const int tid = threadIdx.x, lane = tid & 31, wid = tid >> 5;
    const int warpM = wid & 3, warpN = wid >> 2;  // warpN in {0,1}, 64 cols each
    const int rowBase = blockIdx.x * 128;

    float acc[2][8][4];
#pragma unroll
    for (int mt = 0; mt < 2; mt++)
#pragma unroll
        for (int nt = 0; nt < 8; nt++)
#pragma unroll
            for (int q = 0; q < 4; q++) acc[mt][nt][q] = 0.f;

    uint4 ra[2], rb[2];
    auto loadC = [&](int c) {
#pragma unroll
        for (int i = 0; i < 2; i++) {
            int g = tid + 256 * i;
            int row = g & 127, qq = g >> 7;
            int grow = rowBase + row;
            uint4 w = make_uint4(0, 0, 0, 0);
            if (grow < NN) {
                float4 v0 = lin_ld4(nf, cf, opc, emb, grow, c * 32 + 8 * qq);
                float4 v1 = lin_ld4(nf, cf, opc, emb, grow, c * 32 + 8 * qq + 4);
                w = make_uint4(f2h2(v0.x, v0.y), f2h2(v0.z, v0.w), f2h2(v1.x, v1.y), f2h2(v1.z, v1.w));
            }
            ra[i] = w;
        }
#pragma unroll
        for (int i = 0; i < 2; i++) {
            int g = tid + 256 * i;
            int n = g & 127, qq = g >> 7;
            float f[8];
#pragma unroll
            for (int j = 0; j < 8; j++) {
                int kg = c * 32 + 8 * qq + j;
                f[j] = (kg < 190) ? W[(size_t)kg * 128 + n] : 0.f;
            }
            rb[i] = make_uint4(f2h2(f[0], f[1]), f2h2(f[2], f[3]), f2h2(f[4], f[5]), f2h2(f[6], f[7]));
        }
    };
    auto stage = [&](int b) {
        uint32_t* sa = smem + (b ? 4096 : 0);
        uint32_t* sb = smem + 8192 + (b ? 4096 : 0);
#pragma unroll
        for (int i = 0; i < 2; i++) {
            int g = tid + 256 * i;
            stTile4(sa, g & 127, g >> 7, ra[i]);
            stTile4(sb, g & 127, g >> 7, rb[i]);
        }
    };

    loadC(0); stage(0); __syncthreads();
#pragma unroll 1
    for (int c = 0; c < 6; c++) {
        if (c < 5) loadC(c + 1);
        uint32_t aB = smb + ((c & 1) ? 4096u : 0u) * 4u;
        uint32_t bB = smb + (8192u + ((c & 1) ? 4096u : 0u)) * 4u;
        chunk_mma_ldm<8>(aB, bB, acc, warpM * 32, warpN * 64, lane);
        if (c < 5) { stage((c + 1) & 1); __syncthreads(); }
    }

    const int qr = lane >> 2, qc = lane & 3;
#pragma unroll
    for (int mt = 0; mt < 2; mt++) {
        int r0 = rowBase + warpM * 32 + mt * 16 + qr;
#pragma unroll
        for (int nt = 0; nt < 8; nt++) {
            int gc = warpN * 64 + nt * 8 + 2 * qc;
            float b0 = __ldg(&bias[gc]), b1 = __ldg(&bias[gc + 1]);
            if (r0 < NN)
                C[(size_t)r0 * 64 + gc / 2] =
                    f2h2(fmaxf(acc[mt][nt][0] + b0, 0.f), fmaxf(acc[mt][nt][1] + b1, 0.f));
            if (r0 + 8 < NN)
                C[(size_t)(r0 + 8) * 64 + gc / 2] =
                    f2h2(fmaxf(acc[mt][nt][2] + b0, 0.f), fmaxf(acc[mt][nt][3] + b1, 0.f));
        }
    }
}

// ---------------- projz: Z(half2) = relu(A@PW + PB) @ WL ----------------
template <int K>
__global__ void __launch_bounds__(256)
projz_h(const uint32_t* __restrict__ A, const float* __restrict__ PW,
        const float* __restrict__ PB, const float* __restrict__ WL,
        __half2* __restrict__ Z) {
    constexpr int NCH = K / 32;
    constexpr int CW = K / 2;
    constexpr int NT1 = CW / 8;
    constexpr int INB = K * 32;
    constexpr int INW = 8192 + 2 * INB;
    constexpr int XW = NCH * 4096;
    constexpr int UW = (INW > XW) ? INW : XW;
    constexpr int NST = K / 64;
    extern __shared__ uint32_t smem[];
    uint32_t* W2 = smem + UW;
    const uint32_t smb = smem_u32(smem);

    const int tid = threadIdx.x, lane = tid & 31, wid = tid >> 5;
    const int warpM = wid & 3, warpN = wid >> 2;
    const int rowBase = blockIdx.x * 128;
    const int qr = lane >> 2, qc = lane & 3;

#pragma unroll
    for (int c = 0; c < NCH; c++) {
        int n = tid & 63, qq = tid >> 6;
        float f[8];
#pragma unroll
        for (int j = 0; j < 8; j++) f[j] = WL[(size_t)(c * 32 + 8 * qq + j) * 64 + n];
        stTile4(W2 + c * 2048, n, qq,
                make_uint4(f2h2(f[0], f[1]), f2h2(f[2], f[3]), f2h2(f[4], f[5]), f2h2(f[6], f[7])));
    }

    float acc1[2][NT1][4];
#pragma unroll
    for (int mt = 0; mt < 2; mt++)
#pragma unroll
        for (int nt = 0; nt < NT1; nt++)
#pragma unroll
            for (int q = 0; q < 4; q++) acc1[mt][nt][q] = 0.f;

    uint4 ra[2], rb[NST];
    auto loadC = [&](int c) {
#pragma unroll
        for (int i = 0; i < 2; i++) {
            int g = tid + 256 * i;
            int row = g & 127, qq = g >> 7;
            int grow = rowBase + row;
            ra[i] = (grow < NN)
                ? *reinterpret_cast<const uint4*>(A + (size_t)grow * (K / 2) + c * 16 + 4 * qq)
                : make_uint4(0, 0, 0, 0);
        }
#pragma unroll
        for (int i = 0; i < NST; i++) {
            int g = tid + 256 * i;
            int n = g % K, qq = g / K;
            float f[8];
#pragma unroll
            for (int j = 0; j < 8; j++) f[j] = PW[(size_t)(c * 32 + 8 * qq + j) * K + n];
            rb[i] = make_uint4(f2h2(f[0], f[1]), f2h2(f[2], f[3]), f2h2(f[4], f[5]), f2h2(f[6], f[7]));
        }
    };
    auto stage = [&](int b) {
        uint32_t* sa = smem + (b ? 4096 : 0);
        uint32_t* sb = smem + 8192 + (b ? INB : 0);
#pragma unroll
        for (int i = 0; i < 2; i++) {
            int g = tid + 256 * i;
            stTile4(sa, g & 127, g >> 7, ra[i]);
        }
#pragma unroll
        for (int i = 0; i < NST; i++) {
            int g = tid + 256 * i;
            stTile4(sb, g % K, g / K, rb[i]);
        }
    };

    loadC(0); stage(0); __syncthreads();
#pragma unroll 1
    for (int c = 0; c < NCH; c++) {
        if (c + 1 < NCH) loadC(c + 1);
        uint32_t aB = smb + ((c & 1) ? 4096u : 0u) * 4u;
        uint32_t bB = smb + (8192u + ((c & 1) ? (uint32_t)INB : 0u)) * 4u;
        chunk_mma_ldm<NT1>(aB, bB, acc1, warpM * 32, warpN * CW, lane);
        if (c + 1 < NCH) { stage((c + 1) & 1); __syncthreads(); }
    }
    __syncthreads();

#pragma unroll
    for (int mt = 0; mt < 2; mt++) {
        int r0 = warpM * 32 + mt * 16 + qr;
#pragma unroll
        for (int nt = 0; nt < NT1; nt++) {
            int col = warpN * CW + nt * 8 + 2 * qc;
            float b0 = __ldg(&PB[col]), b1 = __ldg(&PB[col + 1]);
            stXh(smem, r0, col / 2,
                 f2h2(fmaxf(acc1[mt][nt][0] + b0, 0.f), fmaxf(acc1[mt][nt][1] + b1, 0.f)));
            stXh(smem, r0 + 8, col / 2,
                 f2h2(fmaxf(acc1[mt][nt][2] + b0, 0.f), fmaxf(acc1[mt][nt][3] + b1, 0.f)));
        }
    }
    __syncthreads();

    float acc2[2][4][4];
#pragma unroll
    for (int mt = 0; mt < 2; mt++)
#pragma unroll
        for (int nt = 0; nt < 4; nt++)
#pragma unroll
            for (int q = 0; q < 4; q++) acc2[mt][nt][q] = 0.f;
#pragma unroll
    for (int c = 0; c < NCH; c++)
        chunk_mma_ldm<4>(smb + (uint32_t)(c * 4096) * 4u,
                         smb + (uint32_t)(UW + c * 2048) * 4u,
                         acc2, warpM * 32, warpN * 32, lane);

#pragma unroll
    for (int mt = 0; mt < 2; mt++) {
        int r0 = rowBase + warpM * 32 + mt * 16 + qr;
#pragma unroll
        for (int nt = 0; nt < 4; nt++) {
            int gc = warpN * 32 + nt * 8 + 2 * qc;
            if (r0 < NN)
                Z[(size_t)r0 * 32 + gc / 2] = __floats2half2_rn(acc2[mt][nt][0], acc2[mt][nt][1]);
            if (r0 + 8 < NN)
                Z[(size_t)(r0 + 8) * 32 + gc / 2] = __floats2half2_rn(acc2[mt][nt][2], acc2[mt][nt][3]);
        }
    }
}

// ---------------- combine: out = normalize(X@WR + MZ + BL), MZ fp16 ----------------
template <int K, bool HOUT>
__global__ void __launch_bounds__(256)
combine_h(const uint32_t* __restrict__ X, const float* __restrict__ WR,
          const __half2* __restrict__ MZ, const float* __restrict__ BL,
          void* __restrict__ Cout) {
    constexpr int NCH = K / 32;
    extern __shared__ uint32_t smem[];
    const uint32_t smb = smem_u32(smem);
    const int tid = threadIdx.x, lane = tid & 31, wid = tid >> 5;
    const int warpM = wid & 3, warpN = wid >> 2;
    const int rowBase = blockIdx.x * 128;

    float acc[2][4][4];
#pragma unroll
    for (int mt = 0; mt < 2; mt++)
#pragma unroll
        for (int nt = 0; nt < 4; nt++)
#pragma unroll
            for (int q = 0; q < 4; q++) acc[mt][nt][q] = 0.f;

    uint4 ra[2], rb;
    auto loadC = [&](int c) {
#pragma unroll
        for (int i = 0; i < 2; i++) {
            int g = tid + 256 * i;
            int row = g & 127, qq = g >> 7;
            int grow = rowBase + row;
            ra[i] = (grow < NN)
                ? *reinterpret_cast<const uint4*>(X + (size_t)grow * (K / 2) + c * 16 + 4 * qq)
                : make_uint4(0, 0, 0, 0);
        }
        {
            int n = tid & 63, qq = tid >> 6;
            float f[8];
#pragma unroll
            for (int j = 0; j < 8; j++) f[j] = WR[(size_t)(c * 32 + 8 * qq + j) * 64 + n];
            rb = make_uint4(f2h2(f[0], f[1]), f2h2(f[2], f[3]), f2h2(f[4], f[5]), f2h2(f[6], f[7]));
        }
    };
    auto stage = [&](int b) {
        uint32_t* sa = smem + (b ? 4096 : 0);
        uint32_t* sb = smem + 8192 + (b ? 2048 : 0);
#pragma unroll
        for (int i = 0; i < 2; i++) {
            int g = tid + 256 * i;
            stTile4(sa, g & 127, g >> 7, ra[i]);
        }
        stTile4(sb, tid & 63, tid >> 6, rb);
    };

    loadC(0); stage(0); __syncthreads();
#pragma unroll 1
    for (int c = 0; c < NCH; c++) {
        if (c + 1 < NCH) loadC(c + 1);
        uint32_t aB = smb + ((c & 1) ? 4096u : 0u) * 4u;
        uint32_t bB = smb + (8192u + ((c & 1) ? 2048u : 0u)) * 4u;
        chunk_mma_ldm<4>(aB, bB, acc, warpM * 32, warpN * 32, lane);
        if (c + 1 < NCH) { stage((c + 1) & 1); __syncthreads(); }
    }

    __syncthreads();
    float (*sOut)[66] = reinterpret_cast<float(*)[66]>(smem);
    const int qr = lane >> 2, qc = lane & 3;
#pragma unroll
    for (int mt = 0; mt < 2; mt++) {
        int rl = warpM * 32 + mt * 16 + qr;
        int g0 = rowBase + rl, g1 = rowBase + rl + 8;
#pragma unroll
        for (int nt = 0; nt < 4; nt++) {
            int cl = warpN * 32 + nt * 8 + 2 * qc;
            float b0 = __ldg(&BL[cl]), b1 = __ldg(&BL[cl + 1]);
            float2 m0 = (g0 < NN) ? __half22float2(MZ[(size_t)g0 * 32 + cl / 2]) : make_float2(0, 0);
            float2 m1 = (g1 < NN) ? __half22float2(MZ[(size_t)g1 * 32 + cl / 2]) : make_float2(0, 0);
            sOut[rl][cl]         = acc[mt][nt][0] + b0 + m0.x;
            sOut[rl][cl + 1]     = acc[mt][nt][1] + b1 + m0.y;
            sOut[rl + 8][cl]     = acc[mt][nt][2] + b0 + m1.x;
            sOut[rl + 8][cl + 1] = acc[mt][nt][3] + b1 + m1.y;
        }
    }
    __syncthreads();
#pragma unroll
    for (int rr = 0; rr < 16; rr++) {
        int r = wid * 16 + rr;
        int grow = rowBase + r;
        float2 v = *(const float2*)&sOut[r][2 * lane];
        float ss = v.x * v.x + v.y * v.y;
#pragma unroll
        for (int o = 16; o > 0; o >>= 1) ss += __shfl_xor_sync(0xffffffffu, ss, o);
        float sc = 1.0f / fmaxf(sqrtf(ss), 1e-12f);
        if (grow < NN) {
            if (HOUT) {
                ((uint32_t*)Cout)[(size_t)grow * 32 + lane] = f2h2(v.x * sc, v.y * sc);
            } else {
                *(float2*)((float*)Cout + (size_t)grow * 64 + 2 * lane) =
                    make_float2(v.x * sc, v.y * sc);
            }
        }
    }
}

// ---------------- mean aggregation over CSR (fp16 in, fp16 out) ----------------
__global__ void agg_half(const __half2* __restrict__ zp, __half2* __restrict__ msg) {
    int w = (blockIdx.x * blockDim.x + threadIdx.x) >> 5;
    int lane = threadIdx.x & 31;
    if (w >= NN) return;
    int beg = g_rowptr[w], end = g_rowptr[w + 1];
    float2 acc = make_float2(0, 0);
    int e = beg;
    for (; e + 4 <= end; e += 4) {
        int s0 = __ldg(&g_adj[e]);
        int s1 = __ldg(&g_adj[e + 1]);
        int s2 = __ldg(&g_adj[e + 2]);
        int s3 = __ldg(&g_adj[e + 3]);
        float2 v0 = __half22float2(zp[(size_t)s0 * 32 + lane]);
        float2 v1 = __half22float2(zp[(size_t)s1 * 32 + lane]);
        float2 v2 = __half22float2(zp[(size_t)s2 * 32 + lane]);
        float2 v3 = __half22float2(zp[(size_t)s3 * 32 + lane]);
        acc.x += (v0.x + v1.x) + (v2.x + v3.x);
        acc.y += (v0.y + v1.y) + (v2.y + v3.y);
    }
    for (; e < end; e++) {
        int s = __ldg(&g_adj[e]);
        float2 v = __half22float2(zp[(size_t)s * 32 + lane]);
        acc.x += v.x; acc.y += v.y;
    }
    float inv = 1.0f / fmaxf((float)(end - beg), 1.0f);
    msg[(size_t)w * 32 + lane] = __floats2half2_rn(acc.x * inv, acc.y * inv);
}

// ---------------- pooling ----------------
__global__ void pool_kernel(const float* __restrict__ x, const int* __restrict__ batch) {
    int nwarps = (gridDim.x * blockDim.x) >> 5;
    int w = (blockIdx.x * blockDim.x + threadIdx.x) >> 5;
    int lane = threadIdx.x & 31;
    int per = (NN + nwarps - 1) / nwarps;
    int s = w * per;
    int e = min(NN, s + per);
    if (s >= e) return;
    float m0 = -__int_as_float(0x7f800000), m1 = m0;
    float s0 = 0.f, s1 = 0.f;
    int cnt = 0;
    int curg = __ldg(&batch[s]);
    for (int i = s; i < e; i++) {
        int g = __ldg(&batch[i]);
        if (g != curg) {
            atomicMax(&g_gmax[curg * 64 + lane], fenc(m0));
            atomicMax(&g_gmax[curg * 64 + lane + 32], fenc(m1));
            atomicAdd(&g_gsum[curg * 64 + lane], s0);
            atomicAdd(&g_gsum[curg * 64 + lane + 32], s1);
            if (lane == 0) atomicAdd(&g_gcnt[curg], cnt);
            m0 = m1 = -__int_as_float(0x7f800000);
            s0 = s1 = 0.f; cnt = 0; curg = g;
        }
        float v0 = x[(size_t)i * 64 + lane];
        float v1 = x[(size_t)i * 64 + lane + 32];
        m0 = fmaxf(m0, v0); m1 = fmaxf(m1, v1);
        s0 += v0; s1 += v1; cnt++;
    }
    atomicMax(&g_gmax[curg * 64 + lane], fenc(m0));
    atomicMax(&g_gmax[curg * 64 + lane + 32], fenc(m1));
    atomicAdd(&g_gsum[curg * 64 + lane], s0);
    atomicAdd(&g_gsum[curg * 64 + lane + 32], s1);
    if (lane == 0) atomicAdd(&g_gcnt[curg], cnt);
}

// ---------------- final ----------------
__global__ void final_kernel(const float* __restrict__ post_w, const float* __restrict__ post_b,
                             float* __restrict__ out) {
    int g = threadIdx.x;
    if (g >= NG) return;
    float inv = 1.0f / (float)g_gcnt[g];
    float v[64];
    float ss = 0.f;
#pragma unroll
    for (int c = 0; c < 64; c++) {
        float t = fdec(g_gmax[g * 64 + c]) + g_gsum[g * 64 + c] * inv;
        v[c] = t;
        ss += t * t;
    }
    float norm = sqrtf(ss);
    float dot = 0.f;
#pragma unroll
    for (int c = 0; c < 64; c++) dot += v[c] * post_w[c];
    out[g] = dot / norm + post_b[0];
}

// ---------------- launch ----------------
static cudaStream_t g_s2 = nullptr;
static cudaEvent_t g_ev1 = nullptr, g_ev2 = nullptr;

extern "C" void kernel_launch(void* const* d_in, const int* in_sizes, int n_in,
                              void* d_out, int out_size) {
    const float* node_feat = (const float*)d_in[0];
    const float* cfg_feat  = (const float*)d_in[1];
    const int*   opcode    = (const int*)d_in[2];
    const int*   edge      = (const int*)d_in[3];
    const int*   batch     = (const int*)d_in[4];
    const float* op_emb    = (const float*)d_in[5];
    const float* lin_w     = (const float*)d_in[6];
    const float* lin_b     = (const float*)d_in[7];
    const float* post_w    = (const float*)d_in[8];
    const float* post_b    = (const float*)d_in[9];
    const float* pw0 = (const float*)d_in[10];
    const float* pb0 = (const float*)d_in[11];
    const float* wl0 = (const float*)d_in[12];
    const float* bl0 = (const float*)d_in[13];
    const float* wr0 = (const float*)d_in[14];
    const float* pw1 = (const float*)d_in[15];
    const float* pb1 = (const float*)d_in[16];
    const float* wl1 = (const float*)d_in[17];
    const float* bl1 = (const float*)d_in[18];
    const float* wr1 = (const float*)d_in[19];
    const float* pw2 = (const float*)d_in[20];
    const float* pb2 = (const float*)d_in[21];
    const float* wl2 = (const float*)d_in[22];
    const float* bl2 = (const float*)d_in[23];
    const float* wr2 = (const float*)d_in[24];
    float* out = (float*)d_out;

    if (g_s2 == nullptr) {
        cudaStreamCreateWithFlags(&g_s2, cudaStreamNonBlocking);
        cudaEventCreateWithFlags(&g_ev1, cudaEventDisableTiming);
        cudaEventCreateWithFlags(&g_ev2, cudaEventDisableTiming);
        cudaFuncSetAttribute(lin_h,        cudaFuncAttributeMaxDynamicSharedMemorySize, 65536);
        cudaFuncSetAttribute(projz_h<128>, cudaFuncAttributeMaxDynamicSharedMemorySize, 98304);
        cudaFuncSetAttribute(projz_h<64>,  cudaFuncAttributeMaxDynamicSharedMemorySize, 65536);
    }

    const int* src = edge;
    const int* dst = edge + NE;

    const int MB = (NN + 127) / 128;
    const int EB = (NE + 255) / 256;
    const int AGGB = (NN * 32 + 255) / 256;
    const size_t SMEM48 = 49152;
    const size_t SMEM64 = 65536;
    const size_t SMEM_PZ128 = 98304;
    const size_t SMEM_PZ64  = 65536;

    uint32_t* dA; cudaGetSymbolAddress((void**)&dA, g_xA);
    uint32_t* dB; cudaGetSymbolAddress((void**)&dB, g_xB);
    float* dC; cudaGetSymbolAddress((void**)&dC, g_xC);
    __half2* dZ; cudaGetSymbolAddress((void**)&dZ, g_z);
    __half2* dM; cudaGetSymbolAddress((void**)&dM, g_msg);

    // fork: CSR build on side stream
    cudaEventRecord(g_ev1, 0);
    cudaStreamWaitEvent(g_s2, g_ev1, 0);
    init_kernel<<<(NN + 255) / 256, 256, 0, g_s2>>>();
    hist_kernel<<<EB, 256, 0, g_s2>>>(dst);
    scan1_kernel<<<NBLK, 256, 0, g_s2>>>();
    scan2_kernel<<<1, 128, 0, g_s2>>>();
    scan3_kernel<<<NBLK, 256, 0, g_s2>>>();
    fill_adj_kernel<<<EB, 256, 0, g_s2>>>(src, dst);
    cudaEventRecord(g_ev2, g_s2);

    lin_h<<<MB, 256, SMEM64>>>(node_feat, cfg_feat, opcode, op_emb, lin_w, lin_b, dA);
    projz_h<128><<<MB, 256, SMEM_PZ128>>>(dA, pw0, pb0, wl0, dZ);

    cudaStreamWaitEvent(0, g_ev2, 0);

    // layer 0 (d=128 -> 64)
    agg_half<<<AGGB, 256>>>(dZ, dM);
    combine_h<128, true><<<MB, 256, SMEM48>>>(dA, wr0, dM, bl0, dB);

    // layer 1 (d=64 -> 64)
    projz_h<64><<<MB, 256, SMEM_PZ64>>>(dB, pw1, pb1, wl1, dZ);
    agg_half<<<AGGB, 256>>>(dZ, dM);
    combine_h<64, true><<<MB, 256, SMEM48>>>(dB, wr1, dM, bl1, dA);

    // layer 2 (d=64 -> 64), fp32 output for pooling
    projz_h<64><<<MB, 256, SMEM_PZ64>>>(dA, pw2, pb2, wl2, dZ);
    agg_half<<<AGGB, 256>>>(dZ, dM);
    combine_h<64, false><<<MB, 256, SMEM48>>>(dA, wr2, dM, bl2, dC);

    pool_kernel<<<128, 256>>>(dC, batch);
    final_kernel<<<1, 64>>>(post_w, post_b, out);
}

// round 16
// speedup vs baseline: 1.4024x; 1.0832x over previous
#include <cuda_runtime.h>
#include <cuda_fp16.h>
#include <cstdint>

#define NN 100000
#define NE 1600000
#define NG 64
#define NBLK 98   // ceil(NN/1024)

// ---------------- scratch ----------------
__device__ __align__(256) uint32_t g_xA[(size_t)NN * 64];
__device__ __align__(256) uint32_t g_xB[(size_t)NN * 64];
__device__ __align__(256) __half2 g_z[(size_t)NN * 32];
__device__ __align__(256) __half2 g_msg[(size_t)NN * 32];
__device__ int g_deg[NN];
__device__ int g_cursor[NN];
__device__ int g_rowptr[NN + 1];
__device__ int g_adj[NE];
__device__ int g_bsum[NBLK];
__device__ int g_boff[NBLK];
__device__ unsigned g_gmax[NG * 64];
__device__ float g_gsum[NG * 64];
__device__ int g_gcnt[NG];

// ---------------- helpers ----------------
__device__ __forceinline__ uint32_t smem_u32(const void* p) {
    uint32_t a;
    asm("{ .reg .u64 t; cvta.to.shared.u64 t, %1; cvt.u32.u64 %0, t; }" : "=r"(a) : "l"(p));
    return a;
}
__device__ __forceinline__ uint32_t f2h2(float lo, float hi) {
    __half2 h = __floats2half2_rn(lo, hi);
    return *reinterpret_cast<uint32_t*>(&h);
}
__device__ __forceinline__ void mma16(float* c, const uint32_t* a, const uint32_t* b) {
    asm volatile(
        "mma.sync.aligned.m16n8k16.row.col.f32.f16.f16.f32 "
        "{%0,%1,%2,%3}, {%4,%5,%6,%7}, {%8,%9}, {%0,%1,%2,%3};"
        : "+f"(c[0]), "+f"(c[1]), "+f"(c[2]), "+f"(c[3])
        : "r"(a[0]), "r"(a[1]), "r"(a[2]), "r"(a[3]), "r"(b[0]), "r"(b[1]));
}
__device__ __forceinline__ unsigned fenc(float f) {
    unsigned u = __float_as_uint(f);
    return (u & 0x80000000u) ? ~u : (u | 0x80000000u);
}
__device__ __forceinline__ float fdec(unsigned e) {
    return __uint_as_float((e & 0x80000000u) ? (e ^ 0x80000000u) : ~e);
}

// ---------------- fp16 XOR-swizzled tiles ----------------
__device__ __forceinline__ void stTile4(uint32_t* s, int row, int qq, uint4 w) {
    *reinterpret_cast<uint4*>(s + row * 32 + 4 * (qq ^ (row & 7))) = w;
}
__device__ __forceinline__ void stXh(uint32_t* sX, int row, int c2, uint32_t w) {
    uint32_t* t = sX + (c2 >> 4) * 4096;
    int lc = c2 & 15;
    t[row * 32 + 4 * ((lc >> 2) ^ (row & 7)) + (lc & 3)] = w;
}

// ldmatrix-based fragment consumer
template <int NT>
__device__ __forceinline__ void chunk_mma_ldm(uint32_t aB, uint32_t bB,
                                              float (&acc)[2][NT][4], int rowB, int colB, int lane) {
#pragma unroll
    for (int s = 0; s < 2; s++) {
        uint32_t a[2][4];
#pragma unroll
        for (int mt = 0; mt < 2; mt++) {
            int row = rowB + mt * 16 + (lane & 15);
            int qq = 2 * s + (lane >> 4);
            uint32_t addr = aB + row * 128 + 16 * (qq ^ (row & 7));
            asm volatile("ldmatrix.sync.aligned.m8n8.x4.shared.b16 {%0,%1,%2,%3}, [%4];"
                         : "=r"(a[mt][0]), "=r"(a[mt][1]), "=r"(a[mt][2]), "=r"(a[mt][3])
                         : "r"(addr));
        }
#pragma unroll
        for (int ntp = 0; ntp < NT / 2; ntp++) {
            int m = lane >> 3;
            int nt = 2 * ntp + (m >> 1);
            int qq = 2 * s + (m & 1);
            int n = colB + nt * 8 + (lane & 7);
            uint32_t addr = bB + n * 128 + 16 * (qq ^ (n & 7));
            uint32_t b[4];
            asm volatile("ldmatrix.sync.aligned.m8n8.x4.shared.b16 {%0,%1,%2,%3}, [%4];"
                         : "=r"(b[0]), "=r"(b[1]), "=r"(b[2]), "=r"(b[3])
                         : "r"(addr));
#pragma unroll
            for (int mt = 0; mt < 2; mt++) {
                mma16(acc[mt][2 * ntp], a[mt], b);
                mma16(acc[mt][2 * ntp + 1], a[mt], b + 2);
            }
        }
    }
}

// ---------------- init ----------------
__global__ void init_kernel() {
    int j = blockIdx.x * blockDim.x + threadIdx.x;
    if (j < NN) { g_deg[j] = 0; g_cursor[j] = 0; }
    if (j < NG * 64) { g_gmax[j] = 0x007FFFFFu; g_gsum[j] = 0.f; }
    if (j < NG) g_gcnt[j] = 0;
}

// ---------------- CSR build ----------------
__global__ void hist_kernel(const int* __restrict__ dst) {
    int e = blockIdx.x * blockDim.x + threadIdx.x;
    if (e < NE) atomicAdd(&g_deg[dst[e]], 1);
}

__global__ void scan1_kernel() {
    __shared__ int wsum[8];
    int b = blockIdx.x, tid = threadIdx.x, lane = tid & 31, w = tid >> 5;
    int i0 = b * 1024 + tid * 4;
    int s = 0;
#pragma unroll
    for (int j = 0; j < 4; j++) { int i = i0 + j; if (i < NN) s += g_deg[i]; }
#pragma unroll
    for (int o = 16; o > 0; o >>= 1) s += __shfl_xor_sync(0xffffffffu, s, o);
    if (lane == 0) wsum[w] = s;
    __syncthreads();
    if (tid == 0) {
        int t = 0;
#pragma unroll
        for (int k = 0; k < 8; k++) t += wsum[k];
        g_bsum[b] = t;
    }
}

__global__ void scan2_kernel() {
    __shared__ int ws[4];
    int tid = threadIdx.x, lane = tid & 31, w = tid >> 5;
    int v = (tid < NBLK) ? g_bsum[tid] : 0;
    int si = v;
#pragma unroll
    for (int o = 1; o < 32; o <<= 1) { int t = __shfl_up_sync(0xffffffffu, si, o); if (lane >= o) si += t; }
    if (lane == 31) ws[w] = si;
    __syncthreads();
    if (tid == 0) {
        int run = 0;
#pragma unroll
        for (int k = 0; k < 4; k++) { int t = ws[k]; ws[k] = run; run += t; }
        g_rowptr[NN] = run;
    }
    __syncthreads();
    if (tid < NBLK) g_boff[tid] = ws[w] + si - v;
}

__global__ void scan3_kernel() {
    __shared__ int wsum[8];
    int b = blockIdx.x, tid = threadIdx.x, lane = tid & 31, w = tid >> 5;
    int i0 = b * 1024 + tid * 4;
    int v[4], s = 0;
#pragma unroll
    for (int j = 0; j < 4; j++) { int i = i0 + j; v[j] = (i < NN) ? g_deg[i] : 0; s += v[j]; }
    int si = s;
#pragma unroll
    for (int o = 1; o < 32; o <<= 1) { int t = __shfl_up_sync(0xffffffffu, si, o); if (lane >= o) si += t; }
    if (lane == 31) wsum[w] = si;
    __syncthreads();
    if (tid == 0) {
        int run = 0;
#pragma unroll
        for (int k = 0; k < 8; k++) { int t = wsum[k]; wsum[k] = run; run += t; }
    }
    __syncthreads();
    int off = g_boff[b] + wsum[w] + (si - s);
#pragma unroll
    for (int j = 0; j < 4; j++) { int i = i0 + j; if (i < NN) g_rowptr[i] = off; off += v[j]; }
}

__global__ void fill_adj_kernel(const int* __restrict__ src, const int* __restrict__ dst) {
    int e = blockIdx.x * blockDim.x + threadIdx.x;
    if (e < NE) {
        int d = dst[e];
        int p = atomicAdd(&g_cursor[d], 1);
        g_adj[g_rowptr[d] + p] = src[e];
    }
}

// ---------------- lin: one pass, full N=128 (NT=8) ----------------
__device__ __forceinline__ float4 lin_ld4(const float* nf, const float* cf,
                                          const int* opc, const float* emb, int grow, int k) {
    float4 v = make_float4(0, 0, 0, 0);
    if (k < 140)      v = *(const float4*)(nf + (size_t)grow * 140 + k);
    else if (k < 172) v = *(const float4*)(emb + (size_t)opc[grow] * 32 + (k - 140));
    else if (k < 190) {
        const float* cp = cf + (size_t)grow * 18;
        int off = k - 172;
        v.x = cp[off];
        v.y = (off + 1 < 18) ? cp[off + 1] : 0.f;
        v.z = (off + 2 < 18) ? cp[off + 2] : 0.f;
        v.w = (off + 3 < 18) ? cp[off + 3] : 0.f;
    }
    return v;
}

__global__ void __launch_bounds__(256)
lin_h(const float* __restrict__ nf, const float* __restrict__ cf,
      const int* __restrict__ opc, const float* __restrict__ emb,
      const float* __restrict__ W, const float* __restrict__ bias,
      uint32_t* __restrict__ C) {
    extern __shared__ uint32_t smem[];
    const uint32_t smb = smem_u32(smem);
    const int tid = threadIdx.x, lane = tid & 31, wid = tid >> 5;
    const int warpM = wid & 3, warpN = wid >> 2;
    const int rowBase = blockIdx.x * 128;

    float acc[2][8][4];
#pragma unroll
    for (int mt = 0; mt < 2; mt++)
#pragma unroll
        for (int nt = 0; nt < 8; nt++)
#pragma unroll
            for (int q = 0; q < 4; q++) acc[mt][nt][q] = 0.f;

    uint4 ra[2], rb[2];
    auto loadC = [&](int c) {
#pragma unroll
        for (int i = 0; i < 2; i++) {
            int g = tid + 256 * i;
            int row = g & 127, qq = g >> 7;
            int grow = rowBase + row;
            uint4 w = make_uint4(0, 0, 0, 0);
            if (grow < NN) {
                float4 v0 = lin_ld4(nf, cf, opc, emb, grow, c * 32 + 8 * qq);
                float4 v1 = lin_ld4(nf, cf, opc, emb, grow, c * 32 + 8 * qq + 4);
                w = make_uint4(f2h2(v0.x, v0.y), f2h2(v0.z, v0.w), f2h2(v1.x, v1.y), f2h2(v1.z, v1.w));
            }
            ra[i] = w;
        }
#pragma unroll
        for (int i = 0; i < 2; i++) {
            int g = tid + 256 * i;
            int n = g & 127, qq = g >> 7;
            float f[8];
#pragma unroll
            for (int j = 0; j < 8; j++) {
                int kg = c * 32 + 8 * qq + j;
                f[j] = (kg < 190) ? W[(size_t)kg * 128 + n] : 0.f;
            }
            rb[i] = make_uint4(f2h2(f[0], f[1]), f2h2(f[2], f[3]), f2h2(f[4], f[5]), f2h2(f[6], f[7]));
        }
    };
    auto stage = [&](int b) {
        uint32_t* sa = smem + (b ? 4096 : 0);
        uint32_t* sb = smem + 8192 + (b ? 4096 : 0);
#pragma unroll
        for (int i = 0; i < 2; i++) {
            int g = tid + 256 * i;
            stTile4(sa, g & 127, g >> 7, ra[i]);
            stTile4(sb, g & 127, g >> 7, rb[i]);
        }
    };

    loadC(0); stage(0); __syncthreads();
#pragma unroll 1
    for (int c = 0; c < 6; c++) {
        if (c < 5) loadC(c + 1);
        uint32_t aB = smb + ((c & 1) ? 4096u : 0u) * 4u;
        uint32_t bB = smb + (8192u + ((c & 1) ? 4096u : 0u)) * 4u;
        chunk_mma_ldm<8>(aB, bB, acc, warpM * 32, warpN * 64, lane);
        if (c < 5) { stage((c + 1) & 1); __syncthreads(); }
    }

    const int qr = lane >> 2, qc = lane & 3;
#pragma unroll
    for (int mt = 0; mt < 2; mt++) {
        int r0 = rowBase + warpM * 32 + mt * 16 + qr;
#pragma unroll
        for (int nt = 0; nt < 8; nt++) {
            int gc = warpN * 64 + nt * 8 + 2 * qc;
            float b0 = __ldg(&bias[gc]), b1 = __ldg(&bias[gc + 1]);
            if (r0 < NN)
                C[(size_t)r0 * 64 + gc / 2] =
                    f2h2(fmaxf(acc[mt][nt][0] + b0, 0.f), fmaxf(acc[mt][nt][1] + b1, 0.f));
            if (r0 + 8 < NN)
                C[(size_t)(r0 + 8) * 64 + gc / 2] =
                    f2h2(fmaxf(acc[mt][nt][2] + b0, 0.f), fmaxf(acc[mt][nt][3] + b1, 0.f));
        }
    }
}

// ---------------- projz: Z(half2) = relu(A@PW + PB) @ WL ----------------
template <int K>
__global__ void __launch_bounds__(256)
projz_h(const uint32_t* __restrict__ A, const float* __restrict__ PW,
        const float* __restrict__ PB, const float* __restrict__ WL,
        __half2* __restrict__ Z) {
    constexpr int NCH = K / 32;
    constexpr int CW = K / 2;
    constexpr int NT1 = CW / 8;
    constexpr int INB = K * 32;
    constexpr int INW = 8192 + 2 * INB;
    constexpr int XW = NCH * 4096;
    constexpr int UW = (INW > XW) ? INW : XW;
    constexpr int NST = K / 64;
    extern __shared__ uint32_t smem[];
    uint32_t* W2 = smem + UW;
    const uint32_t smb = smem_u32(smem);

    const int tid = threadIdx.x, lane = tid & 31, wid = tid >> 5;
    const int warpM = wid & 3, warpN = wid >> 2;
    const int rowBase = blockIdx.x * 128;
    const int qr = lane >> 2, qc = lane & 3;

#pragma unroll
    for (int c = 0; c < NCH; c++) {
        int n = tid & 63, qq = tid >> 6;
        float f[8];
#pragma unroll
        for (int j = 0; j < 8; j++) f[j] = WL[(size_t)(c * 32 + 8 * qq + j) * 64 + n];
        stTile4(W2 + c * 2048, n, qq,
                make_uint4(f2h2(f[0], f[1]), f2h2(f[2], f[3]), f2h2(f[4], f[5]), f2h2(f[6], f[7])));
    }

    float acc1[2][NT1][4];
#pragma unroll
    for (int mt = 0; mt < 2; mt++)
#pragma unroll
        for (int nt = 0; nt < NT1; nt++)
#pragma unroll
            for (int q = 0; q < 4; q++) acc1[mt][nt][q] = 0.f;

    uint4 ra[2], rb[NST];
    auto loadC = [&](int c) {
#pragma unroll
        for (int i = 0; i < 2; i++) {
            int g = tid + 256 * i;
            int row = g & 127, qq = g >> 7;
            int grow = rowBase + row;
            ra[i] = (grow < NN)
                ? *reinterpret_cast<const uint4*>(A + (size_t)grow * (K / 2) + c * 16 + 4 * qq)
                : make_uint4(0, 0, 0, 0);
        }
#pragma unroll
        for (int i = 0; i < NST; i++) {
            int g = tid + 256 * i;
            int n = g % K, qq = g / K;
            float f[8];
#pragma unroll
            for (int j = 0; j < 8; j++) f[j] = PW[(size_t)(c * 32 + 8 * qq + j) * K + n];
            rb[i] = make_uint4(f2h2(f[0], f[1]), f2h2(f[2], f[3]), f2h2(f[4], f[5]), f2h2(f[6], f[7]));
        }
    };
    auto stage = [&](int b) {
        uint32_t* sa = smem + (b ? 4096 : 0);
        uint32_t* sb = smem + 8192 + (b ? INB : 0);
#pragma unroll
        for (int i = 0; i < 2; i++) {
            int g = tid + 256 * i;
            stTile4(sa, g & 127, g >> 7, ra[i]);
        }
#pragma unroll
        for (int i = 0; i < NST; i++) {
            int g = tid + 256 * i;
            stTile4(sb, g % K, g / K, rb[i]);
        }
    };

    loadC(0); stage(0); __syncthreads();
#pragma unroll 1
    for (int c = 0; c < NCH; c++) {
        if (c + 1 < NCH) loadC(c + 1);
        uint32_t aB = smb + ((c & 1) ? 4096u : 0u) * 4u;
        uint32_t bB = smb + (8192u + ((c & 1) ? (uint32_t)INB : 0u)) * 4u;
        chunk_mma_ldm<NT1>(aB, bB, acc1, warpM * 32, warpN * CW, lane);
        if (c + 1 < NCH) { stage((c + 1) & 1); __syncthreads(); }
    }
    __syncthreads();

#pragma unroll
    for (int mt = 0; mt < 2; mt++) {
        int r0 = warpM * 32 + mt * 16 + qr;
#pragma unroll
        for (int nt = 0; nt < NT1; nt++) {
            int col = warpN * CW + nt * 8 + 2 * qc;
            float b0 = __ldg(&PB[col]), b1 = __ldg(&PB[col + 1]);
            stXh(smem, r0, col / 2,
                 f2h2(fmaxf(acc1[mt][nt][0] + b0, 0.f), fmaxf(acc1[mt][nt][1] + b1, 0.f)));
            stXh(smem, r0 + 8, col / 2,
                 f2h2(fmaxf(acc1[mt][nt][2] + b0, 0.f), fmaxf(acc1[mt][nt][3] + b1, 0.f)));
        }
    }
    __syncthreads();

    float acc2[2][4][4];
#pragma unroll
    for (int mt = 0; mt < 2; mt++)
#pragma unroll
        for (int nt = 0; nt < 4; nt++)
#pragma unroll
            for (int q = 0; q < 4; q++) acc2[mt][nt][q] = 0.f;
#pragma unroll
    for (int c = 0; c < NCH; c++)
        chunk_mma_ldm<4>(smb + (uint32_t)(c * 4096) * 4u,
                         smb + (uint32_t)(UW + c * 2048) * 4u,
                         acc2, warpM * 32, warpN * 32, lane);

#pragma unroll
    for (int mt = 0; mt < 2; mt++) {
        int r0 = rowBase + warpM * 32 + mt * 16 + qr;
#pragma unroll
        for (int nt = 0; nt < 4; nt++) {
            int gc = warpN * 32 + nt * 8 + 2 * qc;
            if (r0 < NN)
                Z[(size_t)r0 * 32 + gc / 2] = __floats2half2_rn(acc2[mt][nt][0], acc2[mt][nt][1]);
            if (r0 + 8 < NN)
                Z[(size_t)(r0 + 8) * 32 + gc / 2] = __floats2half2_rn(acc2[mt][nt][2], acc2[mt][nt][3]);
        }
    }
}

// ---------------- combine: out = normalize(X@WR + MZ + BL); POOL fuses readout ----------------
template <int K, bool POOL>
__global__ void __launch_bounds__(256)
combine_h(const uint32_t* __restrict__ X, const float* __restrict__ WR,
          const __half2* __restrict__ MZ, const float* __restrict__ BL,
          uint32_t* __restrict__ Cout, const int* __restrict__ batch) {
    constexpr int NCH = K / 32;
    extern __shared__ uint32_t smem[];
    const uint32_t smb = smem_u32(smem);
    const int tid = threadIdx.x, lane = tid & 31, wid = tid >> 5;
    const int warpM = wid & 3, warpN = wid >> 2;
    const int rowBase = blockIdx.x * 128;

    float acc[2][4][4];
#pragma unroll
    for (int mt = 0; mt < 2; mt++)
#pragma unroll
        for (int nt = 0; nt < 4; nt++)
#pragma unroll
            for (int q = 0; q < 4; q++) acc[mt][nt][q] = 0.f;

    uint4 ra[2], rb;
    auto loadC = [&](int c) {
#pragma unroll
        for (int i = 0; i < 2; i++) {
            int g = tid + 256 * i;
            int row = g & 127, qq = g >> 7;
            int grow = rowBase + row;
            ra[i] = (grow < NN)
                ? *reinterpret_cast<const uint4*>(X + (size_t)grow * (K / 2) + c * 16 + 4 * qq)
                : make_uint4(0, 0, 0, 0);
        }
        {
            int n = tid & 63, qq = tid >> 6;
            float f[8];
#pragma unroll
            for (int j = 0; j < 8; j++) f[j] = WR[(size_t)(c * 32 + 8 * qq + j) * 64 + n];
            rb = make_uint4(f2h2(f[0], f[1]), f2h2(f[2], f[3]), f2h2(f[4], f[5]), f2h2(f[6], f[7]));
        }
    };
    auto stage = [&](int b) {
        uint32_t* sa = smem + (b ? 4096 : 0);
        uint32_t* sb = smem + 8192 + (b ? 2048 : 0);
#pragma unroll
        for (int i = 0; i < 2; i++) {
            int g = tid + 256 * i;
            stTile4(sa, g & 127, g >> 7, ra[i]);
        }
        stTile4(sb, tid & 63, tid >> 6, rb);
    };

    loadC(0); stage(0); __syncthreads();
#pragma unroll 1
    for (int c = 0; c < NCH; c++) {
        if (c + 1 < NCH) loadC(c + 1);
        uint32_t aB = smb + ((c & 1) ? 4096u : 0u) * 4u;
        uint32_t bB = smb + (8192u + ((c & 1) ? 2048u : 0u)) * 4u;
        chunk_mma_ldm<4>(aB, bB, acc, warpM * 32, warpN * 32, lane);
        if (c + 1 < NCH) { stage((c + 1) & 1); __syncthreads(); }
    }

    __syncthreads();
    float (*sOut)[66] = reinterpret_cast<float(*)[66]>(smem);
    const int qr = lane >> 2, qc = lane & 3;
#pragma unroll
    for (int mt = 0; mt < 2; mt++) {
        int rl = warpM * 32 + mt * 16 + qr;
        int g0 = rowBase + rl, g1 = rowBase + rl + 8;
#pragma unroll
        for (int nt = 0; nt < 4; nt++) {
            int cl = warpN * 32 + nt * 8 + 2 * qc;
            float b0 = __ldg(&BL[cl]), b1 = __ldg(&BL[cl + 1]);
            float2 m0 = (g0 < NN) ? __half22float2(MZ[(size_t)g0 * 32 + cl / 2]) : make_float2(0, 0);
            float2 m1 = (g1 < NN) ? __half22float2(MZ[(size_t)g1 * 32 + cl / 2]) : make_float2(0, 0);
            sOut[rl][cl]         = acc[mt][nt][0] + b0 + m0.x;
            sOut[rl][cl + 1]     = acc[mt][nt][1] + b1 + m0.y;
            sOut[rl + 8][cl]     = acc[mt][nt][2] + b0 + m1.x;
            sOut[rl + 8][cl + 1] = acc[mt][nt][3] + b1 + m1.y;
        }
    }
    __syncthreads();

    if (POOL) {
        // per-warp running max/sum over its 16 consecutive rows; flush on graph change
        float pm0 = -__int_as_float(0x7f800000), pm1 = pm0;
        float ps0 = 0.f, ps1 = 0.f;
        int cnt = 0, curg = -1;
#pragma unroll 1
        for (int rr = 0; rr < 16; rr++) {
            int r = wid * 16 + rr;
            int grow = rowBase + r;
            if (grow >= NN) break;
            float2 v = *(const float2*)&sOut[r][2 * lane];
            float ss = v.x * v.x + v.y * v.y;
#pragma unroll
            for (int o = 16; o > 0; o >>= 1) ss += __shfl_xor_sync(0xffffffffu, ss, o);
            float sc = 1.0f / fmaxf(sqrtf(ss), 1e-12f);
            v.x *= sc; v.y *= sc;
            int g = __ldg(&batch[grow]);
            if (g != curg) {
                if (curg >= 0) {
                    atomicMax(&g_gmax[curg * 64 + 2 * lane], fenc(pm0));
                    atomicMax(&g_gmax[curg * 64 + 2 * lane + 1], fenc(pm1));
                    atomicAdd(&g_gsum[curg * 64 + 2 * lane], ps0);
                    atomicAdd(&g_gsum[curg * 64 + 2 * lane + 1], ps1);
                    if (lane == 0) atomicAdd(&g_gcnt[curg], cnt);
                }
                pm0 = pm1 = -__int_as_float(0x7f800000);
                ps0 = ps1 = 0.f; cnt = 0; curg = g;
            }
            pm0 = fmaxf(pm0, v.x); pm1 = fmaxf(pm1, v.y);
            ps0 += v.x; ps1 += v.y; cnt++;
        }
        if (curg >= 0) {
            atomicMax(&g_gmax[curg * 64 + 2 * lane], fenc(pm0));
            atomicMax(&g_gmax[curg * 64 + 2 * lane + 1], fenc(pm1));
            atomicAdd(&g_gsum[curg * 64 + 2 * lane], ps0);
            atomicAdd(&g_gsum[curg * 64 + 2 * lane + 1], ps1);
            if (lane == 0) atomicAdd(&g_gcnt[curg], cnt);
        }
    } else {
#pragma unroll
        for (int rr = 0; rr < 16; rr++) {
            int r = wid * 16 + rr;
            int grow = rowBase + r;
            float2 v = *(const float2*)&sOut[r][2 * lane];
            float ss = v.x * v.x + v.y * v.y;
#pragma unroll
            for (int o = 16; o > 0; o >>= 1) ss += __shfl_xor_sync(0xffffffffu, ss, o);
            float sc = 1.0f / fmaxf(sqrtf(ss), 1e-12f);
            if (grow < NN)
                Cout[(size_t)grow * 32 + lane] = f2h2(v.x * sc, v.y * sc);
        }
    }
}

// ---------------- mean aggregation over CSR (fp16 in, fp16 out) ----------------
__global__ void agg_half(const __half2* __restrict__ zp, __half2* __restrict__ msg) {
    int w = (blockIdx.x * blockDim.x + threadIdx.x) >> 5;
    int lane = threadIdx.x & 31;
    if (w >= NN) return;
    int beg = g_rowptr[w], end = g_rowptr[w + 1];
    float2 acc = make_float2(0, 0);
    int e = beg;
    for (; e + 4 <= end; e += 4) {
        int s0 = __ldg(&g_adj[e]);
        int s1 = __ldg(&g_adj[e + 1]);
        int s2 = __ldg(&g_adj[e + 2]);
        int s3 = __ldg(&g_adj[e + 3]);
        float2 v0 = __half22float2(zp[(size_t)s0 * 32 + lane]);
        float2 v1 = __half22float2(zp[(size_t)s1 * 32 + lane]);
        float2 v2 = __half22float2(zp[(size_t)s2 * 32 + lane]);
        float2 v3 = __half22float2(zp[(size_t)s3 * 32 + lane]);
        acc.x += (v0.x + v1.x) + (v2.x + v3.x);
        acc.y += (v0.y + v1.y) + (v2.y + v3.y);
    }
    for (; e < end; e++) {
        int s = __ldg(&g_adj[e]);
        float2 v = __half22float2(zp[(size_t)s * 32 + lane]);
        acc.x += v.x; acc.y += v.y;
    }
    float inv = 1.0f / fmaxf((float)(end - beg), 1.0f);
    msg[(size_t)w * 32 + lane] = __floats2half2_rn(acc.x * inv, acc.y * inv);
}

// ---------------- final ----------------
__global__ void final_kernel(const float* __restrict__ post_w, const float* __restrict__ post_b,
                             float* __restrict__ out) {
    int g = threadIdx.x;
    if (g >= NG) return;
    float inv = 1.0f / (float)g_gcnt[g];
    float v[64];
    float ss = 0.f;
#pragma unroll
    for (int c = 0; c < 64; c++) {
        float t = fdec(g_gmax[g * 64 + c]) + g_gsum[g * 64 + c] * inv;
        v[c] = t;
        ss += t * t;
    }
    float norm = sqrtf(ss);
    float dot = 0.f;
#pragma unroll
    for (int c = 0; c < 64; c++) dot += v[c] * post_w[c];
    out[g] = dot / norm + post_b[0];
}

// ---------------- launch ----------------
static cudaStream_t g_s2 = nullptr;
static cudaEvent_t g_ev1 = nullptr, g_ev2 = nullptr;

extern "C" void kernel_launch(void* const* d_in, const int* in_sizes, int n_in,
                              void* d_out, int out_size) {
    const float* node_feat = (const float*)d_in[0];
    const float* cfg_feat  = (const float*)d_in[1];
    const int*   opcode    = (const int*)d_in[2];
    const int*   edge      = (const int*)d_in[3];
    const int*   batch     = (const int*)d_in[4];
    const float* op_emb    = (const float*)d_in[5];
    const float* lin_w     = (const float*)d_in[6];
    const float* lin_b     = (const float*)d_in[7];
    const float* post_w    = (const float*)d_in[8];
    const float* post_b    = (const float*)d_in[9];
    const float* pw0 = (const float*)d_in[10];
    const float* pb0 = (const float*)d_in[11];
    const float* wl0 = (const float*)d_in[12];
    const float* bl0 = (const float*)d_in[13];
    const float* wr0 = (const float*)d_in[14];
    const float* pw1 = (const float*)d_in[15];
    const float* pb1 = (const float*)d_in[16];
    const float* wl1 = (const float*)d_in[17];
    const float* bl1 = (const float*)d_in[18];
    const float* wr1 = (const float*)d_in[19];
    const float* pw2 = (const float*)d_in[20];
    const float* pb2 = (const float*)d_in[21];
    const float* wl2 = (const float*)d_in[22];
    const float* bl2 = (const float*)d_in[23];
    const float* wr2 = (const float*)d_in[24];
    float* out = (float*)d_out;

    if (g_s2 == nullptr) {
        cudaStreamCreateWithFlags(&g_s2, cudaStreamNonBlocking);
        cudaEventCreateWithFlags(&g_ev1, cudaEventDisableTiming);
        cudaEventCreateWithFlags(&g_ev2, cudaEventDisableTiming);
        cudaFuncSetAttribute(lin_h,        cudaFuncAttributeMaxDynamicSharedMemorySize, 65536);
        cudaFuncSetAttribute(projz_h<128>, cudaFuncAttributeMaxDynamicSharedMemorySize, 98304);
        cudaFuncSetAttribute(projz_h<64>,  cudaFuncAttributeMaxDynamicSharedMemorySize, 65536);
    }

    const int* src = edge;
    const int* dst = edge + NE;

    const int MB = (NN + 127) / 128;
    const int EB = (NE + 255) / 256;
    const int AGGB = (NN * 32 + 255) / 256;
    const size_t SMEM48 = 49152;
    const size_t SMEM64 = 65536;
    const size_t SMEM_PZ128 = 98304;
    const size_t SMEM_PZ64  = 65536;

    uint32_t* dA; cudaGetSymbolAddress((void**)&dA, g_xA);
    uint32_t* dB; cudaGetSymbolAddress((void**)&dB, g_xB);
    __half2* dZ; cudaGetSymbolAddress((void**)&dZ, g_z);
    __half2* dM; cudaGetSymbolAddress((void**)&dM, g_msg);

    // fork: CSR build on side stream
    cudaEventRecord(g_ev1, 0);
    cudaStreamWaitEvent(g_s2, g_ev1, 0);
    init_kernel<<<(NN + 255) / 256, 256, 0, g_s2>>>();
    hist_kernel<<<EB, 256, 0, g_s2>>>(dst);
    scan1_kernel<<<NBLK, 256, 0, g_s2>>>();
    scan2_kernel<<<1, 128, 0, g_s2>>>();
    scan3_kernel<<<NBLK, 256, 0, g_s2>>>();
    fill_adj_kernel<<<EB, 256, 0, g_s2>>>(src, dst);
    cudaEventRecord(g_ev2, g_s2);

    lin_h<<<MB, 256, SMEM64>>>(node_feat, cfg_feat, opcode, op_emb, lin_w, lin_b, dA);
    projz_h<128><<<MB, 256, SMEM_PZ128>>>(dA, pw0, pb0, wl0, dZ);

    cudaStreamWaitEvent(0, g_ev2, 0);

    // layer 0 (d=128 -> 64)
    agg_half<<<AGGB, 256>>>(dZ, dM);
    combine_h<128, false><<<MB, 256, SMEM48>>>(dA, wr0, dM, bl0, dB, batch);

    // layer 1 (d=64 -> 64)
    projz_h<64><<<MB, 256, SMEM_PZ64>>>(dB, pw1, pb1, wl1, dZ);
    agg_half<<<AGGB, 256>>>(dZ, dM);
    combine_h<64, false><<<MB, 256, SMEM48>>>(dB, wr1, dM, bl1, dA, batch);

    // layer 2 (d=64 -> 64), fused pooling readout
    projz_h<64><<<MB, 256, SMEM_PZ64>>>(dA, pw2, pb2, wl2, dZ);
    agg_half<<<AGGB, 256>>>(dZ, dM);
    combine_h<64, true><<<MB, 256, SMEM48>>>(dA, wr2, dM, bl2, nullptr, batch);

    final_kernel<<<1, 64>>>(post_w, post_b, out);
}

// round 17
// speedup vs baseline: 1.4448x; 1.0303x over previous
#include <cuda_runtime.h>
#include <cuda_fp16.h>
#include <cstdint>

#define NN 100000
#define NE 1600000
#define NG 64
#define NBLK 98   // ceil(NN/1024)

// ---------------- scratch ----------------
__device__ __align__(256) uint32_t g_xA[(size_t)NN * 64];
__device__ __align__(256) uint32_t g_xB[(size_t)NN * 64];
__device__ __align__(256) __half2 g_z[(size_t)NN * 32];
__device__ __align__(256) __half2 g_msg[(size_t)NN * 32];
__device__ int g_deg[NN];
__device__ int g_cursor[NN];
__device__ int g_rowptr[NN + 1];
__device__ int g_adj[NE];
__device__ int g_bsum[NBLK];
__device__ int g_boff[NBLK];
__device__ unsigned g_gmax[NG * 64];
__device__ float g_gsum[NG * 64];
__device__ int g_gcnt[NG];

// ---------------- helpers ----------------
__device__ __forceinline__ uint32_t smem_u32(const void* p) {
    uint32_t a;
    asm("{ .reg .u64 t; cvta.to.shared.u64 t, %1; cvt.u32.u64 %0, t; }" : "=r"(a) : "l"(p));
    return a;
}
__device__ __forceinline__ uint32_t f2h2(float lo, float hi) {
    __half2 h = __floats2half2_rn(lo, hi);
    return *reinterpret_cast<uint32_t*>(&h);
}
__device__ __forceinline__ void mma16(float* c, const uint32_t* a, const uint32_t* b) {
    asm volatile(
        "mma.sync.aligned.m16n8k16.row.col.f32.f16.f16.f32 "
        "{%0,%1,%2,%3}, {%4,%5,%6,%7}, {%8,%9}, {%0,%1,%2,%3};"
        : "+f"(c[0]), "+f"(c[1]), "+f"(c[2]), "+f"(c[3])
        : "r"(a[0]), "r"(a[1]), "r"(a[2]), "r"(a[3]), "r"(b[0]), "r"(b[1]));
}
__device__ __forceinline__ unsigned fenc(float f) {
    unsigned u = __float_as_uint(f);
    return (u & 0x80000000u) ? ~u : (u | 0x80000000u);
}
__device__ __forceinline__ float fdec(unsigned e) {
    return __uint_as_float((e & 0x80000000u) ? (e ^ 0x80000000u) : ~e);
}

// ---------------- fp16 XOR-swizzled tiles ----------------
__device__ __forceinline__ void stTile4(uint32_t* s, int row, int qq, uint4 w) {
    *reinterpret_cast<uint4*>(s + row * 32 + 4 * (qq ^ (row & 7))) = w;
}
__device__ __forceinline__ void stXh(uint32_t* sX, int row, int c2, uint32_t w) {
    uint32_t* t = sX + (c2 >> 4) * 4096;
    int lc = c2 & 15;
    t[row * 32 + 4 * ((lc >> 2) ^ (row & 7)) + (lc & 3)] = w;
}

// ldmatrix-based fragment consumer
template <int NT>
__device__ __forceinline__ void chunk_mma_ldm(uint32_t aB, uint32_t bB,
                                              float (&acc)[2][NT][4], int rowB, int colB, int lane) {
#pragma unroll
    for (int s = 0; s < 2; s++) {
        uint32_t a[2][4];
#pragma unroll
        for (int mt = 0; mt < 2; mt++) {
            int row = rowB + mt * 16 + (lane & 15);
            int qq = 2 * s + (lane >> 4);
            uint32_t addr = aB + row * 128 + 16 * (qq ^ (row & 7));
            asm volatile("ldmatrix.sync.aligned.m8n8.x4.shared.b16 {%0,%1,%2,%3}, [%4];"
                         : "=r"(a[mt][0]), "=r"(a[mt][1]), "=r"(a[mt][2]), "=r"(a[mt][3])
                         : "r"(addr));
        }
#pragma unroll
        for (int ntp = 0; ntp < NT / 2; ntp++) {
            int m = lane >> 3;
            int nt = 2 * ntp + (m >> 1);
            int qq = 2 * s + (m & 1);
            int n = colB + nt * 8 + (lane & 7);
            uint32_t addr = bB + n * 128 + 16 * (qq ^ (n & 7));
            uint32_t b[4];
            asm volatile("ldmatrix.sync.aligned.m8n8.x4.shared.b16 {%0,%1,%2,%3}, [%4];"
                         : "=r"(b[0]), "=r"(b[1]), "=r"(b[2]), "=r"(b[3])
                         : "r"(addr));
#pragma unroll
            for (int mt = 0; mt < 2; mt++) {
                mma16(acc[mt][2 * ntp], a[mt], b);
                mma16(acc[mt][2 * ntp + 1], a[mt], b + 2);
            }
        }
    }
}

// ---------------- init ----------------
__global__ void init_kernel() {
    int j = blockIdx.x * blockDim.x + threadIdx.x;
    if (j < NN) { g_deg[j] = 0; g_cursor[j] = 0; }
    if (j < NG * 64) { g_gmax[j] = 0x007FFFFFu; g_gsum[j] = 0.f; }
    if (j < NG) g_gcnt[j] = 0;
}

// ---------------- CSR build ----------------
__global__ void hist_kernel(const int* __restrict__ dst) {
    int e = blockIdx.x * blockDim.x + threadIdx.x;
    if (e < NE) atomicAdd(&g_deg[dst[e]], 1);
}

__global__ void scan1_kernel() {
    __shared__ int wsum[8];
    int b = blockIdx.x, tid = threadIdx.x, lane = tid & 31, w = tid >> 5;
    int i0 = b * 1024 + tid * 4;
    int s = 0;
#pragma unroll
    for (int j = 0; j < 4; j++) { int i = i0 + j; if (i < NN) s += g_deg[i]; }
#pragma unroll
    for (int o = 16; o > 0; o >>= 1) s += __shfl_xor_sync(0xffffffffu, s, o);
    if (lane == 0) wsum[w] = s;
    __syncthreads();
    if (tid == 0) {
        int t = 0;
#pragma unroll
        for (int k = 0; k < 8; k++) t += wsum[k];
        g_bsum[b] = t;
    }
}

__global__ void scan2_kernel() {
    __shared__ int ws[4];
    int tid = threadIdx.x, lane = tid & 31, w = tid >> 5;
    int v = (tid < NBLK) ? g_bsum[tid] : 0;
    int si = v;
#pragma unroll
    for (int o = 1; o < 32; o <<= 1) { int t = __shfl_up_sync(0xffffffffu, si, o); if (lane >= o) si += t; }
    if (lane == 31) ws[w] = si;
    __syncthreads();
    if (tid == 0) {
        int run = 0;
#pragma unroll
        for (int k = 0; k < 4; k++) { int t = ws[k]; ws[k] = run; run += t; }
        g_rowptr[NN] = run;
    }
    __syncthreads();
    if (tid < NBLK) g_boff[tid] = ws[w] + si - v;
}

__global__ void scan3_kernel() {
    __shared__ int wsum[8];
    int b = blockIdx.x, tid = threadIdx.x, lane = tid & 31, w = tid >> 5;
    int i0 = b * 1024 + tid * 4;
    int v[4], s = 0;
#pragma unroll
    for (int j = 0; j < 4; j++) { int i = i0 + j; v[j] = (i < NN) ? g_deg[i] : 0; s += v[j]; }
    int si = s;
#pragma unroll
    for (int o = 1; o < 32; o <<= 1) { int t = __shfl_up_sync(0xffffffffu, si, o); if (lane >= o) si += t; }
    if (lane == 31) wsum[w] = si;
    __syncthreads();
    if (tid == 0) {
        int run = 0;
#pragma unroll
        for (int k = 0; k < 8; k++) { int t = wsum[k]; wsum[k] = run; run += t; }
    }
    __syncthreads();
    int off = g_boff[b] + wsum[w] + (si - s);
#pragma unroll
    for (int j = 0; j < 4; j++) { int i = i0 + j; if (i < NN) g_rowptr[i] = off; off += v[j]; }
}

__global__ void fill_adj_kernel(const int* __restrict__ src, const int* __restrict__ dst) {
    int e = blockIdx.x * blockDim.x + threadIdx.x;
    if (e < NE) {
        int d = dst[e];
        int p = atomicAdd(&g_cursor[d], 1);
        g_adj[g_rowptr[d] + p] = src[e];
    }
}

// ---------------- lin: one pass, full N=128 (NT=8) ----------------
__device__ __forceinline__ float4 lin_ld4(const float* nf, const float* cf,
                                          const int* opc, const float* emb, int grow, int k) {
    float4 v = make_float4(0, 0, 0, 0);
    if (k < 140)      v = *(const float4*)(nf + (size_t)grow * 140 + k);
    else if (k < 172) v = *(const float4*)(emb + (size_t)opc[grow] * 32 + (k - 140));
    else if (k < 190) {
        const float* cp = cf + (size_t)grow * 18;
        int off = k - 172;
        v.x = cp[off];
        v.y = (off + 1 < 18) ? cp[off + 1] : 0.f;
        v.z = (off + 2 < 18) ? cp[off + 2] : 0.f;
        v.w = (off + 3 < 18) ? cp[off + 3] : 0.f;
    }
    return v;
}

__global__ void __launch_bounds__(256)
lin_h(const float* __restrict__ nf, const float* __restrict__ cf,
      const int* __restrict__ opc, const float* __restrict__ emb,
      const float* __restrict__ W, const float* __restrict__ bias,
      uint32_t* __restrict__ C) {
    extern __shared__ uint32_t smem[];
    const uint32_t smb = smem_u32(smem);
    const int tid = threadIdx.x, lane = tid & 31, wid = tid >> 5;
    const int warpM = wid & 3, warpN = wid >> 2;
    const int rowBase = blockIdx.x * 128;

    float acc[2][8][4];
#pragma unroll
    for (int mt = 0; mt < 2; mt++)
#pragma unroll
        for (int nt = 0; nt < 8; nt++)
#pragma unroll
            for (int q = 0; q < 4; q++) acc[mt][nt][q] = 0.f;

    uint4 ra[2], rb[2];
    auto loadC = [&](int c) {
#pragma unroll
        for (int i = 0; i < 2; i++) {
            int g = tid + 256 * i;
            int row = g & 127, qq = g >> 7;
            int grow = rowBase + row;
            uint4 w = make_uint4(0, 0, 0, 0);
            if (grow < NN) {
                float4 v0 = lin_ld4(nf, cf, opc, emb, grow, c * 32 + 8 * qq);
                float4 v1 = lin_ld4(nf, cf, opc, emb, grow, c * 32 + 8 * qq + 4);
                w = make_uint4(f2h2(v0.x, v0.y), f2h2(v0.z, v0.w), f2h2(v1.x, v1.y), f2h2(v1.z, v1.w));
            }
            ra[i] = w;
        }
#pragma unroll
        for (int i = 0; i < 2; i++) {
            int g = tid + 256 * i;
            int n = g & 127, qq = g >> 7;
            float f[8];
#pragma unroll
            for (int j = 0; j < 8; j++) {
                int kg = c * 32 + 8 * qq + j;
                f[j] = (kg < 190) ? W[(size_t)kg * 128 + n] : 0.f;
            }
            rb[i] = make_uint4(f2h2(f[0], f[1]), f2h2(f[2], f[3]), f2h2(f[4], f[5]), f2h2(f[6], f[7]));
        }
    };
    auto stage = [&](int b) {
        uint32_t* sa = smem + (b ? 4096 : 0);
        uint32_t* sb = smem + 8192 + (b ? 4096 : 0);
#pragma unroll
        for (int i = 0; i < 2; i++) {
            int g = tid + 256 * i;
            stTile4(sa, g & 127, g >> 7, ra[i]);
            stTile4(sb, g & 127, g >> 7, rb[i]);
        }
    };

    loadC(0); stage(0); __syncthreads();
#pragma unroll 1
    for (int c = 0; c < 6; c++) {
        if (c < 5) loadC(c + 1);
        uint32_t aB = smb + ((c & 1) ? 4096u : 0u) * 4u;
        uint32_t bB = smb + (8192u + ((c & 1) ? 4096u : 0u)) * 4u;
        chunk_mma_ldm<8>(aB, bB, acc, warpM * 32, warpN * 64, lane);
        if (c < 5) { stage((c + 1) & 1); __syncthreads(); }
    }

    const int qr = lane >> 2, qc = lane & 3;
#pragma unroll
    for (int mt = 0; mt < 2; mt++) {
        int r0 = rowBase + warpM * 32 + mt * 16 + qr;
#pragma unroll
        for (int nt = 0; nt < 8; nt++) {
            int gc = warpN * 64 + nt * 8 + 2 * qc;
            float b0 = __ldg(&bias[gc]), b1 = __ldg(&bias[gc + 1]);
            if (r0 < NN)
                C[(size_t)r0 * 64 + gc / 2] =
                    f2h2(fmaxf(acc[mt][nt][0] + b0, 0.f), fmaxf(acc[mt][nt][1] + b1, 0.f));
            if (r0 + 8 < NN)
                C[(size_t)(r0 + 8) * 64 + gc / 2] =
                    f2h2(fmaxf(acc[mt][nt][2] + b0, 0.f), fmaxf(acc[mt][nt][3] + b1, 0.f));
        }
    }
}

// ---------------- projz<128>: Z(half2) = relu(A@PW + PB) @ WL  (layer 0 only) ----------------
__global__ void __launch_bounds__(256)
projz128(const uint32_t* __restrict__ A, const float* __restrict__ PW,
         const float* __restrict__ PB, const float* __restrict__ WL,
         __half2* __restrict__ Z) {
    constexpr int K = 128, NCH = 4, CW = 64, NT1 = 8, INB = 4096;
    constexpr int UW = 16384;  // max(8192 + 2*4096, 4*4096)
    extern __shared__ uint32_t smem[];
    uint32_t* W2 = smem + UW;
    const uint32_t smb = smem_u32(smem);

    const int tid = threadIdx.x, lane = tid & 31, wid = tid >> 5;
    const int warpM = wid & 3, warpN = wid >> 2;
    const int rowBase = blockIdx.x * 128;
    const int qr = lane >> 2, qc = lane & 3;

#pragma unroll
    for (int c = 0; c < NCH; c++) {
        int n = tid & 63, qq = tid >> 6;
        float f[8];
#pragma unroll
        for (int j = 0; j < 8; j++) f[j] = WL[(size_t)(c * 32 + 8 * qq + j) * 64 + n];
        stTile4(W2 + c * 2048, n, qq,
                make_uint4(f2h2(f[0], f[1]), f2h2(f[2], f[3]), f2h2(f[4], f[5]), f2h2(f[6], f[7])));
    }

    float acc1[2][NT1][4];
#pragma unroll
    for (int mt = 0; mt < 2; mt++)
#pragma unroll
        for (int nt = 0; nt < NT1; nt++)
#pragma unroll
            for (int q = 0; q < 4; q++) acc1[mt][nt][q] = 0.f;

    uint4 ra[2], rb[2];
    auto loadC = [&](int c) {
#pragma unroll
        for (int i = 0; i < 2; i++) {
            int g = tid + 256 * i;
            int row = g & 127, qq = g >> 7;
            int grow = rowBase + row;
            ra[i] = (grow < NN)
                ? *reinterpret_cast<const uint4*>(A + (size_t)grow * 64 + c * 16 + 4 * qq)
                : make_uint4(0, 0, 0, 0);
        }
#pragma unroll
        for (int i = 0; i < 2; i++) {
            int g = tid + 256 * i;
            int n = g % K, qq = g / K;
            float f[8];
#pragma unroll
            for (int j = 0; j < 8; j++) f[j] = PW[(size_t)(c * 32 + 8 * qq + j) * K + n];
            rb[i] = make_uint4(f2h2(f[0], f[1]), f2h2(f[2], f[3]), f2h2(f[4], f[5]), f2h2(f[6], f[7]));
        }
    };
    auto stage = [&](int b) {
        uint32_t* sa = smem + (b ? 4096 : 0);
        uint32_t* sb = smem + 8192 + (b ? INB : 0);
#pragma unroll
        for (int i = 0; i < 2; i++) {
            int g = tid + 256 * i;
            stTile4(sa, g & 127, g >> 7, ra[i]);
            stTile4(sb, g % K, g / K, rb[i]);
        }
    };

    loadC(0); stage(0); __syncthreads();
#pragma unroll 1
    for (int c = 0; c < NCH; c++) {
        if (c + 1 < NCH) loadC(c + 1);
        uint32_t aB = smb + ((c & 1) ? 4096u : 0u) * 4u;
        uint32_t bB = smb + (8192u + ((c & 1) ? (uint32_t)INB : 0u)) * 4u;
        chunk_mma_ldm<NT1>(aB, bB, acc1, warpM * 32, warpN * CW, lane);
        if (c + 1 < NCH) { stage((c + 1) & 1); __syncthreads(); }
    }
    __syncthreads();

#pragma unroll
    for (int mt = 0; mt < 2; mt++) {
        int r0 = warpM * 32 + mt * 16 + qr;
#pragma unroll
        for (int nt = 0; nt < NT1; nt++) {
            int col = warpN * CW + nt * 8 + 2 * qc;
            float b0 = __ldg(&PB[col]), b1 = __ldg(&PB[col + 1]);
            stXh(smem, r0, col / 2,
                 f2h2(fmaxf(acc1[mt][nt][0] + b0, 0.f), fmaxf(acc1[mt][nt][1] + b1, 0.f)));
            stXh(smem, r0 + 8, col / 2,
                 f2h2(fmaxf(acc1[mt][nt][2] + b0, 0.f), fmaxf(acc1[mt][nt][3] + b1, 0.f)));
        }
    }
    __syncthreads();

    float acc2[2][4][4];
#pragma unroll
    for (int mt = 0; mt < 2; mt++)
#pragma unroll
        for (int nt = 0; nt < 4; nt++)
#pragma unroll
            for (int q = 0; q < 4; q++) acc2[mt][nt][q] = 0.f;
#pragma unroll
    for (int c = 0; c < NCH; c++)
        chunk_mma_ldm<4>(smb + (uint32_t)(c * 4096) * 4u,
                         smb + (uint32_t)(UW + c * 2048) * 4u,
                         acc2, warpM * 32, warpN * 32, lane);

#pragma unroll
    for (int mt = 0; mt < 2; mt++) {
        int r0 = rowBase + warpM * 32 + mt * 16 + qr;
#pragma unroll
        for (int nt = 0; nt < 4; nt++) {
            int gc = warpN * 32 + nt * 8 + 2 * qc;
            if (r0 < NN)
                Z[(size_t)r0 * 32 + gc / 2] = __floats2half2_rn(acc2[mt][nt][0], acc2[mt][nt][1]);
            if (r0 + 8 < NN)
                Z[(size_t)(r0 + 8) * 32 + gc / 2] = __floats2half2_rn(acc2[mt][nt][2], acc2[mt][nt][3]);
        }
    }
}

// ---------------- fused combine + next-layer projz ----------------
// Phase A: x = normalize(X@WR + MZ + BL), write Xout (half2).
// Phase B: Z = relu(x@PW + PB) @ WL   (all 64-d), x taken from smem.
// smem layout (words): [0..8192) X dbuf / x tiles; [8192..12288) WR dbuf / PW tiles;
//                      [12288..16384) WL tiles (staged at start). Total 64KB.
template <int K>
__global__ void __launch_bounds__(256)
combine_proj_h(const uint32_t* __restrict__ X, const float* __restrict__ WR,
               const __half2* __restrict__ MZ, const float* __restrict__ BL,
               uint32_t* __restrict__ Xout,
               const float* __restrict__ PW, const float* __restrict__ PB,
               const float* __restrict__ WL, __half2* __restrict__ Z) {
    constexpr int NCH = K / 32;
    extern __shared__ uint32_t smem[];
    const uint32_t smb = smem_u32(smem);
    const int tid = threadIdx.x, lane = tid & 31, wid = tid >> 5;
    const int warpM = wid & 3, warpN = wid >> 2;
    const int rowBase = blockIdx.x * 128;
    const int qr = lane >> 2, qc = lane & 3;

    // stage WL (64x64) into [12288..16384)
#pragma unroll
    for (int c = 0; c < 2; c++) {
        int n = tid & 63, qq = tid >> 6;
        float f[8];
#pragma unroll
        for (int j = 0; j < 8; j++) f[j] = WL[(size_t)(c * 32 + 8 * qq + j) * 64 + n];
        stTile4(smem + 12288 + c * 2048, n, qq,
                make_uint4(f2h2(f[0], f[1]), f2h2(f[2], f[3]), f2h2(f[4], f[5]), f2h2(f[6], f[7])));
    }

    // ---- phase A: X@WR ----
    float acc[2][4][4];
#pragma unroll
    for (int mt = 0; mt < 2; mt++)
#pragma unroll
        for (int nt = 0; nt < 4; nt++)
#pragma unroll
            for (int q = 0; q < 4; q++) acc[mt][nt][q] = 0.f;

    uint4 ra[2], rb;
    auto loadC = [&](int c) {
#pragma unroll
        for (int i = 0; i < 2; i++) {
            int g = tid + 256 * i;
            int row = g & 127, qq = g >> 7;
            int grow = rowBase + row;
            ra[i] = (grow < NN)
                ? *reinterpret_cast<const uint4*>(X + (size_t)grow * (K / 2) + c * 16 + 4 * qq)
                : make_uint4(0, 0, 0, 0);
        }
        {
            int n = tid & 63, qq = tid >> 6;
            float f[8];
#pragma unroll
            for (int j = 0; j < 8; j++) f[j] = WR[(size_t)(c * 32 + 8 * qq + j) * 64 + n];
            rb = make_uint4(f2h2(f[0], f[1]), f2h2(f[2], f[3]), f2h2(f[4], f[5]), f2h2(f[6], f[7]));
        }
    };
    auto stage = [&](int b) {
        uint32_t* sa = smem + (b ? 4096 : 0);
        uint32_t* sb = smem + 8192 + (b ? 2048 : 0);
#pragma unroll
        for (int i = 0; i < 2; i++) {
            int g = tid + 256 * i;
            stTile4(sa, g & 127, g >> 7, ra[i]);
        }
        stTile4(sb, tid & 63, tid >> 6, rb);
    };

    loadC(0); stage(0); __syncthreads();
#pragma unroll 1
    for (int c = 0; c < NCH; c++) {
        if (c + 1 < NCH) loadC(c + 1);
        uint32_t aB = smb + ((c & 1) ? 4096u : 0u) * 4u;
        uint32_t bB = smb + (8192u + ((c & 1) ? 2048u : 0u)) * 4u;
        chunk_mma_ldm<4>(aB, bB, acc, warpM * 32, warpN * 32, lane);
        if (c + 1 < NCH) { stage((c + 1) & 1); __syncthreads(); }
    }

    // epilogue A: + MZ + BL into sOut, normalize into regs, write Xout
    __syncthreads();
    float (*sOut)[66] = reinterpret_cast<float(*)[66]>(smem);
#pragma unroll
    for (int mt = 0; mt < 2; mt++) {
        int rl = warpM * 32 + mt * 16 + qr;
        int g0 = rowBase + rl, g1 = rowBase + rl + 8;
#pragma unroll
        for (int nt = 0; nt < 4; nt++) {
            int cl = warpN * 32 + nt * 8 + 2 * qc;
            float b0 = __ldg(&BL[cl]), b1 = __ldg(&BL[cl + 1]);
            float2 m0 = (g0 < NN) ? __half22float2(MZ[(size_t)g0 * 32 + cl / 2]) : make_float2(0, 0);
            float2 m1 = (g1 < NN) ? __half22float2(MZ[(size_t)g1 * 32 + cl / 2]) : make_float2(0, 0);
            sOut[rl][cl]         = acc[mt][nt][0] + b0 + m0.x;
            sOut[rl][cl + 1]     = acc[mt][nt][1] + b1 + m0.y;
            sOut[rl + 8][cl]     = acc[mt][nt][2] + b0 + m1.x;
            sOut[rl + 8][cl + 1] = acc[mt][nt][3] + b1 + m1.y;
        }
    }
    __syncthreads();
    uint32_t hx[16];
#pragma unroll
    for (int rr = 0; rr < 16; rr++) {
        int r = wid * 16 + rr;
        int grow = rowBase + r;
        float2 v = *(const float2*)&sOut[r][2 * lane];
        float ss = v.x * v.x + v.y * v.y;
#pragma unroll
        for (int o = 16; o > 0; o >>= 1) ss += __shfl_xor_sync(0xffffffffu, ss, o);
        float sc = 1.0f / fmaxf(sqrtf(ss), 1e-12f);
        hx[rr] = f2h2(v.x * sc, v.y * sc);
        if (grow < NN) Xout[(size_t)grow * 32 + lane] = hx[rr];
    }
    __syncthreads();   // all sOut reads complete

    // ---- stage x tiles [0..8192) and PW tiles [8192..12288) ----
#pragma unroll
    for (int rr = 0; rr < 16; rr++) stXh(smem, wid * 16 + rr, lane, hx[rr]);
#pragma unroll
    for (int c = 0; c < 2; c++) {
        int n = tid & 63, qq = tid >> 6;
        float f[8];
#pragma unroll
        for (int j = 0; j < 8; j++) f[j] = PW[(size_t)(c * 32 + 8 * qq + j) * 64 + n];
        stTile4(smem + 8192 + c * 2048, n, qq,
                make_uint4(f2h2(f[0], f[1]), f2h2(f[2], f[3]), f2h2(f[4], f[5]), f2h2(f[6], f[7])));
    }
    __syncthreads();

    // ---- phase B1: xp = x @ PW  (CW=32, NT1=4) ----
    float acc1[2][4][4];
#pragma unroll
    for (int mt = 0; mt < 2; mt++)
#pragma unroll
        for (int nt = 0; nt < 4; nt++)
#pragma unroll
            for (int q = 0; q < 4; q++) acc1[mt][nt][q] = 0.f;
#pragma unroll
    for (int c = 0; c < 2; c++)
        chunk_mma_ldm<4>(smb + (uint32_t)(c * 4096) * 4u,
                         smb + (uint32_t)(8192 + c * 2048) * 4u,
                         acc1, warpM * 32, warpN * 32, lane);
    __syncthreads();

    // restage xp = relu(acc1 + PB) into x tiles
#pragma unroll
    for (int mt = 0; mt < 2; mt++) {
        int r0 = warpM * 32 + mt * 16 + qr;
#pragma unroll
        for (int nt = 0; nt < 4; nt++) {
            int col = warpN * 32 + nt * 8 + 2 * qc;
            float b0 = __ldg(&PB[col]), b1 = __ldg(&PB[col + 1]);
            stXh(smem, r0, col / 2,
                 f2h2(fmaxf(acc1[mt][nt][0] + b0, 0.f), fmaxf(acc1[mt][nt][1] + b1, 0.f)));
            stXh(smem, r0 + 8, col / 2,
                 f2h2(fmaxf(acc1[mt][nt][2] + b0, 0.f), fmaxf(acc1[mt][nt][3] + b1, 0.f)));
        }
    }
    __syncthreads();

    // ---- phase B2: Z = xp @ WL ----
    float acc2[2][4][4];
#pragma unroll
    for (int mt = 0; mt < 2; mt++)
#pragma unroll
        for (int nt = 0; nt < 4; nt++)
#pragma unroll
            for (int q = 0; q < 4; q++) acc2[mt][nt][q] = 0.f;
#pragma unroll
    for (int c = 0; c < 2; c++)
        chunk_mma_ldm<4>(smb + (uint32_t)(c * 4096) * 4u,
                         smb + (uint32_t)(12288 + c * 2048) * 4u,
                         acc2, warpM * 32, warpN * 32, lane);

#pragma unroll
    for (int mt = 0; mt < 2; mt++) {
        int r0 = rowBase + warpM * 32 + mt * 16 + qr;
#pragma unroll
        for (int nt = 0; nt < 4; nt++) {
            int gc = warpN * 32 + nt * 8 + 2 * qc;
            if (r0 < NN)
                Z[(size_t)r0 * 32 + gc / 2] = __floats2half2_rn(acc2[mt][nt][0], acc2[mt][nt][1]);
            if (r0 + 8 < NN)
                Z[(size_t)(r0 + 8) * 32 + gc / 2] = __floats2half2_rn(acc2[mt][nt][2], acc2[mt][nt][3]);
        }
    }
}

// ---------------- final combine (POOL fused readout) ----------------
__global__ void __launch_bounds__(256)
combine_pool(const uint32_t* __restrict__ X, const float* __restrict__ WR,
             const __half2* __restrict__ MZ, const float* __restrict__ BL,
             const int* __restrict__ batch) {
    constexpr int NCH = 2;
    extern __shared__ uint32_t smem[];
    const uint32_t smb = smem_u32(smem);
    const int tid = threadIdx.x, lane = tid & 31, wid = tid >> 5;
    const int warpM = wid & 3, warpN = wid >> 2;
    const int rowBase = blockIdx.x * 128;

    float acc[2][4][4];
#pragma unroll
    for (int mt = 0; mt < 2; mt++)
#pragma unroll
        for (int nt = 0; nt < 4; nt++)
#pragma unroll
            for (int q = 0; q < 4; q++) acc[mt][nt][q] = 0.f;

    uint4 ra[2], rb;
    auto loadC = [&](int c) {
#pragma unroll
        for (int i = 0; i < 2; i++) {
            int g = tid + 256 * i;
            int row = g & 127, qq = g >> 7;
            int grow = rowBase + row;
            ra[i] = (grow < NN)
                ? *reinterpret_cast<const uint4*>(X + (size_t)grow * 32 + c * 16 + 4 * qq)
                : make_uint4(0, 0, 0, 0);
        }
        {
            int n = tid & 63, qq = tid >> 6;
            float f[8];
#pragma unroll
            for (int j = 0; j < 8; j++) f[j] = WR[(size_t)(c * 32 + 8 * qq + j) * 64 + n];
            rb = make_uint4(f2h2(f[0], f[1]), f2h2(f[2], f[3]), f2h2(f[4], f[5]), f2h2(f[6], f[7]));
        }
    };
    auto stage = [&](int b) {
        uint32_t* sa = smem + (b ? 4096 : 0);
        uint32_t* sb = smem + 8192 + (b ? 2048 : 0);
#pragma unroll
        for (int i = 0; i < 2; i++) {
            int g = tid + 256 * i;
            stTile4(sa, g & 127, g >> 7, ra[i]);
        }
        stTile4(sb, tid & 63, tid >> 6, rb);
    };

    loadC(0); stage(0); __syncthreads();
#pragma unroll 1
    for (int c = 0; c < NCH; c++) {
        if (c + 1 < NCH) loadC(c + 1);
        uint32_t aB = smb + ((c & 1) ? 4096u : 0u) * 4u;
        uint32_t bB = smb + (8192u + ((c & 1) ? 2048u : 0u)) * 4u;
        chunk_mma_ldm<4>(aB, bB, acc, warpM * 32, warpN * 32, lane);
        if (c + 1 < NCH) { stage((c + 1) & 1); __syncthreads(); }
    }

    __syncthreads();
    float (*sOut)[66] = reinterpret_cast<float(*)[66]>(smem);
    const int qr = lane >> 2, qc = lane & 3;
#pragma unroll
    for (int mt = 0; mt < 2; mt++) {
        int rl = warpM * 32 + mt * 16 + qr;
        int g0 = rowBase + rl, g1 = rowBase + rl + 8;
#pragma unroll
        for (int nt = 0; nt < 4; nt++) {
            int cl = warpN * 32 + nt * 8 + 2 * qc;
            float b0 = __ldg(&BL[cl]), b1 = __ldg(&BL[cl + 1]);
            float2 m0 = (g0 < NN) ? __half22float2(MZ[(size_t)g0 * 32 + cl / 2]) : make_float2(0, 0);
            float2 m1 = (g1 < NN) ? __half22float2(MZ[(size_t)g1 * 32 + cl / 2]) : make_float2(0, 0);
            sOut[rl][cl]         = acc[mt][nt][0] + b0 + m0.x;
            sOut[rl][cl + 1]     = acc[mt][nt][1] + b1 + m0.y;
            sOut[rl + 8][cl]     = acc[mt][nt][2] + b0 + m1.x;
            sOut[rl + 8][cl + 1] = acc[mt][nt][3] + b1 + m1.y;
        }
    }
    __syncthreads();

    float pm0 = -__int_as_float(0x7f800000), pm1 = pm0;
    float ps0 = 0.f, ps1 = 0.f;
    int cnt = 0, curg = -1;
#pragma unroll 1
    for (int rr = 0; rr < 16; rr++) {
        int r = wid * 16 + rr;
        int grow = rowBase + r;
        if (grow >= NN) break;
        float2 v = *(const float2*)&sOut[r][2 * lane];
        float ss = v.x * v.x + v.y * v.y;
#pragma unroll
        for (int o = 16; o > 0; o >>= 1) ss += __shfl_xor_sync(0xffffffffu, ss, o);
        float sc = 1.0f / fmaxf(sqrtf(ss), 1e-12f);
        v.x *= sc; v.y *= sc;
        int g = __ldg(&batch[grow]);
        if (g != curg) {
            if (curg >= 0) {
                atomicMax(&g_gmax[curg * 64 + 2 * lane], fenc(pm0));
                atomicMax(&g_gmax[curg * 64 + 2 * lane + 1], fenc(pm1));
                atomicAdd(&g_gsum[curg * 64 + 2 * lane], ps0);
                atomicAdd(&g_gsum[curg * 64 + 2 * lane + 1], ps1);
                if (lane == 0) atomicAdd(&g_gcnt[curg], cnt);
            }
            pm0 = pm1 = -__int_as_float(0x7f800000);
            ps0 = ps1 = 0.f; cnt = 0; curg = g;
        }
        pm0 = fmaxf(pm0, v.x); pm1 = fmaxf(pm1, v.y);
        ps0 += v.x; ps1 += v.y; cnt++;
    }
    if (curg >= 0) {
        atomicMax(&g_gmax[curg * 64 + 2 * lane], fenc(pm0));
        atomicMax(&g_gmax[curg * 64 + 2 * lane + 1], fenc(pm1));
        atomicAdd(&g_gsum[curg * 64 + 2 * lane], ps0);
        atomicAdd(&g_gsum[curg * 64 + 2 * lane + 1], ps1);
        if (lane == 0) atomicAdd(&g_gcnt[curg], cnt);
    }
}

// ---------------- mean aggregation over CSR (fp16 in, fp16 out) ----------------
__global__ void agg_half(const __half2* __restrict__ zp, __half2* __restrict__ msg) {
    int w = (blockIdx.x * blockDim.x + threadIdx.x) >> 5;
    int lane = threadIdx.x & 31;
    if (w >= NN) return;
    int beg = g_rowptr[w], end = g_rowptr[w + 1];
    float2 acc = make_float2(0, 0);
    int e = beg;
    for (; e + 4 <= end; e += 4) {
        int s0 = __ldg(&g_adj[e]);
        int s1 = __ldg(&g_adj[e + 1]);
        int s2 = __ldg(&g_adj[e + 2]);
        int s3 = __ldg(&g_adj[e + 3]);
        float2 v0 = __half22float2(zp[(size_t)s0 * 32 + lane]);
        float2 v1 = __half22float2(zp[(size_t)s1 * 32 + lane]);
        float2 v2 = __half22float2(zp[(size_t)s2 * 32 + lane]);
        float2 v3 = __half22float2(zp[(size_t)s3 * 32 + lane]);
        acc.x += (v0.x + v1.x) + (v2.x + v3.x);
        acc.y += (v0.y + v1.y) + (v2.y + v3.y);
    }
    for (; e < end; e++) {
        int s = __ldg(&g_adj[e]);
        float2 v = __half22float2(zp[(size_t)s * 32 + lane]);
        acc.x += v.x; acc.y += v.y;
    }
    float inv = 1.0f / fmaxf((float)(end - beg), 1.0f);
    msg[(size_t)w * 32 + lane] = __floats2half2_rn(acc.x * inv, acc.y * inv);
}

// ---------------- final ----------------
__global__ void final_kernel(const float* __restrict__ post_w, const float* __restrict__ post_b,
                             float* __restrict__ out) {
    int g = threadIdx.x;
    if (g >= NG) return;
    float inv = 1.0f / (float)g_gcnt[g];
    float v[64];
    float ss = 0.f;
#pragma unroll
    for (int c = 0; c < 64; c++) {
        float t = fdec(g_gmax[g * 64 + c]) + g_gsum[g * 64 + c] * inv;
        v[c] = t;
        ss += t * t;
    }
    float norm = sqrtf(ss);
    float dot = 0.f;
#pragma unroll
    for (int c = 0; c < 64; c++) dot += v[c] * post_w[c];
    out[g] = dot / norm + post_b[0];
}

// ---------------- launch ----------------
static cudaStream_t g_s2 = nullptr;
static cudaEvent_t g_ev1 = nullptr, g_ev2 = nullptr;

extern "C" void kernel_launch(void* const* d_in, const int* in_sizes, int n_in,
                              void* d_out, int out_size) {
    const float* node_feat = (const float*)d_in[0];
    const float* cfg_feat  = (const float*)d_in[1];
    const int*   opcode    = (const int*)d_in[2];
    const int*   edge      = (const int*)d_in[3];
    const int*   batch     = (const int*)d_in[4];
    const float* op_emb    = (const float*)d_in[5];
    const float* lin_w     = (const float*)d_in[6];
    const float* lin_b     = (const float*)d_in[7];
    const float* post_w    = (const float*)d_in[8];
    const float* post_b    = (const float*)d_in[9];
    const float* pw0 = (const float*)d_in[10];
    const float* pb0 = (const float*)d_in[11];
    const float* wl0 = (const float*)d_in[12];
    const float* bl0 = (const float*)d_in[13];
    const float* wr0 = (const float*)d_in[14];
    const float* pw1 = (const float*)d_in[15];
    const float* pb1 = (const float*)d_in[16];
    const float* wl1 = (const float*)d_in[17];
    const float* bl1 = (const float*)d_in[18];
    const float* wr1 = (const float*)d_in[19];
    const float* pw2 = (const float*)d_in[20];
    const float* pb2 = (const float*)d_in[21];
    const float* wl2 = (const float*)d_in[22];
    const float* bl2 = (const float*)d_in[23];
    const float* wr2 = (const float*)d_in[24];
    float* out = (float*)d_out;

    if (g_s2 == nullptr) {
        cudaStreamCreateWithFlags(&g_s2, cudaStreamNonBlocking);
        cudaEventCreateWithFlags(&g_ev1, cudaEventDisableTiming);
        cudaEventCreateWithFlags(&g_ev2, cudaEventDisableTiming);
        cudaFuncSetAttribute(lin_h,    cudaFuncAttributeMaxDynamicSharedMemorySize, 65536);
        cudaFuncSetAttribute(projz128, cudaFuncAttributeMaxDynamicSharedMemorySize, 98304);
        cudaFuncSetAttribute(combine_proj_h<128>, cudaFuncAttributeMaxDynamicSharedMemorySize, 65536);
        cudaFuncSetAttribute(combine_proj_h<64>,  cudaFuncAttributeMaxDynamicSharedMemorySize, 65536);
    }

    const int* src = edge;
    const int* dst = edge + NE;

    const int MB = (NN + 127) / 128;
    const int EB = (NE + 255) / 256;
    const int AGGB = (NN * 32 + 255) / 256;
    const size_t SMEM48 = 49152;
    const size_t SMEM64 = 65536;
    const size_t SMEM_PZ128 = 98304;

    uint32_t* dA; cudaGetSymbolAddress((void**)&dA, g_xA);
    uint32_t* dB; cudaGetSymbolAddress((void**)&dB, g_xB);
    __half2* dZ; cudaGetSymbolAddress((void**)&dZ, g_z);
    __half2* dM; cudaGetSymbolAddress((void**)&dM, g_msg);

    // fork: CSR build on side stream
    cudaEventRecord(g_ev1, 0);
    cudaStreamWaitEvent(g_s2, g_ev1, 0);
    init_kernel<<<(NN + 255) / 256, 256, 0, g_s2>>>();
    hist_kernel<<<EB, 256, 0, g_s2>>>(dst);
    scan1_kernel<<<NBLK, 256, 0, g_s2>>>();
    scan2_kernel<<<1, 128, 0, g_s2>>>();
    scan3_kernel<<<NBLK, 256, 0, g_s2>>>();
    fill_adj_kernel<<<EB, 256, 0, g_s2>>>(src, dst);
    cudaEventRecord(g_ev2, g_s2);

    lin_h<<<MB, 256, SMEM64>>>(node_feat, cfg_feat, opcode, op_emb, lin_w, lin_b, dA);
    projz128<<<MB, 256, SMEM_PZ128>>>(dA, pw0, pb0, wl0, dZ);

    cudaStreamWaitEvent(0, g_ev2, 0);

    // layer 0 combine fused with layer-1 projz
    agg_half<<<AGGB, 256>>>(dZ, dM);
    combine_proj_h<128><<<MB, 256, SMEM64>>>(dA, wr0, dM, bl0, dB, pw1, pb1, wl1, dZ);

    // layer 1 combine fused with layer-2 projz
    agg_half<<<AGGB, 256>>>(dZ, dM);
    combine_proj_h<64><<<MB, 256, SMEM64>>>(dB, wr1, dM, bl1, dA, pw2, pb2, wl2, dZ);

    // layer 2 combine with fused pooling readout
    agg_half<<<AGGB, 256>>>(dZ, dM);
    combine_pool<<<MB, 256, SMEM48>>>(dA, wr2, dM, bl2, batch);

    final_kernel<<<1, 64>>>(post_w, post_b, out);
}